// round 1
// baseline (speedup 1.0000x reference)
#include <cuda_runtime.h>
#include <math.h>

// ---------------- problem constants ----------------
#define BATCH 4
#define SEQ   2048
#define DMODEL 1024
#define NHEADS 16
#define DK    64
#define MEMT  32
#define TTOT  (SEQ + MEMT)       // 2080
#define DFF   4096
#define ROWS  (BATCH * SEQ)      // 8192

// ---------------- device scratch ----------------
__device__ float g_xn [ROWS * DMODEL];
__device__ float g_q  [BATCH * NHEADS * SEQ  * DK];
__device__ float g_k  [BATCH * NHEADS * TTOT * DK];
__device__ float g_v  [BATCH * NHEADS * TTOT * DK];
__device__ float g_ctx[ROWS * DMODEL];
__device__ float g_x1 [ROWS * DMODEL];
__device__ float g_xn2[ROWS * DMODEL];
__device__ float g_h1 [ROWS * DFF];
__device__ float g_part[BATCH * 16 * DMODEL];

// ---------------- layer norm (ddof=1, div by std+eps) ----------------
__global__ __launch_bounds__(256) void ln_kernel(
    const float* __restrict__ x, const float* __restrict__ alpha,
    const float* __restrict__ bias, float* __restrict__ out)
{
    int row = blockIdx.x;
    int tid = threadIdx.x;
    const float4* xr = (const float4*)(x + (size_t)row * DMODEL);
    float4 v = xr[tid];
    float s  = v.x + v.y + v.z + v.w;
    float ss = v.x*v.x + v.y*v.y + v.z*v.z + v.w*v.w;
    #pragma unroll
    for (int off = 16; off > 0; off >>= 1) {
        s  += __shfl_xor_sync(0xffffffffu, s,  off);
        ss += __shfl_xor_sync(0xffffffffu, ss, off);
    }
    __shared__ float rs[8], rss[8];
    int wid = tid >> 5, lane = tid & 31;
    if (lane == 0) { rs[wid] = s; rss[wid] = ss; }
    __syncthreads();
    float S = 0.f, SS = 0.f;
    #pragma unroll
    for (int w = 0; w < 8; w++) { S += rs[w]; SS += rss[w]; }
    float mean = S * (1.f / DMODEL);
    float var  = (SS - (float)DMODEL * mean * mean) * (1.f / (DMODEL - 1));
    float inv  = 1.f / (sqrtf(fmaxf(var, 0.f)) + 1e-6f);
    float4 a  = ((const float4*)alpha)[tid];
    float4 bb = ((const float4*)bias)[tid];
    float4 o;
    o.x = a.x * (v.x - mean) * inv + bb.x;
    o.y = a.y * (v.y - mean) * inv + bb.y;
    o.z = a.z * (v.z - mean) * inv + bb.z;
    o.w = a.w * (v.w - mean) * inv + bb.w;
    ((float4*)(out + (size_t)row * DMODEL))[tid] = o;
}

// ---------------- generic tiled GEMM: C = A[MxK] @ W[KxN] ----------------
// epilogue variants
#define EPI_PLAIN      0
#define EPI_QHEAD      1
#define EPI_KVHEAD     2
#define EPI_RESID      3
#define EPI_BIAS_RELU  4
#define EPI_BIAS_RESID 5

template<int EPI>
__global__ __launch_bounds__(256) void gemm_kernel(
    const float* __restrict__ A, const float* __restrict__ W,
    float* __restrict__ C, const float* __restrict__ bias,
    const float* __restrict__ R, int M, int N, int K)
{
    __shared__ float As[16][132];
    __shared__ float Bs[16][64];
    int tid = threadIdx.x;
    int bm = blockIdx.y, bn = blockIdx.x;
    int ty = tid >> 4, tx = tid & 15;

    const float* Ab = A + (size_t)bm * 128 * K;
    const float* Wb = W + (size_t)bn * 64;

    float acc[8][4];
    #pragma unroll
    for (int i = 0; i < 8; i++)
        #pragma unroll
        for (int j = 0; j < 4; j++) acc[i][j] = 0.f;

    for (int kt = 0; kt < K; kt += 16) {
        #pragma unroll
        for (int l = 0; l < 2; l++) {
            int fid = tid + l * 256;
            int r = fid >> 2, cq = fid & 3;
            float4 t = *(const float4*)(Ab + (size_t)r * K + kt + cq * 4);
            As[cq*4+0][r] = t.x; As[cq*4+1][r] = t.y;
            As[cq*4+2][r] = t.z; As[cq*4+3][r] = t.w;
        }
        {
            int r = tid >> 4, c = (tid & 15) * 4;
            float4 t = *(const float4*)(Wb + (size_t)(kt + r) * N + c);
            Bs[r][c+0] = t.x; Bs[r][c+1] = t.y; Bs[r][c+2] = t.z; Bs[r][c+3] = t.w;
        }
        __syncthreads();
        #pragma unroll
        for (int k = 0; k < 16; k++) {
            float a[8], bv[4];
            #pragma unroll
            for (int i = 0; i < 8; i++) a[i] = As[k][ty + 16*i];
            #pragma unroll
            for (int j = 0; j < 4; j++) bv[j] = Bs[k][tx + 16*j];
            #pragma unroll
            for (int i = 0; i < 8; i++)
                #pragma unroll
                for (int j = 0; j < 4; j++)
                    acc[i][j] = fmaf(a[i], bv[j], acc[i][j]);
        }
        __syncthreads();
    }

    #pragma unroll
    for (int i = 0; i < 8; i++) {
        int r = bm * 128 + ty + 16*i;
        #pragma unroll
        for (int j = 0; j < 4; j++) {
            int c = bn * 64 + tx + 16*j;
            float vv = acc[i][j];
            if (EPI == EPI_PLAIN) {
                C[(size_t)r * N + c] = vv;
            } else if (EPI == EPI_QHEAD) {
                int b = r >> 11, s = r & 2047, h = c >> 6, d = c & 63;
                C[(((size_t)(b*NHEADS + h)) * SEQ + s) * DK + d] = vv;
            } else if (EPI == EPI_KVHEAD) {
                int b = r >> 11, s = r & 2047, h = c >> 6, d = c & 63;
                C[(((size_t)(b*NHEADS + h)) * TTOT + MEMT + s) * DK + d] = vv;
            } else if (EPI == EPI_RESID) {
                C[(size_t)r * N + c] = vv + R[(size_t)r * N + c];
            } else if (EPI == EPI_BIAS_RELU) {
                vv += bias[c];
                C[(size_t)r * N + c] = fmaxf(vv, 0.f);
            } else if (EPI == EPI_BIAS_RESID) {
                C[(size_t)r * N + c] = vv + bias[c] + R[(size_t)r * N + c];
            }
        }
    }
}

// ---------------- memory-token K/V projection ----------------
__global__ __launch_bounds__(1024) void memproj_kernel(
    const float* __restrict__ mt, const float* __restrict__ wk,
    const float* __restrict__ wv, float* __restrict__ kh, float* __restrict__ vh)
{
    int m = blockIdx.x;        // 0..31
    int c = threadIdx.x;       // 0..1023
    float ak = 0.f, av = 0.f;
    #pragma unroll 4
    for (int kk = 0; kk < DMODEL; kk++) {
        float xm = mt[(size_t)m * DMODEL + kk];
        ak = fmaf(xm, wk[(size_t)kk * DMODEL + c], ak);
        av = fmaf(xm, wv[(size_t)kk * DMODEL + c], av);
    }
    int h = c >> 6, d = c & 63;
    #pragma unroll
    for (int b = 0; b < BATCH; b++) {
        size_t idx = (((size_t)(b*NHEADS + h)) * TTOT + m) * DK + d;
        kh[idx] = ak;
        vh[idx] = av;
    }
}

// ---------------- flash attention (fp32, online softmax) ----------------
__global__ __launch_bounds__(256) void attn_kernel(
    const float* __restrict__ q, const float* __restrict__ k,
    const float* __restrict__ v, const int* __restrict__ mask,
    float* __restrict__ ctx)
{
    __shared__ float qs[64][65];
    __shared__ float ks[32][65];
    __shared__ float vs[32][65];
    __shared__ float ps[64][33];

    int tid = threadIdx.x;
    int row = tid >> 2;          // 0..63 query row within tile
    int sub = tid & 3;           // 0..3
    int bh = blockIdx.y;         // b*16 + h
    int b  = bh >> 4;
    int h  = bh & 15;
    int q0 = blockIdx.x * 64;

    const float* qb = q + (((size_t)bh) * SEQ + q0) * DK;
    const float* kb = k + ((size_t)bh) * TTOT * DK;
    const float* vb = v + ((size_t)bh) * TTOT * DK;

    // load Q tile
    #pragma unroll
    for (int l = 0; l < 4; l++) {
        int fid = tid + l * 256;
        int r = fid >> 4, c = (fid & 15) << 2;
        float4 t = *(const float4*)(qb + (size_t)r * DK + c);
        qs[r][c] = t.x; qs[r][c+1] = t.y; qs[r][c+2] = t.z; qs[r][c+3] = t.w;
    }

    float m_i = -INFINITY, l_i = 0.f;
    float o[16];
    #pragma unroll
    for (int d = 0; d < 16; d++) o[d] = 0.f;

    int qg = q0 + row;
    const int* mrow = mask + (size_t)qg * TTOT;

    for (int ch = 0; ch < 65; ch++) {
        int t0 = ch * 32;
        __syncthreads();   // protect ks/vs/qs reuse from previous iteration
        #pragma unroll
        for (int l = 0; l < 2; l++) {
            int fid = tid + l * 256;
            int r = fid >> 4, c = (fid & 15) << 2;
            float4 tk = *(const float4*)(kb + (size_t)(t0 + r) * DK + c);
            ks[r][c] = tk.x; ks[r][c+1] = tk.y; ks[r][c+2] = tk.z; ks[r][c+3] = tk.w;
            float4 tv = *(const float4*)(vb + (size_t)(t0 + r) * DK + c);
            vs[r][c] = tv.x; vs[r][c+1] = tv.y; vs[r][c+2] = tv.z; vs[r][c+3] = tv.w;
        }
        __syncthreads();

        // scores: 8 columns per thread, dot over 64
        float acc[8];
        #pragma unroll
        for (int jj = 0; jj < 8; jj++) acc[jj] = 0.f;
        int jbase = sub * 8;
        #pragma unroll 8
        for (int d = 0; d < 64; d++) {
            float qd = qs[row][d];
            #pragma unroll
            for (int jj = 0; jj < 8; jj++)
                acc[jj] = fmaf(qd, ks[jbase + jj][d], acc[jj]);
        }
        float mymax = -INFINITY;
        #pragma unroll
        for (int jj = 0; jj < 8; jj++) {
            float sc = acc[jj] * 0.125f;
            if (mrow[t0 + jbase + jj] == 0) sc = -1e9f;
            acc[jj] = sc;
            mymax = fmaxf(mymax, sc);
        }
        mymax = fmaxf(mymax, __shfl_xor_sync(0xffffffffu, mymax, 1));
        mymax = fmaxf(mymax, __shfl_xor_sync(0xffffffffu, mymax, 2));
        float m_new = fmaxf(m_i, mymax);
        float psum = 0.f;
        #pragma unroll
        for (int jj = 0; jj < 8; jj++) {
            float p = expf(acc[jj] - m_new);
            ps[row][jbase + jj] = p;
            psum += p;
        }
        psum += __shfl_xor_sync(0xffffffffu, psum, 1);
        psum += __shfl_xor_sync(0xffffffffu, psum, 2);
        float alpha = expf(m_i - m_new);
        l_i = l_i * alpha + psum;
        m_i = m_new;
        __syncthreads();

        // o update: dims sub*16 .. sub*16+15
        int dbase = sub * 16;
        #pragma unroll
        for (int d = 0; d < 16; d++) o[d] *= alpha;
        #pragma unroll 4
        for (int j = 0; j < 32; j++) {
            float p = ps[row][j];
            #pragma unroll
            for (int d = 0; d < 16; d++)
                o[d] = fmaf(p, vs[j][dbase + d], o[d]);
        }
    }

    float invl = 1.f / l_i;
    float* cr = ctx + ((size_t)b * SEQ + q0 + row) * DMODEL + h * DK + sub * 16;
    #pragma unroll
    for (int d4 = 0; d4 < 4; d4++) {
        float4 ov;
        ov.x = o[d4*4+0] * invl; ov.y = o[d4*4+1] * invl;
        ov.z = o[d4*4+2] * invl; ov.w = o[d4*4+3] * invl;
        *(float4*)(cr + d4 * 4) = ov;
    }
}

// ---------------- new_memory = broadcast(mean over seq) ----------------
__global__ __launch_bounds__(1024) void mem_partial_kernel(
    const float* __restrict__ xo, float* __restrict__ part)
{
    int b = blockIdx.x, cz = blockIdx.y, d = threadIdx.x;
    const float* base = xo + ((size_t)b * SEQ + cz * 128) * DMODEL + d;
    float s = 0.f;
    #pragma unroll 4
    for (int i = 0; i < 128; i++) s += base[(size_t)i * DMODEL];
    part[((size_t)b * 16 + cz) * DMODEL + d] = s;
}

__global__ __launch_bounds__(1024) void mem_final_kernel(
    const float* __restrict__ part, float* __restrict__ memout)
{
    int b = blockIdx.x, d = threadIdx.x;
    float s = 0.f;
    #pragma unroll
    for (int i = 0; i < 16; i++) s += part[((size_t)b * 16 + i) * DMODEL + d];
    float vv = s * (1.f / SEQ);
    #pragma unroll
    for (int m = 0; m < MEMT; m++)
        memout[((size_t)b * MEMT + m) * DMODEL + d] = vv;
}

// ---------------- launch ----------------
extern "C" void kernel_launch(void* const* d_in, const int* in_sizes, int n_in,
                              void* d_out, int out_size)
{
    const float* x    = (const float*)d_in[0];
    const int*   mask = (const int*)  d_in[1];
    const float* mem  = (const float*)d_in[2];
    const float* wq   = (const float*)d_in[3];
    const float* wk   = (const float*)d_in[4];
    const float* wv   = (const float*)d_in[5];
    const float* wo   = (const float*)d_in[6];
    const float* ln1a = (const float*)d_in[7];
    const float* ln1b = (const float*)d_in[8];
    const float* ln2a = (const float*)d_in[9];
    const float* ln2b = (const float*)d_in[10];
    const float* fw1  = (const float*)d_in[11];
    const float* fb1  = (const float*)d_in[12];
    const float* fw2  = (const float*)d_in[13];
    const float* fb2  = (const float*)d_in[14];
    float* out = (float*)d_out;
    float* out_mem = out + (size_t)ROWS * DMODEL;

    void* p;
    float *xn, *q, *k, *v, *ctx, *x1, *xn2, *h1, *part;
    cudaGetSymbolAddress(&p, g_xn);  xn  = (float*)p;
    cudaGetSymbolAddress(&p, g_q);   q   = (float*)p;
    cudaGetSymbolAddress(&p, g_k);   k   = (float*)p;
    cudaGetSymbolAddress(&p, g_v);   v   = (float*)p;
    cudaGetSymbolAddress(&p, g_ctx); ctx = (float*)p;
    cudaGetSymbolAddress(&p, g_x1);  x1  = (float*)p;
    cudaGetSymbolAddress(&p, g_xn2); xn2 = (float*)p;
    cudaGetSymbolAddress(&p, g_h1);  h1  = (float*)p;
    cudaGetSymbolAddress(&p, g_part);part= (float*)p;

    // LN1
    ln_kernel<<<ROWS, 256>>>(x, ln1a, ln1b, xn);

    // Q/K/V projections into head layout
    gemm_kernel<EPI_QHEAD> <<<dim3(DMODEL/64, ROWS/128), 256>>>(xn, wq, q, nullptr, nullptr, ROWS, DMODEL, DMODEL);
    gemm_kernel<EPI_KVHEAD><<<dim3(DMODEL/64, ROWS/128), 256>>>(xn, wk, k, nullptr, nullptr, ROWS, DMODEL, DMODEL);
    gemm_kernel<EPI_KVHEAD><<<dim3(DMODEL/64, ROWS/128), 256>>>(xn, wv, v, nullptr, nullptr, ROWS, DMODEL, DMODEL);

    // memory-token K/V rows (broadcast over batch)
    memproj_kernel<<<MEMT, 1024>>>(mem, wk, wv, k, v);

    // attention
    attn_kernel<<<dim3(SEQ/64, BATCH*NHEADS), 256>>>(q, k, v, mask, ctx);

    // x1 = x + ctx @ w_o
    gemm_kernel<EPI_RESID><<<dim3(DMODEL/64, ROWS/128), 256>>>(ctx, wo, x1, nullptr, x, ROWS, DMODEL, DMODEL);

    // LN2
    ln_kernel<<<ROWS, 256>>>(x1, ln2a, ln2b, xn2);

    // FFN
    gemm_kernel<EPI_BIAS_RELU> <<<dim3(DFF/64,   ROWS/128), 256>>>(xn2, fw1, h1, fb1, nullptr, ROWS, DFF, DMODEL);
    gemm_kernel<EPI_BIAS_RESID><<<dim3(DMODEL/64, ROWS/128), 256>>>(h1, fw2, out, fb2, x1, ROWS, DMODEL, DFF);

    // new_memory
    mem_partial_kernel<<<dim3(BATCH, 16), 1024>>>(out, part);
    mem_final_kernel<<<BATCH, 1024>>>(part, out_mem);
}

// round 2
// speedup vs baseline: 1.5578x; 1.5578x over previous
#include <cuda_runtime.h>
#include <math.h>
#include <stdint.h>

// ---------------- problem constants ----------------
#define BATCH 4
#define SEQ   2048
#define DMODEL 1024
#define NHEADS 16
#define DK    64
#define MEMT  32
#define TTOT  (SEQ + MEMT)       // 2080
#define DFF   4096
#define ROWS  (BATCH * SEQ)      // 8192

// ---------------- device scratch ----------------
__device__ float g_xn [ROWS * DMODEL];
__device__ float g_q  [BATCH * NHEADS * SEQ  * DK];
__device__ float g_k  [BATCH * NHEADS * TTOT * DK];
__device__ float g_v  [BATCH * NHEADS * TTOT * DK];
__device__ float g_ctx[ROWS * DMODEL];
__device__ float g_x1 [ROWS * DMODEL];
__device__ float g_xn2[ROWS * DMODEL];
__device__ float g_h1 [ROWS * DFF];
__device__ float g_part[BATCH * 16 * DMODEL];

// ---------------- small helpers ----------------
__device__ __forceinline__ uint32_t f2tf32(float f) {
    uint32_t u;
    asm("cvt.rna.tf32.f32 %0, %1;" : "=r"(u) : "f"(f));
    return u;
}
__device__ __forceinline__ void cp_async16(uint32_t dst, const void* src) {
    asm volatile("cp.async.cg.shared.global [%0], [%1], 16;\n" :: "r"(dst), "l"(src));
}
__device__ __forceinline__ void mma_tf32(float* c, const uint32_t* a, const uint32_t* b) {
    asm volatile(
        "mma.sync.aligned.m16n8k8.row.col.f32.tf32.tf32.f32 "
        "{%0,%1,%2,%3},{%4,%5,%6,%7},{%8,%9},{%0,%1,%2,%3};"
        : "+f"(c[0]), "+f"(c[1]), "+f"(c[2]), "+f"(c[3])
        : "r"(a[0]), "r"(a[1]), "r"(a[2]), "r"(a[3]), "r"(b[0]), "r"(b[1]));
}

// ---------------- layer norm (ddof=1, div by std+eps) ----------------
__global__ __launch_bounds__(256) void ln_kernel(
    const float* __restrict__ x, const float* __restrict__ alpha,
    const float* __restrict__ bias, float* __restrict__ out)
{
    int row = blockIdx.x;
    int tid = threadIdx.x;
    const float4* xr = (const float4*)(x + (size_t)row * DMODEL);
    float4 v = xr[tid];
    float s  = v.x + v.y + v.z + v.w;
    float ss = v.x*v.x + v.y*v.y + v.z*v.z + v.w*v.w;
    #pragma unroll
    for (int off = 16; off > 0; off >>= 1) {
        s  += __shfl_xor_sync(0xffffffffu, s,  off);
        ss += __shfl_xor_sync(0xffffffffu, ss, off);
    }
    __shared__ float rs[8], rss[8];
    int wid = tid >> 5, lane = tid & 31;
    if (lane == 0) { rs[wid] = s; rss[wid] = ss; }
    __syncthreads();
    float S = 0.f, SS = 0.f;
    #pragma unroll
    for (int w = 0; w < 8; w++) { S += rs[w]; SS += rss[w]; }
    float mean = S * (1.f / DMODEL);
    float var  = (SS - (float)DMODEL * mean * mean) * (1.f / (DMODEL - 1));
    float inv  = 1.f / (sqrtf(fmaxf(var, 0.f)) + 1e-6f);
    float4 a  = ((const float4*)alpha)[tid];
    float4 bb = ((const float4*)bias)[tid];
    float4 o;
    o.x = a.x * (v.x - mean) * inv + bb.x;
    o.y = a.y * (v.y - mean) * inv + bb.y;
    o.z = a.z * (v.z - mean) * inv + bb.z;
    o.w = a.w * (v.w - mean) * inv + bb.w;
    ((float4*)(out + (size_t)row * DMODEL))[tid] = o;
}

// ---------------- TF32 tensor-core GEMM: C = A[MxK] @ W[KxN] ----------------
#define EPI_PLAIN      0
#define EPI_QHEAD      1
#define EPI_KVHEAD     2
#define EPI_RESID      3
#define EPI_BIAS_RELU  4
#define EPI_BIAS_RESID 5

// tile config
#define BM 128
#define BN 128
#define BK 32
#define AST 36            // BK + 4 pad  -> conflict-free A frag loads
#define BST 136           // BN + 8 pad  -> conflict-free B frag loads
#define ASZ (BM * AST)    // 4608 floats per stage
#define BSZ (BK * BST)    // 4352 floats per stage
#define GEMM_SMEM_BYTES ((2 * ASZ + 2 * BSZ) * 4)   // 71680

template<int EPI>
__global__ __launch_bounds__(256) void gemm_tc(
    const float* __restrict__ A, const float* __restrict__ W,
    float* __restrict__ C, const float* __restrict__ bias,
    const float* __restrict__ R, int M, int N, int K)
{
    extern __shared__ float sm[];
    float* As = sm;             // 2 stages of [BM][AST]
    float* Bs = sm + 2 * ASZ;   // 2 stages of [BK][BST]

    int tid  = threadIdx.x;
    int warp = tid >> 5, lane = tid & 31;
    int wm = warp & 1;          // 0..1 -> 64-row slab
    int wn = warp >> 1;         // 0..3 -> 32-col slab
    int lr = lane >> 2;         // 0..7
    int lc = lane & 3;          // 0..3

    const float* Abase = A + (size_t)blockIdx.y * BM * K;
    const float* Wbase = W + (size_t)blockIdx.x * BN;

    uint32_t sA = __cvta_generic_to_shared(As);
    uint32_t sB = __cvta_generic_to_shared(Bs);

    float acc[4][4][4];
    #pragma unroll
    for (int mt = 0; mt < 4; mt++)
        #pragma unroll
        for (int nt = 0; nt < 4; nt++)
            #pragma unroll
            for (int i = 0; i < 4; i++) acc[mt][nt][i] = 0.f;

#define LOAD_STAGE(st, kt) do {                                                  \
        _Pragma("unroll")                                                        \
        for (int l = 0; l < 4; l++) {                                            \
            int fid = tid + l * 256;                                             \
            int r = fid >> 3, c4 = fid & 7;                                      \
            cp_async16(sA + (uint32_t)(((st) * ASZ) + r * AST + c4 * 4) * 4,     \
                       Abase + (size_t)r * K + (size_t)(kt) * BK + c4 * 4);      \
        }                                                                        \
        _Pragma("unroll")                                                        \
        for (int l = 0; l < 4; l++) {                                            \
            int fid = tid + l * 256;                                             \
            int r = fid >> 5, c4 = fid & 31;                                     \
            cp_async16(sB + (uint32_t)(((st) * BSZ) + r * BST + c4 * 4) * 4,     \
                       Wbase + (size_t)((kt) * BK + r) * N + c4 * 4);            \
        }                                                                        \
        asm volatile("cp.async.commit_group;");                                  \
    } while (0)

    int NT = K / BK;
    LOAD_STAGE(0, 0);

    for (int kt = 0; kt < NT; kt++) {
        int st = kt & 1;
        if (kt + 1 < NT) {
            LOAD_STAGE(st ^ 1, kt + 1);
            asm volatile("cp.async.wait_group 1;");
        } else {
            asm volatile("cp.async.wait_group 0;");
        }
        __syncthreads();

        const float* as = As + st * ASZ;
        const float* bs = Bs + st * BSZ;

        #pragma unroll
        for (int ks = 0; ks < 4; ks++) {
            int k0 = ks * 8 + lc;
            uint32_t af[4][4], bf[4][2];
            #pragma unroll
            for (int mt = 0; mt < 4; mt++) {
                int r0 = wm * 64 + mt * 16 + lr;
                af[mt][0] = f2tf32(as[r0       * AST + k0    ]);
                af[mt][1] = f2tf32(as[(r0 + 8) * AST + k0    ]);
                af[mt][2] = f2tf32(as[r0       * AST + k0 + 4]);
                af[mt][3] = f2tf32(as[(r0 + 8) * AST + k0 + 4]);
            }
            #pragma unroll
            for (int nt = 0; nt < 4; nt++) {
                int c0 = wn * 32 + nt * 8 + lr;
                bf[nt][0] = f2tf32(bs[k0       * BST + c0]);
                bf[nt][1] = f2tf32(bs[(k0 + 4) * BST + c0]);
            }
            #pragma unroll
            for (int mt = 0; mt < 4; mt++)
                #pragma unroll
                for (int nt = 0; nt < 4; nt++)
                    mma_tf32(acc[mt][nt], af[mt], bf[nt]);
        }
        __syncthreads();
    }

    // epilogue: c0,c1 = (row, 2lc),(row, 2lc+1); c2,c3 = (row+8, ...)
    #pragma unroll
    for (int mt = 0; mt < 4; mt++) {
        #pragma unroll
        for (int rg = 0; rg < 2; rg++) {
            int r = blockIdx.y * BM + wm * 64 + mt * 16 + lr + rg * 8;
            #pragma unroll
            for (int nt = 0; nt < 4; nt++) {
                int c = blockIdx.x * BN + wn * 32 + nt * 8 + lc * 2;
                float v0 = acc[mt][nt][rg * 2 + 0];
                float v1 = acc[mt][nt][rg * 2 + 1];
                if (EPI == EPI_PLAIN) {
                    float2 o = make_float2(v0, v1);
                    *(float2*)(C + (size_t)r * N + c) = o;
                } else if (EPI == EPI_QHEAD) {
                    int b = r >> 11, s = r & 2047, h = c >> 6, d = c & 63;
                    float2 o = make_float2(v0, v1);
                    *(float2*)(C + ((((size_t)(b * NHEADS + h)) * SEQ + s) * DK + d)) = o;
                } else if (EPI == EPI_KVHEAD) {
                    int b = r >> 11, s = r & 2047, h = c >> 6, d = c & 63;
                    float2 o = make_float2(v0, v1);
                    *(float2*)(C + ((((size_t)(b * NHEADS + h)) * TTOT + MEMT + s) * DK + d)) = o;
                } else if (EPI == EPI_RESID) {
                    float2 rr = *(const float2*)(R + (size_t)r * N + c);
                    float2 o = make_float2(v0 + rr.x, v1 + rr.y);
                    *(float2*)(C + (size_t)r * N + c) = o;
                } else if (EPI == EPI_BIAS_RELU) {
                    float2 bb = *(const float2*)(bias + c);
                    float2 o = make_float2(fmaxf(v0 + bb.x, 0.f), fmaxf(v1 + bb.y, 0.f));
                    *(float2*)(C + (size_t)r * N + c) = o;
                } else if (EPI == EPI_BIAS_RESID) {
                    float2 bb = *(const float2*)(bias + c);
                    float2 rr = *(const float2*)(R + (size_t)r * N + c);
                    float2 o = make_float2(v0 + bb.x + rr.x, v1 + bb.y + rr.y);
                    *(float2*)(C + (size_t)r * N + c) = o;
                }
            }
        }
    }
#undef LOAD_STAGE
}

// ---------------- memory-token K/V projection ----------------
__global__ __launch_bounds__(1024) void memproj_kernel(
    const float* __restrict__ mt, const float* __restrict__ wk,
    const float* __restrict__ wv, float* __restrict__ kh, float* __restrict__ vh)
{
    int m = blockIdx.x;        // 0..31
    int c = threadIdx.x;       // 0..1023
    float ak = 0.f, av = 0.f;
    #pragma unroll 4
    for (int kk = 0; kk < DMODEL; kk++) {
        float xm = mt[(size_t)m * DMODEL + kk];
        ak = fmaf(xm, wk[(size_t)kk * DMODEL + c], ak);
        av = fmaf(xm, wv[(size_t)kk * DMODEL + c], av);
    }
    int h = c >> 6, d = c & 63;
    #pragma unroll
    for (int b = 0; b < BATCH; b++) {
        size_t idx = (((size_t)(b * NHEADS + h)) * TTOT + m) * DK + d;
        kh[idx] = ak;
        vh[idx] = av;
    }
}

// ---------------- flash attention (fp32, online softmax) ----------------
__global__ __launch_bounds__(256) void attn_kernel(
    const float* __restrict__ q, const float* __restrict__ k,
    const float* __restrict__ v, const int* __restrict__ mask,
    float* __restrict__ ctx)
{
    __shared__ float qs[64][65];
    __shared__ float ks[32][65];
    __shared__ float vs[32][65];
    __shared__ float ps[64][33];

    int tid = threadIdx.x;
    int row = tid >> 2;
    int sub = tid & 3;
    int bh = blockIdx.y;
    int b  = bh >> 4;
    int h  = bh & 15;
    int q0 = blockIdx.x * 64;

    const float* qb = q + (((size_t)bh) * SEQ + q0) * DK;
    const float* kb = k + ((size_t)bh) * TTOT * DK;
    const float* vb = v + ((size_t)bh) * TTOT * DK;

    #pragma unroll
    for (int l = 0; l < 4; l++) {
        int fid = tid + l * 256;
        int r = fid >> 4, c = (fid & 15) << 2;
        float4 t = *(const float4*)(qb + (size_t)r * DK + c);
        qs[r][c] = t.x; qs[r][c+1] = t.y; qs[r][c+2] = t.z; qs[r][c+3] = t.w;
    }

    float m_i = -INFINITY, l_i = 0.f;
    float o[16];
    #pragma unroll
    for (int d = 0; d < 16; d++) o[d] = 0.f;

    int qg = q0 + row;
    const int* mrow = mask + (size_t)qg * TTOT;

    for (int ch = 0; ch < 65; ch++) {
        int t0 = ch * 32;
        __syncthreads();
        #pragma unroll
        for (int l = 0; l < 2; l++) {
            int fid = tid + l * 256;
            int r = fid >> 4, c = (fid & 15) << 2;
            float4 tk = *(const float4*)(kb + (size_t)(t0 + r) * DK + c);
            ks[r][c] = tk.x; ks[r][c+1] = tk.y; ks[r][c+2] = tk.z; ks[r][c+3] = tk.w;
            float4 tv = *(const float4*)(vb + (size_t)(t0 + r) * DK + c);
            vs[r][c] = tv.x; vs[r][c+1] = tv.y; vs[r][c+2] = tv.z; vs[r][c+3] = tv.w;
        }
        __syncthreads();

        float acc[8];
        #pragma unroll
        for (int jj = 0; jj < 8; jj++) acc[jj] = 0.f;
        int jbase = sub * 8;
        #pragma unroll 8
        for (int d = 0; d < 64; d++) {
            float qd = qs[row][d];
            #pragma unroll
            for (int jj = 0; jj < 8; jj++)
                acc[jj] = fmaf(qd, ks[jbase + jj][d], acc[jj]);
        }
        float mymax = -INFINITY;
        #pragma unroll
        for (int jj = 0; jj < 8; jj++) {
            float sc = acc[jj] * 0.125f;
            if (mrow[t0 + jbase + jj] == 0) sc = -1e9f;
            acc[jj] = sc;
            mymax = fmaxf(mymax, sc);
        }
        mymax = fmaxf(mymax, __shfl_xor_sync(0xffffffffu, mymax, 1));
        mymax = fmaxf(mymax, __shfl_xor_sync(0xffffffffu, mymax, 2));
        float m_new = fmaxf(m_i, mymax);
        float psum = 0.f;
        #pragma unroll
        for (int jj = 0; jj < 8; jj++) {
            float p = expf(acc[jj] - m_new);
            ps[row][jbase + jj] = p;
            psum += p;
        }
        psum += __shfl_xor_sync(0xffffffffu, psum, 1);
        psum += __shfl_xor_sync(0xffffffffu, psum, 2);
        float alpha = expf(m_i - m_new);
        l_i = l_i * alpha + psum;
        m_i = m_new;
        __syncthreads();

        int dbase = sub * 16;
        #pragma unroll
        for (int d = 0; d < 16; d++) o[d] *= alpha;
        #pragma unroll 4
        for (int j = 0; j < 32; j++) {
            float p = ps[row][j];
            #pragma unroll
            for (int d = 0; d < 16; d++)
                o[d] = fmaf(p, vs[j][dbase + d], o[d]);
        }
    }

    float invl = 1.f / l_i;
    float* cr = ctx + ((size_t)b * SEQ + q0 + row) * DMODEL + h * DK + sub * 16;
    #pragma unroll
    for (int d4 = 0; d4 < 4; d4++) {
        float4 ov;
        ov.x = o[d4*4+0] * invl; ov.y = o[d4*4+1] * invl;
        ov.z = o[d4*4+2] * invl; ov.w = o[d4*4+3] * invl;
        *(float4*)(cr + d4 * 4) = ov;
    }
}

// ---------------- new_memory = broadcast(mean over seq) ----------------
__global__ __launch_bounds__(1024) void mem_partial_kernel(
    const float* __restrict__ xo, float* __restrict__ part)
{
    int b = blockIdx.x, cz = blockIdx.y, d = threadIdx.x;
    const float* base = xo + ((size_t)b * SEQ + cz * 128) * DMODEL + d;
    float s = 0.f;
    #pragma unroll 4
    for (int i = 0; i < 128; i++) s += base[(size_t)i * DMODEL];
    part[((size_t)b * 16 + cz) * DMODEL + d] = s;
}

__global__ __launch_bounds__(1024) void mem_final_kernel(
    const float* __restrict__ part, float* __restrict__ memout)
{
    int b = blockIdx.x, d = threadIdx.x;
    float s = 0.f;
    #pragma unroll
    for (int i = 0; i < 16; i++) s += part[((size_t)b * 16 + i) * DMODEL + d];
    float vv = s * (1.f / SEQ);
    #pragma unroll
    for (int m = 0; m < MEMT; m++)
        memout[((size_t)b * MEMT + m) * DMODEL + d] = vv;
}

// ---------------- launch ----------------
extern "C" void kernel_launch(void* const* d_in, const int* in_sizes, int n_in,
                              void* d_out, int out_size)
{
    const float* x    = (const float*)d_in[0];
    const int*   mask = (const int*)  d_in[1];
    const float* mem  = (const float*)d_in[2];
    const float* wq   = (const float*)d_in[3];
    const float* wk   = (const float*)d_in[4];
    const float* wv   = (const float*)d_in[5];
    const float* wo   = (const float*)d_in[6];
    const float* ln1a = (const float*)d_in[7];
    const float* ln1b = (const float*)d_in[8];
    const float* ln2a = (const float*)d_in[9];
    const float* ln2b = (const float*)d_in[10];
    const float* fw1  = (const float*)d_in[11];
    const float* fb1  = (const float*)d_in[12];
    const float* fw2  = (const float*)d_in[13];
    const float* fb2  = (const float*)d_in[14];
    float* out = (float*)d_out;
    float* out_mem = out + (size_t)ROWS * DMODEL;

    void* p;
    float *xn, *q, *k, *v, *ctx, *x1, *xn2, *h1, *part;
    cudaGetSymbolAddress(&p, g_xn);  xn  = (float*)p;
    cudaGetSymbolAddress(&p, g_q);   q   = (float*)p;
    cudaGetSymbolAddress(&p, g_k);   k   = (float*)p;
    cudaGetSymbolAddress(&p, g_v);   v   = (float*)p;
    cudaGetSymbolAddress(&p, g_ctx); ctx = (float*)p;
    cudaGetSymbolAddress(&p, g_x1);  x1  = (float*)p;
    cudaGetSymbolAddress(&p, g_xn2); xn2 = (float*)p;
    cudaGetSymbolAddress(&p, g_h1);  h1  = (float*)p;
    cudaGetSymbolAddress(&p, g_part);part= (float*)p;

    // allow >48KB dynamic smem for all gemm instantiations
    cudaFuncSetAttribute(gemm_tc<EPI_QHEAD>,     cudaFuncAttributeMaxDynamicSharedMemorySize, GEMM_SMEM_BYTES);
    cudaFuncSetAttribute(gemm_tc<EPI_KVHEAD>,    cudaFuncAttributeMaxDynamicSharedMemorySize, GEMM_SMEM_BYTES);
    cudaFuncSetAttribute(gemm_tc<EPI_RESID>,     cudaFuncAttributeMaxDynamicSharedMemorySize, GEMM_SMEM_BYTES);
    cudaFuncSetAttribute(gemm_tc<EPI_BIAS_RELU>, cudaFuncAttributeMaxDynamicSharedMemorySize, GEMM_SMEM_BYTES);
    cudaFuncSetAttribute(gemm_tc<EPI_BIAS_RESID>,cudaFuncAttributeMaxDynamicSharedMemorySize, GEMM_SMEM_BYTES);

    // LN1
    ln_kernel<<<ROWS, 256>>>(x, ln1a, ln1b, xn);

    // Q/K/V projections into head layout (TF32 tensor cores)
    gemm_tc<EPI_QHEAD> <<<dim3(DMODEL/BN, ROWS/BM), 256, GEMM_SMEM_BYTES>>>(xn, wq, q, nullptr, nullptr, ROWS, DMODEL, DMODEL);
    gemm_tc<EPI_KVHEAD><<<dim3(DMODEL/BN, ROWS/BM), 256, GEMM_SMEM_BYTES>>>(xn, wk, k, nullptr, nullptr, ROWS, DMODEL, DMODEL);
    gemm_tc<EPI_KVHEAD><<<dim3(DMODEL/BN, ROWS/BM), 256, GEMM_SMEM_BYTES>>>(xn, wv, v, nullptr, nullptr, ROWS, DMODEL, DMODEL);

    // memory-token K/V rows (broadcast over batch)
    memproj_kernel<<<MEMT, 1024>>>(mem, wk, wv, k, v);

    // attention
    attn_kernel<<<dim3(SEQ/64, BATCH*NHEADS), 256>>>(q, k, v, mask, ctx);

    // x1 = x + ctx @ w_o
    gemm_tc<EPI_RESID><<<dim3(DMODEL/BN, ROWS/BM), 256, GEMM_SMEM_BYTES>>>(ctx, wo, x1, nullptr, x, ROWS, DMODEL, DMODEL);

    // LN2
    ln_kernel<<<ROWS, 256>>>(x1, ln2a, ln2b, xn2);

    // FFN
    gemm_tc<EPI_BIAS_RELU> <<<dim3(DFF/BN,   ROWS/BM), 256, GEMM_SMEM_BYTES>>>(xn2, fw1, h1, fb1, nullptr, ROWS, DFF, DMODEL);
    gemm_tc<EPI_BIAS_RESID><<<dim3(DMODEL/BN, ROWS/BM), 256, GEMM_SMEM_BYTES>>>(h1, fw2, out, fb2, x1, ROWS, DMODEL, DFF);

    // new_memory
    mem_partial_kernel<<<dim3(BATCH, 16), 1024>>>(out, part);
    mem_final_kernel<<<BATCH, 1024>>>(part, out_mem);
}

// round 3
// speedup vs baseline: 5.3670x; 3.4452x over previous
#include <cuda_runtime.h>
#include <math.h>
#include <stdint.h>

// ---------------- problem constants ----------------
#define BATCH 4
#define SEQ   2048
#define DMODEL 1024
#define NHEADS 16
#define DK    64
#define MEMT  32
#define TTOT  (SEQ + MEMT)       // 2080
#define T_PAD 2112               // 33 * 64
#define NKT   33                 // key tiles of 64
#define DFF   4096
#define ROWS  (BATCH * SEQ)      // 8192
#define NWORDS 66                // mask bit-words per query row (covers T_PAD)

// ---------------- device scratch ----------------
__device__ float g_xn [ROWS * DMODEL];
__device__ float g_q  [BATCH * NHEADS * SEQ   * DK];
__device__ float g_k  [BATCH * NHEADS * T_PAD * DK];
__device__ float g_v  [BATCH * NHEADS * T_PAD * DK];
__device__ float g_ctx[ROWS * DMODEL];
__device__ float g_x1 [ROWS * DMODEL];
__device__ float g_xn2[ROWS * DMODEL];
__device__ float g_h1 [ROWS * DFF];
__device__ float g_part[BATCH * 16 * DMODEL];
__device__ uint32_t g_mb[SEQ * NWORDS];

// ---------------- small helpers ----------------
__device__ __forceinline__ uint32_t f2tf32(float f) {
    uint32_t u;
    asm("cvt.rna.tf32.f32 %0, %1;" : "=r"(u) : "f"(f));
    return u;
}
__device__ __forceinline__ void cp_async16(uint32_t dst, const void* src) {
    asm volatile("cp.async.cg.shared.global [%0], [%1], 16;\n" :: "r"(dst), "l"(src));
}
__device__ __forceinline__ void mma_tf32(float* c, const uint32_t* a, const uint32_t* b) {
    asm volatile(
        "mma.sync.aligned.m16n8k8.row.col.f32.tf32.tf32.f32 "
        "{%0,%1,%2,%3},{%4,%5,%6,%7},{%8,%9},{%0,%1,%2,%3};"
        : "+f"(c[0]), "+f"(c[1]), "+f"(c[2]), "+f"(c[3])
        : "r"(a[0]), "r"(a[1]), "r"(a[2]), "r"(a[3]), "r"(b[0]), "r"(b[1]));
}

// ---------------- layer norm (ddof=1, div by std+eps) ----------------
__global__ __launch_bounds__(256) void ln_kernel(
    const float* __restrict__ x, const float* __restrict__ alpha,
    const float* __restrict__ bias, float* __restrict__ out)
{
    int row = blockIdx.x;
    int tid = threadIdx.x;
    const float4* xr = (const float4*)(x + (size_t)row * DMODEL);
    float4 v = xr[tid];
    float s  = v.x + v.y + v.z + v.w;
    float ss = v.x*v.x + v.y*v.y + v.z*v.z + v.w*v.w;
    #pragma unroll
    for (int off = 16; off > 0; off >>= 1) {
        s  += __shfl_xor_sync(0xffffffffu, s,  off);
        ss += __shfl_xor_sync(0xffffffffu, ss, off);
    }
    __shared__ float rs[8], rss[8];
    int wid = tid >> 5, lane = tid & 31;
    if (lane == 0) { rs[wid] = s; rss[wid] = ss; }
    __syncthreads();
    float S = 0.f, SS = 0.f;
    #pragma unroll
    for (int w = 0; w < 8; w++) { S += rs[w]; SS += rss[w]; }
    float mean = S * (1.f / DMODEL);
    float var  = (SS - (float)DMODEL * mean * mean) * (1.f / (DMODEL - 1));
    float inv  = 1.f / (sqrtf(fmaxf(var, 0.f)) + 1e-6f);
    float4 a  = ((const float4*)alpha)[tid];
    float4 bb = ((const float4*)bias)[tid];
    float4 o;
    o.x = a.x * (v.x - mean) * inv + bb.x;
    o.y = a.y * (v.y - mean) * inv + bb.y;
    o.z = a.z * (v.z - mean) * inv + bb.z;
    o.w = a.w * (v.w - mean) * inv + bb.w;
    ((float4*)(out + (size_t)row * DMODEL))[tid] = o;
}

// ---------------- TF32 tensor-core GEMM: C = A[MxK] @ W[KxN] ----------------
#define EPI_PLAIN      0
#define EPI_QHEAD      1
#define EPI_KVHEAD     2
#define EPI_RESID      3
#define EPI_BIAS_RELU  4
#define EPI_BIAS_RESID 5

#define BM 128
#define BN 128
#define BK 32
#define AST 36
#define BST 136
#define ASZ (BM * AST)
#define BSZ (BK * BST)
#define GEMM_SMEM_BYTES ((2 * ASZ + 2 * BSZ) * 4)

template<int EPI>
__global__ __launch_bounds__(256) void gemm_tc(
    const float* __restrict__ A, const float* __restrict__ W,
    float* __restrict__ C, const float* __restrict__ bias,
    const float* __restrict__ R, int M, int N, int K)
{
    extern __shared__ float sm[];
    float* As = sm;
    float* Bs = sm + 2 * ASZ;

    int tid  = threadIdx.x;
    int warp = tid >> 5, lane = tid & 31;
    int wm = warp & 1;
    int wn = warp >> 1;
    int lr = lane >> 2;
    int lc = lane & 3;

    const float* Abase = A + (size_t)blockIdx.y * BM * K;
    const float* Wbase = W + (size_t)blockIdx.x * BN;

    uint32_t sA = __cvta_generic_to_shared(As);
    uint32_t sB = __cvta_generic_to_shared(Bs);

    float acc[4][4][4];
    #pragma unroll
    for (int mt = 0; mt < 4; mt++)
        #pragma unroll
        for (int nt = 0; nt < 4; nt++)
            #pragma unroll
            for (int i = 0; i < 4; i++) acc[mt][nt][i] = 0.f;

#define LOAD_STAGE(st, kt) do {                                                  \
        _Pragma("unroll")                                                        \
        for (int l = 0; l < 4; l++) {                                            \
            int fid = tid + l * 256;                                             \
            int r = fid >> 3, c4 = fid & 7;                                      \
            cp_async16(sA + (uint32_t)(((st) * ASZ) + r * AST + c4 * 4) * 4,     \
                       Abase + (size_t)r * K + (size_t)(kt) * BK + c4 * 4);      \
        }                                                                        \
        _Pragma("unroll")                                                        \
        for (int l = 0; l < 4; l++) {                                            \
            int fid = tid + l * 256;                                             \
            int r = fid >> 5, c4 = fid & 31;                                     \
            cp_async16(sB + (uint32_t)(((st) * BSZ) + r * BST + c4 * 4) * 4,     \
                       Wbase + (size_t)((kt) * BK + r) * N + c4 * 4);            \
        }                                                                        \
        asm volatile("cp.async.commit_group;");                                  \
    } while (0)

    int NT = K / BK;
    LOAD_STAGE(0, 0);

    for (int kt = 0; kt < NT; kt++) {
        int st = kt & 1;
        if (kt + 1 < NT) {
            LOAD_STAGE(st ^ 1, kt + 1);
            asm volatile("cp.async.wait_group 1;");
        } else {
            asm volatile("cp.async.wait_group 0;");
        }
        __syncthreads();

        const float* as = As + st * ASZ;
        const float* bs = Bs + st * BSZ;

        #pragma unroll
        for (int ks = 0; ks < 4; ks++) {
            int k0 = ks * 8 + lc;
            uint32_t af[4][4], bf[4][2];
            #pragma unroll
            for (int mt = 0; mt < 4; mt++) {
                int r0 = wm * 64 + mt * 16 + lr;
                af[mt][0] = f2tf32(as[r0       * AST + k0    ]);
                af[mt][1] = f2tf32(as[(r0 + 8) * AST + k0    ]);
                af[mt][2] = f2tf32(as[r0       * AST + k0 + 4]);
                af[mt][3] = f2tf32(as[(r0 + 8) * AST + k0 + 4]);
            }
            #pragma unroll
            for (int nt = 0; nt < 4; nt++) {
                int c0 = wn * 32 + nt * 8 + lr;
                bf[nt][0] = f2tf32(bs[k0       * BST + c0]);
                bf[nt][1] = f2tf32(bs[(k0 + 4) * BST + c0]);
            }
            #pragma unroll
            for (int mt = 0; mt < 4; mt++)
                #pragma unroll
                for (int nt = 0; nt < 4; nt++)
                    mma_tf32(acc[mt][nt], af[mt], bf[nt]);
        }
        __syncthreads();
    }

    #pragma unroll
    for (int mt = 0; mt < 4; mt++) {
        #pragma unroll
        for (int rg = 0; rg < 2; rg++) {
            int r = blockIdx.y * BM + wm * 64 + mt * 16 + lr + rg * 8;
            #pragma unroll
            for (int nt = 0; nt < 4; nt++) {
                int c = blockIdx.x * BN + wn * 32 + nt * 8 + lc * 2;
                float v0 = acc[mt][nt][rg * 2 + 0];
                float v1 = acc[mt][nt][rg * 2 + 1];
                if (EPI == EPI_PLAIN) {
                    *(float2*)(C + (size_t)r * N + c) = make_float2(v0, v1);
                } else if (EPI == EPI_QHEAD) {
                    int b = r >> 11, s = r & 2047, h = c >> 6, d = c & 63;
                    *(float2*)(C + ((((size_t)(b * NHEADS + h)) * SEQ + s) * DK + d)) = make_float2(v0, v1);
                } else if (EPI == EPI_KVHEAD) {
                    int b = r >> 11, s = r & 2047, h = c >> 6, d = c & 63;
                    *(float2*)(C + ((((size_t)(b * NHEADS + h)) * T_PAD + MEMT + s) * DK + d)) = make_float2(v0, v1);
                } else if (EPI == EPI_RESID) {
                    float2 rr = *(const float2*)(R + (size_t)r * N + c);
                    *(float2*)(C + (size_t)r * N + c) = make_float2(v0 + rr.x, v1 + rr.y);
                } else if (EPI == EPI_BIAS_RELU) {
                    float2 bb = *(const float2*)(bias + c);
                    *(float2*)(C + (size_t)r * N + c) = make_float2(fmaxf(v0 + bb.x, 0.f), fmaxf(v1 + bb.y, 0.f));
                } else if (EPI == EPI_BIAS_RESID) {
                    float2 bb = *(const float2*)(bias + c);
                    float2 rr = *(const float2*)(R + (size_t)r * N + c);
                    *(float2*)(C + (size_t)r * N + c) = make_float2(v0 + bb.x + rr.x, v1 + bb.y + rr.y);
                }
            }
        }
    }
#undef LOAD_STAGE
}

// ---------------- memory-token K/V projection ----------------
__global__ __launch_bounds__(1024) void memproj_kernel(
    const float* __restrict__ mt, const float* __restrict__ wk,
    const float* __restrict__ wv, float* __restrict__ kh, float* __restrict__ vh)
{
    int m = blockIdx.x;
    int c = threadIdx.x;
    float ak = 0.f, av = 0.f;
    #pragma unroll 4
    for (int kk = 0; kk < DMODEL; kk++) {
        float xm = mt[(size_t)m * DMODEL + kk];
        ak = fmaf(xm, wk[(size_t)kk * DMODEL + c], ak);
        av = fmaf(xm, wv[(size_t)kk * DMODEL + c], av);
    }
    int h = c >> 6, d = c & 63;
    #pragma unroll
    for (int b = 0; b < BATCH; b++) {
        size_t idx = (((size_t)(b * NHEADS + h)) * T_PAD + m) * DK + d;
        kh[idx] = ak;
        vh[idx] = av;
    }
}

// ---------------- zero the K/V padding rows (t in [TTOT, T_PAD)) ----------------
__global__ __launch_bounds__(256) void padclear_kernel(float* k, float* v)
{
    int bh = blockIdx.x;
    size_t base = ((size_t)bh * T_PAD + TTOT) * DK;
    for (int i = threadIdx.x; i < (T_PAD - TTOT) * DK; i += 256) {
        k[base + i] = 0.f;
        v[base + i] = 0.f;
    }
}

// ---------------- compress mask to bits: mb[s][w] covers t = 32w..32w+31 ----------------
__global__ void maskbits_kernel(const int* __restrict__ mask, uint32_t* __restrict__ mb)
{
    int s = blockIdx.x;
    int w = threadIdx.x;            // 0..65
    uint32_t bits = 0;
    #pragma unroll 4
    for (int j = 0; j < 32; j++) {
        int t = w * 32 + j;
        if (t < TTOT && mask[(size_t)s * TTOT + t] != 0) bits |= (1u << j);
    }
    mb[(size_t)s * NWORDS + w] = bits;
}

// ---------------- TF32 tensor-core flash attention ----------------
// block: 256 thr (8 warps). 64 queries x full T. warp = (wm 0..3 rows, wn 0..1 col-half)
#define KST 68
#define VST 72
#define PST 68
#define ATTN_SMEM_BYTES ((2*64*KST + 2*64*VST + 64*PST + 256) * 4)

__global__ __launch_bounds__(256) void attn_tc(
    const float* __restrict__ q, const float* __restrict__ k,
    const float* __restrict__ v, const uint32_t* __restrict__ mb,
    float* __restrict__ ctx)
{
    extern __shared__ float smf[];
    float*    ks_ = smf;                          // 2 stages [64][KST]
    float*    vs_ = ks_ + 2 * 64 * KST;           // 2 stages [64][VST]
    uint32_t* ps_ = (uint32_t*)(vs_ + 2 * 64 * VST); // [64][PST] tf32
    float*    redmax = (float*)(ps_ + 64 * PST);  // [2][64]
    float*    redsum = redmax + 128;              // [2][64]

    int tid  = threadIdx.x;
    int warp = tid >> 5, lane = tid & 31;
    int wm = warp & 3, wn = warp >> 2;
    int lr = lane >> 2, lc = lane & 3;
    int bh = blockIdx.y;
    int b  = bh >> 4, h = bh & 15;
    int q0 = blockIdx.x * 64;

    const float* qb = q + (((size_t)bh) * SEQ + q0) * DK;
    const float* kb = k + ((size_t)bh) * T_PAD * DK;
    const float* vb = v + ((size_t)bh) * T_PAD * DK;

    int row0 = wm * 16 + lr;
    int row1 = row0 + 8;
    int grow0 = q0 + row0, grow1 = q0 + row1;

    // Q fragments resident in registers for all tiles
    uint32_t qf[8][4];
    #pragma unroll
    for (int ksi = 0; ksi < 8; ksi++) {
        qf[ksi][0] = f2tf32(qb[(size_t)row0 * DK + ksi * 8 + lc    ]);
        qf[ksi][1] = f2tf32(qb[(size_t)row1 * DK + ksi * 8 + lc    ]);
        qf[ksi][2] = f2tf32(qb[(size_t)row0 * DK + ksi * 8 + lc + 4]);
        qf[ksi][3] = f2tf32(qb[(size_t)row1 * DK + ksi * 8 + lc + 4]);
    }

    float o[4][4];
    #pragma unroll
    for (int nt = 0; nt < 4; nt++)
        #pragma unroll
        for (int i = 0; i < 4; i++) o[nt][i] = 0.f;

    float m0 = -INFINITY, m1 = -INFINITY, l0 = 0.f, l1 = 0.f;

    uint32_t sK = __cvta_generic_to_shared(ks_);
    uint32_t sV = __cvta_generic_to_shared(vs_);

#define LOADKV(st, tile) do {                                                         \
        _Pragma("unroll")                                                             \
        for (int l = 0; l < 4; l++) {                                                 \
            int fid = tid + l * 256;                                                  \
            int r = fid >> 4, c4 = fid & 15;                                          \
            cp_async16(sK + (uint32_t)((st) * 64 * KST + r * KST + c4 * 4) * 4,       \
                       kb + ((size_t)(tile) * 64 + r) * DK + c4 * 4);                 \
            cp_async16(sV + (uint32_t)((st) * 64 * VST + r * VST + c4 * 4) * 4,       \
                       vb + ((size_t)(tile) * 64 + r) * DK + c4 * 4);                 \
        }                                                                             \
        asm volatile("cp.async.commit_group;");                                       \
    } while (0)

    LOADKV(0, 0);

    for (int t = 0; t < NKT; t++) {
        int st = t & 1;
        __syncthreads();                    // everyone done with stage st (t-2) and ps (t-1)
        if (t + 1 < NKT) {
            LOADKV(st ^ 1, t + 1);
            asm volatile("cp.async.wait_group 1;");
        } else {
            asm volatile("cp.async.wait_group 0;");
        }
        __syncthreads();                    // stage st visible

        // ---- S = Q @ K^T  (per-warp 16x32 slice) ----
        float c[4][4];
        #pragma unroll
        for (int nt = 0; nt < 4; nt++)
            #pragma unroll
            for (int i = 0; i < 4; i++) c[nt][i] = 0.f;

        const float* ksb = ks_ + st * 64 * KST;
        #pragma unroll
        for (int ksi = 0; ksi < 8; ksi++) {
            int k0 = ksi * 8 + lc;
            #pragma unroll
            for (int nt = 0; nt < 4; nt++) {
                int c0 = wn * 32 + nt * 8 + lr;
                uint32_t bf[2];
                bf[0] = f2tf32(ksb[c0 * KST + k0    ]);
                bf[1] = f2tf32(ksb[c0 * KST + k0 + 4]);
                mma_tf32(c[nt], qf[ksi], bf);
            }
        }

        // ---- mask + scale + row max ----
        uint32_t mw0 = mb[(size_t)grow0 * NWORDS + t * 2 + wn];
        uint32_t mw1 = mb[(size_t)grow1 * NWORDS + t * 2 + wn];
        float mx0 = -INFINITY, mx1 = -INFINITY;
        #pragma unroll
        for (int nt = 0; nt < 4; nt++) {
            int j = nt * 8 + 2 * lc;
            c[nt][0] = ((mw0 >> j)       & 1u) ? c[nt][0] * 0.125f : -1e9f;
            c[nt][1] = ((mw0 >> (j + 1)) & 1u) ? c[nt][1] * 0.125f : -1e9f;
            c[nt][2] = ((mw1 >> j)       & 1u) ? c[nt][2] * 0.125f : -1e9f;
            c[nt][3] = ((mw1 >> (j + 1)) & 1u) ? c[nt][3] * 0.125f : -1e9f;
            mx0 = fmaxf(mx0, fmaxf(c[nt][0], c[nt][1]));
            mx1 = fmaxf(mx1, fmaxf(c[nt][2], c[nt][3]));
        }
        mx0 = fmaxf(mx0, __shfl_xor_sync(0xffffffffu, mx0, 1));
        mx0 = fmaxf(mx0, __shfl_xor_sync(0xffffffffu, mx0, 2));
        mx1 = fmaxf(mx1, __shfl_xor_sync(0xffffffffu, mx1, 1));
        mx1 = fmaxf(mx1, __shfl_xor_sync(0xffffffffu, mx1, 2));
        if (lc == 0) {
            redmax[wn * 64 + row0] = mx0;
            redmax[wn * 64 + row1] = mx1;
        }
        __syncthreads();

        float mn0 = fmaxf(m0, fmaxf(redmax[row0], redmax[64 + row0]));
        float mn1 = fmaxf(m1, fmaxf(redmax[row1], redmax[64 + row1]));
        float a0 = __expf(m0 - mn0);
        float a1 = __expf(m1 - mn1);
        m0 = mn0; m1 = mn1;

        // ---- p = exp(s - m), store tf32 P, partial row sums ----
        float s0 = 0.f, s1 = 0.f;
        #pragma unroll
        for (int nt = 0; nt < 4; nt++) {
            int col = wn * 32 + nt * 8 + 2 * lc;
            float p00 = __expf(c[nt][0] - mn0);
            float p01 = __expf(c[nt][1] - mn0);
            float p10 = __expf(c[nt][2] - mn1);
            float p11 = __expf(c[nt][3] - mn1);
            s0 += p00 + p01;
            s1 += p10 + p11;
            ps_[row0 * PST + col    ] = f2tf32(p00);
            ps_[row0 * PST + col + 1] = f2tf32(p01);
            ps_[row1 * PST + col    ] = f2tf32(p10);
            ps_[row1 * PST + col + 1] = f2tf32(p11);
        }
        s0 += __shfl_xor_sync(0xffffffffu, s0, 1);
        s0 += __shfl_xor_sync(0xffffffffu, s0, 2);
        s1 += __shfl_xor_sync(0xffffffffu, s1, 1);
        s1 += __shfl_xor_sync(0xffffffffu, s1, 2);
        if (lc == 0) {
            redsum[wn * 64 + row0] = s0;
            redsum[wn * 64 + row1] = s1;
        }
        __syncthreads();

        l0 = l0 * a0 + redsum[row0] + redsum[64 + row0];
        l1 = l1 * a1 + redsum[row1] + redsum[64 + row1];

        // ---- rescale O, then O += P @ V ----
        #pragma unroll
        for (int nt = 0; nt < 4; nt++) {
            o[nt][0] *= a0; o[nt][1] *= a0;
            o[nt][2] *= a1; o[nt][3] *= a1;
        }
        const float* vsb = vs_ + st * 64 * VST;
        #pragma unroll
        for (int ksi = 0; ksi < 8; ksi++) {
            int k0 = ksi * 8 + lc;
            uint32_t af[4];
            af[0] = ps_[row0 * PST + k0    ];
            af[1] = ps_[row1 * PST + k0    ];
            af[2] = ps_[row0 * PST + k0 + 4];
            af[3] = ps_[row1 * PST + k0 + 4];
            #pragma unroll
            for (int nt = 0; nt < 4; nt++) {
                int n0 = wn * 32 + nt * 8 + lr;
                uint32_t bf[2];
                bf[0] = f2tf32(vsb[(k0    ) * VST + n0]);
                bf[1] = f2tf32(vsb[(k0 + 4) * VST + n0]);
                mma_tf32(o[nt], af, bf);
            }
        }
    }

    // ---- normalize + write ctx ----
    float inv0 = 1.f / l0, inv1 = 1.f / l1;
    #pragma unroll
    for (int nt = 0; nt < 4; nt++) {
        int col = h * 64 + wn * 32 + nt * 8 + 2 * lc;
        *(float2*)(ctx + ((size_t)b * SEQ + grow0) * DMODEL + col) =
            make_float2(o[nt][0] * inv0, o[nt][1] * inv0);
        *(float2*)(ctx + ((size_t)b * SEQ + grow1) * DMODEL + col) =
            make_float2(o[nt][2] * inv1, o[nt][3] * inv1);
    }
#undef LOADKV
}

// ---------------- new_memory = broadcast(mean over seq) ----------------
__global__ __launch_bounds__(1024) void mem_partial_kernel(
    const float* __restrict__ xo, float* __restrict__ part)
{
    int b = blockIdx.x, cz = blockIdx.y, d = threadIdx.x;
    const float* base = xo + ((size_t)b * SEQ + cz * 128) * DMODEL + d;
    float s = 0.f;
    #pragma unroll 4
    for (int i = 0; i < 128; i++) s += base[(size_t)i * DMODEL];
    part[((size_t)b * 16 + cz) * DMODEL + d] = s;
}

__global__ __launch_bounds__(1024) void mem_final_kernel(
    const float* __restrict__ part, float* __restrict__ memout)
{
    int b = blockIdx.x, d = threadIdx.x;
    float s = 0.f;
    #pragma unroll
    for (int i = 0; i < 16; i++) s += part[((size_t)b * 16 + i) * DMODEL + d];
    float vv = s * (1.f / SEQ);
    #pragma unroll
    for (int m = 0; m < MEMT; m++)
        memout[((size_t)b * MEMT + m) * DMODEL + d] = vv;
}

// ---------------- launch ----------------
extern "C" void kernel_launch(void* const* d_in, const int* in_sizes, int n_in,
                              void* d_out, int out_size)
{
    const float* x    = (const float*)d_in[0];
    const int*   mask = (const int*)  d_in[1];
    const float* mem  = (const float*)d_in[2];
    const float* wq   = (const float*)d_in[3];
    const float* wk   = (const float*)d_in[4];
    const float* wv   = (const float*)d_in[5];
    const float* wo   = (const float*)d_in[6];
    const float* ln1a = (const float*)d_in[7];
    const float* ln1b = (const float*)d_in[8];
    const float* ln2a = (const float*)d_in[9];
    const float* ln2b = (const float*)d_in[10];
    const float* fw1  = (const float*)d_in[11];
    const float* fb1  = (const float*)d_in[12];
    const float* fw2  = (const float*)d_in[13];
    const float* fb2  = (const float*)d_in[14];
    float* out = (float*)d_out;
    float* out_mem = out + (size_t)ROWS * DMODEL;

    void* p;
    float *xn, *q, *k, *v, *ctx, *x1, *xn2, *h1, *part;
    uint32_t* mb;
    cudaGetSymbolAddress(&p, g_xn);  xn  = (float*)p;
    cudaGetSymbolAddress(&p, g_q);   q   = (float*)p;
    cudaGetSymbolAddress(&p, g_k);   k   = (float*)p;
    cudaGetSymbolAddress(&p, g_v);   v   = (float*)p;
    cudaGetSymbolAddress(&p, g_ctx); ctx = (float*)p;
    cudaGetSymbolAddress(&p, g_x1);  x1  = (float*)p;
    cudaGetSymbolAddress(&p, g_xn2); xn2 = (float*)p;
    cudaGetSymbolAddress(&p, g_h1);  h1  = (float*)p;
    cudaGetSymbolAddress(&p, g_part);part= (float*)p;
    cudaGetSymbolAddress(&p, g_mb);  mb  = (uint32_t*)p;

    cudaFuncSetAttribute(gemm_tc<EPI_QHEAD>,     cudaFuncAttributeMaxDynamicSharedMemorySize, GEMM_SMEM_BYTES);
    cudaFuncSetAttribute(gemm_tc<EPI_KVHEAD>,    cudaFuncAttributeMaxDynamicSharedMemorySize, GEMM_SMEM_BYTES);
    cudaFuncSetAttribute(gemm_tc<EPI_RESID>,     cudaFuncAttributeMaxDynamicSharedMemorySize, GEMM_SMEM_BYTES);
    cudaFuncSetAttribute(gemm_tc<EPI_BIAS_RELU>, cudaFuncAttributeMaxDynamicSharedMemorySize, GEMM_SMEM_BYTES);
    cudaFuncSetAttribute(gemm_tc<EPI_BIAS_RESID>,cudaFuncAttributeMaxDynamicSharedMemorySize, GEMM_SMEM_BYTES);
    cudaFuncSetAttribute(attn_tc, cudaFuncAttributeMaxDynamicSharedMemorySize, ATTN_SMEM_BYTES);

    // LN1 + mask compression + K/V pad clear (independent)
    ln_kernel<<<ROWS, 256>>>(x, ln1a, ln1b, xn);
    maskbits_kernel<<<SEQ, NWORDS>>>(mask, mb);
    padclear_kernel<<<BATCH * NHEADS, 256>>>(k, v);

    // Q/K/V projections into head layout (TF32 tensor cores)
    gemm_tc<EPI_QHEAD> <<<dim3(DMODEL/BN, ROWS/BM), 256, GEMM_SMEM_BYTES>>>(xn, wq, q, nullptr, nullptr, ROWS, DMODEL, DMODEL);
    gemm_tc<EPI_KVHEAD><<<dim3(DMODEL/BN, ROWS/BM), 256, GEMM_SMEM_BYTES>>>(xn, wk, k, nullptr, nullptr, ROWS, DMODEL, DMODEL);
    gemm_tc<EPI_KVHEAD><<<dim3(DMODEL/BN, ROWS/BM), 256, GEMM_SMEM_BYTES>>>(xn, wv, v, nullptr, nullptr, ROWS, DMODEL, DMODEL);

    // memory-token K/V rows (broadcast over batch)
    memproj_kernel<<<MEMT, 1024>>>(mem, wk, wv, k, v);

    // tensor-core flash attention
    attn_tc<<<dim3(SEQ/64, BATCH*NHEADS), 256, ATTN_SMEM_BYTES>>>(q, k, v, mb, ctx);

    // x1 = x + ctx @ w_o
    gemm_tc<EPI_RESID><<<dim3(DMODEL/BN, ROWS/BM), 256, GEMM_SMEM_BYTES>>>(ctx, wo, x1, nullptr, x, ROWS, DMODEL, DMODEL);

    // LN2
    ln_kernel<<<ROWS, 256>>>(x1, ln2a, ln2b, xn2);

    // FFN
    gemm_tc<EPI_BIAS_RELU> <<<dim3(DFF/BN,   ROWS/BM), 256, GEMM_SMEM_BYTES>>>(xn2, fw1, h1, fb1, nullptr, ROWS, DFF, DMODEL);
    gemm_tc<EPI_BIAS_RESID><<<dim3(DMODEL/BN, ROWS/BM), 256, GEMM_SMEM_BYTES>>>(h1, fw2, out, fb2, x1, ROWS, DMODEL, DFF);

    // new_memory
    mem_partial_kernel<<<dim3(BATCH, 16), 1024>>>(out, part);
    mem_final_kernel<<<BATCH, 1024>>>(part, out_mem);
}

// round 5
// speedup vs baseline: 5.5408x; 1.0324x over previous
#include <cuda_runtime.h>
#include <math.h>
#include <stdint.h>

// ---------------- problem constants ----------------
#define BATCH 4
#define SEQ   2048
#define DMODEL 1024
#define NHEADS 16
#define DK    64
#define MEMT  32
#define TTOT  (SEQ + MEMT)       // 2080
#define T_PAD 2112               // 33 * 64
#define NKT   33                 // key tiles of 64
#define DFF   4096
#define ROWS  (BATCH * SEQ)      // 8192
#define NWORDS 66                // mask bit-words per query row

// ---------------- device scratch ----------------
__device__ float g_xn [ROWS * DMODEL];
__device__ float g_q  [BATCH * NHEADS * SEQ   * DK];
__device__ float g_k  [BATCH * NHEADS * T_PAD * DK];
__device__ float g_v  [BATCH * NHEADS * T_PAD * DK];
__device__ float g_ctx[ROWS * DMODEL];
__device__ float g_x1 [ROWS * DMODEL];
__device__ float g_xn2[ROWS * DMODEL];
__device__ float g_h1 [ROWS * DFF];
__device__ float g_part[BATCH * 16 * DMODEL];
__device__ uint32_t g_mb[SEQ * NWORDS];
// tf32-rounded weight copies
__device__ float g_wq [DMODEL * DMODEL];
__device__ float g_wk [DMODEL * DMODEL];
__device__ float g_wv [DMODEL * DMODEL];
__device__ float g_wo [DMODEL * DMODEL];
__device__ float g_fw1[DMODEL * DFF];
__device__ float g_fw2[DFF * DMODEL];

// ---------------- small helpers ----------------
// RNA round fp32 -> tf32 (stored as fp32 with low 13 mantissa bits zero)
__device__ __forceinline__ float tf32r(float f) {
    uint32_t u;
    asm("cvt.rna.tf32.f32 %0, %1;" : "=r"(u) : "f"(f));
    return __uint_as_float(u);
}
// raw bits: valid tf32 operand when the value is already tf32-rounded
__device__ __forceinline__ uint32_t fbits(float f) { return __float_as_uint(f); }

__device__ __forceinline__ void cp_async16(uint32_t dst, const void* src) {
    asm volatile("cp.async.cg.shared.global [%0], [%1], 16;\n" :: "r"(dst), "l"(src));
}
__device__ __forceinline__ void mma_tf32(float* c, const uint32_t* a, const uint32_t* b) {
    asm volatile(
        "mma.sync.aligned.m16n8k8.row.col.f32.tf32.tf32.f32 "
        "{%0,%1,%2,%3},{%4,%5,%6,%7},{%8,%9},{%0,%1,%2,%3};"
        : "+f"(c[0]), "+f"(c[1]), "+f"(c[2]), "+f"(c[3])
        : "r"(a[0]), "r"(a[1]), "r"(a[2]), "r"(a[3]), "r"(b[0]), "r"(b[1]));
}

// ---------------- weight pre-rounding ----------------
__global__ __launch_bounds__(256) void round_kernel(
    const float* __restrict__ src, float* __restrict__ dst, int n4)
{
    int i = blockIdx.x * 256 + threadIdx.x;
    if (i < n4) {
        float4 t = ((const float4*)src)[i];
        t.x = tf32r(t.x); t.y = tf32r(t.y); t.z = tf32r(t.z); t.w = tf32r(t.w);
        ((float4*)dst)[i] = t;
    }
}

// ---------------- layer norm (ddof=1, div by std+eps); output tf32-rounded ----------------
__global__ __launch_bounds__(256) void ln_kernel(
    const float* __restrict__ x, const float* __restrict__ alpha,
    const float* __restrict__ bias, float* __restrict__ out)
{
    int row = blockIdx.x;
    int tid = threadIdx.x;
    const float4* xr = (const float4*)(x + (size_t)row * DMODEL);
    float4 v = xr[tid];
    float s  = v.x + v.y + v.z + v.w;
    float ss = v.x*v.x + v.y*v.y + v.z*v.z + v.w*v.w;
    #pragma unroll
    for (int off = 16; off > 0; off >>= 1) {
        s  += __shfl_xor_sync(0xffffffffu, s,  off);
        ss += __shfl_xor_sync(0xffffffffu, ss, off);
    }
    __shared__ float rs[8], rss[8];
    int wid = tid >> 5, lane = tid & 31;
    if (lane == 0) { rs[wid] = s; rss[wid] = ss; }
    __syncthreads();
    float S = 0.f, SS = 0.f;
    #pragma unroll
    for (int w = 0; w < 8; w++) { S += rs[w]; SS += rss[w]; }
    float mean = S * (1.f / DMODEL);
    float var  = (SS - (float)DMODEL * mean * mean) * (1.f / (DMODEL - 1));
    float inv  = 1.f / (sqrtf(fmaxf(var, 0.f)) + 1e-6f);
    float4 a  = ((const float4*)alpha)[tid];
    float4 bb = ((const float4*)bias)[tid];
    float4 o;
    o.x = tf32r(a.x * (v.x - mean) * inv + bb.x);
    o.y = tf32r(a.y * (v.y - mean) * inv + bb.y);
    o.z = tf32r(a.z * (v.z - mean) * inv + bb.z);
    o.w = tf32r(a.w * (v.w - mean) * inv + bb.w);
    ((float4*)(out + (size_t)row * DMODEL))[tid] = o;
}

// ---------------- TF32 tensor-core GEMM: C = A[MxK] @ W[KxN] ----------------
// A and W must already be tf32-rounded.
#define EPI_PLAIN      0
#define EPI_QHEAD      1   // rounded (feeds attention mma)
#define EPI_KVHEAD     2   // rounded (feeds attention mma)
#define EPI_RESID      3   // full fp32
#define EPI_BIAS_RELU  4   // rounded (feeds ffn2 mma)
#define EPI_BIAS_RESID 5   // full fp32

#define BM 128
#define BN 128
#define BK 32
#define AST 36
#define BST 136
#define ASZ (BM * AST)
#define BSZ (BK * BST)
#define GEMM_SMEM_BYTES ((2 * ASZ + 2 * BSZ) * 4)

template<int EPI>
__global__ __launch_bounds__(256, 2) void gemm_tc(
    const float* __restrict__ A, const float* __restrict__ W,
    float* __restrict__ C, const float* __restrict__ bias,
    const float* __restrict__ R, int M, int N, int K)
{
    extern __shared__ float sm[];
    float* As = sm;
    float* Bs = sm + 2 * ASZ;

    int tid  = threadIdx.x;
    int warp = tid >> 5, lane = tid & 31;
    int wm = warp & 1;
    int wn = warp >> 1;
    int lr = lane >> 2;
    int lc = lane & 3;

    const float* Abase = A + (size_t)blockIdx.y * BM * K;
    const float* Wbase = W + (size_t)blockIdx.x * BN;

    uint32_t sA = __cvta_generic_to_shared(As);
    uint32_t sB = __cvta_generic_to_shared(Bs);

    float acc[4][4][4];
    #pragma unroll
    for (int mt = 0; mt < 4; mt++)
        #pragma unroll
        for (int nt = 0; nt < 4; nt++)
            #pragma unroll
            for (int i = 0; i < 4; i++) acc[mt][nt][i] = 0.f;

#define LOAD_STAGE(st, kt) do {                                                  \
        _Pragma("unroll")                                                        \
        for (int l = 0; l < 4; l++) {                                            \
            int fid = tid + l * 256;                                             \
            int r = fid >> 3, c4 = fid & 7;                                      \
            cp_async16(sA + (uint32_t)(((st) * ASZ) + r * AST + c4 * 4) * 4,     \
                       Abase + (size_t)r * K + (size_t)(kt) * BK + c4 * 4);      \
        }                                                                        \
        _Pragma("unroll")                                                        \
        for (int l = 0; l < 4; l++) {                                            \
            int fid = tid + l * 256;                                             \
            int r = fid >> 5, c4 = fid & 31;                                     \
            cp_async16(sB + (uint32_t)(((st) * BSZ) + r * BST + c4 * 4) * 4,     \
                       Wbase + (size_t)((kt) * BK + r) * N + c4 * 4);            \
        }                                                                        \
        asm volatile("cp.async.commit_group;");                                  \
    } while (0)

    int NT = K / BK;
    LOAD_STAGE(0, 0);

    for (int kt = 0; kt < NT; kt++) {
        int st = kt & 1;
        if (kt + 1 < NT) {
            LOAD_STAGE(st ^ 1, kt + 1);
            asm volatile("cp.async.wait_group 1;");
        } else {
            asm volatile("cp.async.wait_group 0;");
        }
        __syncthreads();

        const float* as = As + st * ASZ;
        const float* bs = Bs + st * BSZ;

        #pragma unroll
        for (int ks = 0; ks < 4; ks++) {
            int k0 = ks * 8 + lc;
            uint32_t af[4][4], bf[4][2];
            #pragma unroll
            for (int mt = 0; mt < 4; mt++) {
                int r0 = wm * 64 + mt * 16 + lr;
                af[mt][0] = fbits(as[r0       * AST + k0    ]);
                af[mt][1] = fbits(as[(r0 + 8) * AST + k0    ]);
                af[mt][2] = fbits(as[r0       * AST + k0 + 4]);
                af[mt][3] = fbits(as[(r0 + 8) * AST + k0 + 4]);
            }
            #pragma unroll
            for (int nt = 0; nt < 4; nt++) {
                int c0 = wn * 32 + nt * 8 + lr;
                bf[nt][0] = fbits(bs[k0       * BST + c0]);
                bf[nt][1] = fbits(bs[(k0 + 4) * BST + c0]);
            }
            #pragma unroll
            for (int mt = 0; mt < 4; mt++)
                #pragma unroll
                for (int nt = 0; nt < 4; nt++)
                    mma_tf32(acc[mt][nt], af[mt], bf[nt]);
        }
        __syncthreads();
    }

    #pragma unroll
    for (int mt = 0; mt < 4; mt++) {
        #pragma unroll
        for (int rg = 0; rg < 2; rg++) {
            int r = blockIdx.y * BM + wm * 64 + mt * 16 + lr + rg * 8;
            #pragma unroll
            for (int nt = 0; nt < 4; nt++) {
                int c = blockIdx.x * BN + wn * 32 + nt * 8 + lc * 2;
                float v0 = acc[mt][nt][rg * 2 + 0];
                float v1 = acc[mt][nt][rg * 2 + 1];
                if (EPI == EPI_PLAIN) {
                    *(float2*)(C + (size_t)r * N + c) = make_float2(v0, v1);
                } else if (EPI == EPI_QHEAD) {
                    int b = r >> 11, s = r & 2047, h = c >> 6, d = c & 63;
                    *(float2*)(C + ((((size_t)(b * NHEADS + h)) * SEQ + s) * DK + d)) =
                        make_float2(tf32r(v0), tf32r(v1));
                } else if (EPI == EPI_KVHEAD) {
                    int b = r >> 11, s = r & 2047, h = c >> 6, d = c & 63;
                    *(float2*)(C + ((((size_t)(b * NHEADS + h)) * T_PAD + MEMT + s) * DK + d)) =
                        make_float2(tf32r(v0), tf32r(v1));
                } else if (EPI == EPI_RESID) {
                    float2 rr = *(const float2*)(R + (size_t)r * N + c);
                    *(float2*)(C + (size_t)r * N + c) = make_float2(v0 + rr.x, v1 + rr.y);
                } else if (EPI == EPI_BIAS_RELU) {
                    float2 bb = *(const float2*)(bias + c);
                    *(float2*)(C + (size_t)r * N + c) =
                        make_float2(tf32r(fmaxf(v0 + bb.x, 0.f)), tf32r(fmaxf(v1 + bb.y, 0.f)));
                } else if (EPI == EPI_BIAS_RESID) {
                    float2 bb = *(const float2*)(bias + c);
                    float2 rr = *(const float2*)(R + (size_t)r * N + c);
                    *(float2*)(C + (size_t)r * N + c) = make_float2(v0 + bb.x + rr.x, v1 + bb.y + rr.y);
                }
            }
        }
    }
#undef LOAD_STAGE
}

// ---------------- memory-token K/V projection (rounded outputs) ----------------
__global__ __launch_bounds__(1024) void memproj_kernel(
    const float* __restrict__ mt, const float* __restrict__ wk,
    const float* __restrict__ wv, float* __restrict__ kh, float* __restrict__ vh)
{
    int m = blockIdx.x;
    int c = threadIdx.x;
    float ak = 0.f, av = 0.f;
    #pragma unroll 4
    for (int kk = 0; kk < DMODEL; kk++) {
        float xm = mt[(size_t)m * DMODEL + kk];
        ak = fmaf(xm, wk[(size_t)kk * DMODEL + c], ak);
        av = fmaf(xm, wv[(size_t)kk * DMODEL + c], av);
    }
    ak = tf32r(ak); av = tf32r(av);
    int h = c >> 6, d = c & 63;
    #pragma unroll
    for (int b = 0; b < BATCH; b++) {
        size_t idx = (((size_t)(b * NHEADS + h)) * T_PAD + m) * DK + d;
        kh[idx] = ak;
        vh[idx] = av;
    }
}

// ---------------- zero K/V padding rows ----------------
__global__ __launch_bounds__(256) void padclear_kernel(float* k, float* v)
{
    int bh = blockIdx.x;
    size_t base = ((size_t)bh * T_PAD + TTOT) * DK;
    for (int i = threadIdx.x; i < (T_PAD - TTOT) * DK; i += 256) {
        k[base + i] = 0.f;
        v[base + i] = 0.f;
    }
}

// ---------------- compress mask to bits ----------------
__global__ void maskbits_kernel(const int* __restrict__ mask, uint32_t* __restrict__ mb)
{
    int s = blockIdx.x;
    int w = threadIdx.x;
    uint32_t bits = 0;
    #pragma unroll 4
    for (int j = 0; j < 32; j++) {
        int t = w * 32 + j;
        if (t < TTOT && mask[(size_t)s * TTOT + t] != 0) bits |= (1u << j);
    }
    mb[(size_t)s * NWORDS + w] = bits;
}

// ---------------- TF32 tensor-core flash attention ----------------
// q/k/v buffers are pre-rounded; P rounded at store. Raw-bit mma operands.
#define KST 68
#define VST 72
#define PST 68
#define ATTN_SMEM_BYTES ((2*64*KST + 2*64*VST + 64*PST + 256) * 4)

__global__ __launch_bounds__(256) void attn_tc(
    const float* __restrict__ q, const float* __restrict__ k,
    const float* __restrict__ v, const uint32_t* __restrict__ mb,
    float* __restrict__ ctx)
{
    extern __shared__ float smf[];
    float*    ks_ = smf;
    float*    vs_ = ks_ + 2 * 64 * KST;
    uint32_t* ps_ = (uint32_t*)(vs_ + 2 * 64 * VST);
    float*    redmax = (float*)(ps_ + 64 * PST);
    float*    redsum = redmax + 128;

    int tid  = threadIdx.x;
    int warp = tid >> 5, lane = tid & 31;
    int wm = warp & 3, wn = warp >> 2;
    int lr = lane >> 2, lc = lane & 3;
    int bh = blockIdx.y;
    int b  = bh >> 4, h = bh & 15;
    int q0 = blockIdx.x * 64;

    const float* qb = q + (((size_t)bh) * SEQ + q0) * DK;
    const float* kb = k + ((size_t)bh) * T_PAD * DK;
    const float* vb = v + ((size_t)bh) * T_PAD * DK;

    int row0 = wm * 16 + lr;
    int row1 = row0 + 8;
    int grow0 = q0 + row0, grow1 = q0 + row1;

    uint32_t qf[8][4];
    #pragma unroll
    for (int ksi = 0; ksi < 8; ksi++) {
        qf[ksi][0] = fbits(qb[(size_t)row0 * DK + ksi * 8 + lc    ]);
        qf[ksi][1] = fbits(qb[(size_t)row1 * DK + ksi * 8 + lc    ]);
        qf[ksi][2] = fbits(qb[(size_t)row0 * DK + ksi * 8 + lc + 4]);
        qf[ksi][3] = fbits(qb[(size_t)row1 * DK + ksi * 8 + lc + 4]);
    }

    float o[4][4];
    #pragma unroll
    for (int nt = 0; nt < 4; nt++)
        #pragma unroll
        for (int i = 0; i < 4; i++) o[nt][i] = 0.f;

    float m0 = -INFINITY, m1 = -INFINITY, l0 = 0.f, l1 = 0.f;

    uint32_t sK = __cvta_generic_to_shared(ks_);
    uint32_t sV = __cvta_generic_to_shared(vs_);

#define LOADKV(st, tile) do {                                                         \
        _Pragma("unroll")                                                             \
        for (int l = 0; l < 4; l++) {                                                 \
            int fid = tid + l * 256;                                                  \
            int r = fid >> 4, c4 = fid & 15;                                          \
            cp_async16(sK + (uint32_t)((st) * 64 * KST + r * KST + c4 * 4) * 4,       \
                       kb + ((size_t)(tile) * 64 + r) * DK + c4 * 4);                 \
            cp_async16(sV + (uint32_t)((st) * 64 * VST + r * VST + c4 * 4) * 4,       \
                       vb + ((size_t)(tile) * 64 + r) * DK + c4 * 4);                 \
        }                                                                             \
        asm volatile("cp.async.commit_group;");                                       \
    } while (0)

    LOADKV(0, 0);

    for (int t = 0; t < NKT; t++) {
        int st = t & 1;
        __syncthreads();
        if (t + 1 < NKT) {
            LOADKV(st ^ 1, t + 1);
            asm volatile("cp.async.wait_group 1;");
        } else {
            asm volatile("cp.async.wait_group 0;");
        }
        __syncthreads();

        float c[4][4];
        #pragma unroll
        for (int nt = 0; nt < 4; nt++)
            #pragma unroll
            for (int i = 0; i < 4; i++) c[nt][i] = 0.f;

        const float* ksb = ks_ + st * 64 * KST;
        #pragma unroll
        for (int ksi = 0; ksi < 8; ksi++) {
            int k0 = ksi * 8 + lc;
            #pragma unroll
            for (int nt = 0; nt < 4; nt++) {
                int c0 = wn * 32 + nt * 8 + lr;
                uint32_t bf[2];
                bf[0] = fbits(ksb[c0 * KST + k0    ]);
                bf[1] = fbits(ksb[c0 * KST + k0 + 4]);
                mma_tf32(c[nt], qf[ksi], bf);
            }
        }

        uint32_t mw0 = mb[(size_t)grow0 * NWORDS + t * 2 + wn];
        uint32_t mw1 = mb[(size_t)grow1 * NWORDS + t * 2 + wn];
        float mx0 = -INFINITY, mx1 = -INFINITY;
        #pragma unroll
        for (int nt = 0; nt < 4; nt++) {
            int j = nt * 8 + 2 * lc;
            c[nt][0] = ((mw0 >> j)       & 1u) ? c[nt][0] * 0.125f : -1e9f;
            c[nt][1] = ((mw0 >> (j + 1)) & 1u) ? c[nt][1] * 0.125f : -1e9f;
            c[nt][2] = ((mw1 >> j)       & 1u) ? c[nt][2] * 0.125f : -1e9f;
            c[nt][3] = ((mw1 >> (j + 1)) & 1u) ? c[nt][3] * 0.125f : -1e9f;
            mx0 = fmaxf(mx0, fmaxf(c[nt][0], c[nt][1]));
            mx1 = fmaxf(mx1, fmaxf(c[nt][2], c[nt][3]));
        }
        mx0 = fmaxf(mx0, __shfl_xor_sync(0xffffffffu, mx0, 1));
        mx0 = fmaxf(mx0, __shfl_xor_sync(0xffffffffu, mx0, 2));
        mx1 = fmaxf(mx1, __shfl_xor_sync(0xffffffffu, mx1, 1));
        mx1 = fmaxf(mx1, __shfl_xor_sync(0xffffffffu, mx1, 2));
        if (lc == 0) {
            redmax[wn * 64 + row0] = mx0;
            redmax[wn * 64 + row1] = mx1;
        }
        __syncthreads();

        float mn0 = fmaxf(m0, fmaxf(redmax[row0], redmax[64 + row0]));
        float mn1 = fmaxf(m1, fmaxf(redmax[row1], redmax[64 + row1]));
        float a0 = __expf(m0 - mn0);
        float a1 = __expf(m1 - mn1);
        m0 = mn0; m1 = mn1;

        float s0 = 0.f, s1 = 0.f;
        #pragma unroll
        for (int nt = 0; nt < 4; nt++) {
            int col = wn * 32 + nt * 8 + 2 * lc;
            float p00 = __expf(c[nt][0] - mn0);
            float p01 = __expf(c[nt][1] - mn0);
            float p10 = __expf(c[nt][2] - mn1);
            float p11 = __expf(c[nt][3] - mn1);
            s0 += p00 + p01;
            s1 += p10 + p11;
            // RNA-round P once at store; PV mma then reads raw bits
            ps_[row0 * PST + col    ] = fbits(tf32r(p00));
            ps_[row0 * PST + col + 1] = fbits(tf32r(p01));
            ps_[row1 * PST + col    ] = fbits(tf32r(p10));
            ps_[row1 * PST + col + 1] = fbits(tf32r(p11));
        }
        s0 += __shfl_xor_sync(0xffffffffu, s0, 1);
        s0 += __shfl_xor_sync(0xffffffffu, s0, 2);
        s1 += __shfl_xor_sync(0xffffffffu, s1, 1);
        s1 += __shfl_xor_sync(0xffffffffu, s1, 2);
        if (lc == 0) {
            redsum[wn * 64 + row0] = s0;
            redsum[wn * 64 + row1] = s1;
        }
        __syncthreads();

        l0 = l0 * a0 + redsum[row0] + redsum[64 + row0];
        l1 = l1 * a1 + redsum[row1] + redsum[64 + row1];

        #pragma unroll
        for (int nt = 0; nt < 4; nt++) {
            o[nt][0] *= a0; o[nt][1] *= a0;
            o[nt][2] *= a1; o[nt][3] *= a1;
        }
        const float* vsb = vs_ + st * 64 * VST;
        #pragma unroll
        for (int ksi = 0; ksi < 8; ksi++) {
            int k0 = ksi * 8 + lc;
            uint32_t af[4];
            af[0] = ps_[row0 * PST + k0    ];
            af[1] = ps_[row1 * PST + k0    ];
            af[2] = ps_[row0 * PST + k0 + 4];
            af[3] = ps_[row1 * PST + k0 + 4];
            #pragma unroll
            for (int nt = 0; nt < 4; nt++) {
                int n0 = wn * 32 + nt * 8 + lr;
                uint32_t bf[2];
                bf[0] = fbits(vsb[(k0    ) * VST + n0]);
                bf[1] = fbits(vsb[(k0 + 4) * VST + n0]);
                mma_tf32(o[nt], af, bf);
            }
        }
    }

    // ctx feeds the W_o GEMM -> round output
    float inv0 = 1.f / l0, inv1 = 1.f / l1;
    #pragma unroll
    for (int nt = 0; nt < 4; nt++) {
        int col = h * 64 + wn * 32 + nt * 8 + 2 * lc;
        *(float2*)(ctx + ((size_t)b * SEQ + grow0) * DMODEL + col) =
            make_float2(tf32r(o[nt][0] * inv0), tf32r(o[nt][1] * inv0));
        *(float2*)(ctx + ((size_t)b * SEQ + grow1) * DMODEL + col) =
            make_float2(tf32r(o[nt][2] * inv1), tf32r(o[nt][3] * inv1));
    }
#undef LOADKV
}

// ---------------- new_memory = broadcast(mean over seq) ----------------
__global__ __launch_bounds__(1024) void mem_partial_kernel(
    const float* __restrict__ xo, float* __restrict__ part)
{
    int b = blockIdx.x, cz = blockIdx.y, d = threadIdx.x;
    const float* base = xo + ((size_t)b * SEQ + cz * 128) * DMODEL + d;
    float s = 0.f;
    #pragma unroll 4
    for (int i = 0; i < 128; i++) s += base[(size_t)i * DMODEL];
    part[((size_t)b * 16 + cz) * DMODEL + d] = s;
}

__global__ __launch_bounds__(1024) void mem_final_kernel(
    const float* __restrict__ part, float* __restrict__ memout)
{
    int b = blockIdx.x, d = threadIdx.x;
    float s = 0.f;
    #pragma unroll
    for (int i = 0; i < 16; i++) s += part[((size_t)b * 16 + i) * DMODEL + d];
    float vv = s * (1.f / SEQ);
    #pragma unroll
    for (int m = 0; m < MEMT; m++)
        memout[((size_t)b * MEMT + m) * DMODEL + d] = vv;
}

// ---------------- launch ----------------
extern "C" void kernel_launch(void* const* d_in, const int* in_sizes, int n_in,
                              void* d_out, int out_size)
{
    const float* x    = (const float*)d_in[0];
    const int*   mask = (const int*)  d_in[1];
    const float* mem  = (const float*)d_in[2];
    const float* wq   = (const float*)d_in[3];
    const float* wk   = (const float*)d_in[4];
    const float* wv   = (const float*)d_in[5];
    const float* wo   = (const float*)d_in[6];
    const float* ln1a = (const float*)d_in[7];
    const float* ln1b = (const float*)d_in[8];
    const float* ln2a = (const float*)d_in[9];
    const float* ln2b = (const float*)d_in[10];
    const float* fw1  = (const float*)d_in[11];
    const float* fb1  = (const float*)d_in[12];
    const float* fw2  = (const float*)d_in[13];
    const float* fb2  = (const float*)d_in[14];
    float* out = (float*)d_out;
    float* out_mem = out + (size_t)ROWS * DMODEL;

    void* p;
    float *xn, *q, *k, *v, *ctx, *x1, *xn2, *h1, *part;
    float *wqr, *wkr, *wvr, *wor, *fw1r, *fw2r;
    uint32_t* mb;
    cudaGetSymbolAddress(&p, g_xn);  xn  = (float*)p;
    cudaGetSymbolAddress(&p, g_q);   q   = (float*)p;
    cudaGetSymbolAddress(&p, g_k);   k   = (float*)p;
    cudaGetSymbolAddress(&p, g_v);   v   = (float*)p;
    cudaGetSymbolAddress(&p, g_ctx); ctx = (float*)p;
    cudaGetSymbolAddress(&p, g_x1);  x1  = (float*)p;
    cudaGetSymbolAddress(&p, g_xn2); xn2 = (float*)p;
    cudaGetSymbolAddress(&p, g_h1);  h1  = (float*)p;
    cudaGetSymbolAddress(&p, g_part);part= (float*)p;
    cudaGetSymbolAddress(&p, g_mb);  mb  = (uint32_t*)p;
    cudaGetSymbolAddress(&p, g_wq);  wqr = (float*)p;
    cudaGetSymbolAddress(&p, g_wk);  wkr = (float*)p;
    cudaGetSymbolAddress(&p, g_wv);  wvr = (float*)p;
    cudaGetSymbolAddress(&p, g_wo);  wor = (float*)p;
    cudaGetSymbolAddress(&p, g_fw1); fw1r= (float*)p;
    cudaGetSymbolAddress(&p, g_fw2); fw2r= (float*)p;

    cudaFuncSetAttribute(gemm_tc<EPI_QHEAD>,     cudaFuncAttributeMaxDynamicSharedMemorySize, GEMM_SMEM_BYTES);
    cudaFuncSetAttribute(gemm_tc<EPI_KVHEAD>,    cudaFuncAttributeMaxDynamicSharedMemorySize, GEMM_SMEM_BYTES);
    cudaFuncSetAttribute(gemm_tc<EPI_RESID>,     cudaFuncAttributeMaxDynamicSharedMemorySize, GEMM_SMEM_BYTES);
    cudaFuncSetAttribute(gemm_tc<EPI_BIAS_RELU>, cudaFuncAttributeMaxDynamicSharedMemorySize, GEMM_SMEM_BYTES);
    cudaFuncSetAttribute(gemm_tc<EPI_BIAS_RESID>,cudaFuncAttributeMaxDynamicSharedMemorySize, GEMM_SMEM_BYTES);
    cudaFuncSetAttribute(attn_tc, cudaFuncAttributeMaxDynamicSharedMemorySize, ATTN_SMEM_BYTES);

    // pre-round all weights to tf32 (RNA) once per call
    const int NSQ = DMODEL * DMODEL / 4, NFF = DMODEL * DFF / 4;
    round_kernel<<<(NSQ + 255) / 256, 256>>>(wq, wqr, NSQ);
    round_kernel<<<(NSQ + 255) / 256, 256>>>(wk, wkr, NSQ);
    round_kernel<<<(NSQ + 255) / 256, 256>>>(wv, wvr, NSQ);
    round_kernel<<<(NSQ + 255) / 256, 256>>>(wo, wor, NSQ);
    round_kernel<<<(NFF + 255) / 256, 256>>>(fw1, fw1r, NFF);
    round_kernel<<<(NFF + 255) / 256, 256>>>(fw2, fw2r, NFF);

    ln_kernel<<<ROWS, 256>>>(x, ln1a, ln1b, xn);
    maskbits_kernel<<<SEQ, NWORDS>>>(mask, mb);
    padclear_kernel<<<BATCH * NHEADS, 256>>>(k, v);

    gemm_tc<EPI_QHEAD> <<<dim3(DMODEL/BN, ROWS/BM), 256, GEMM_SMEM_BYTES>>>(xn, wqr, q, nullptr, nullptr, ROWS, DMODEL, DMODEL);
    gemm_tc<EPI_KVHEAD><<<dim3(DMODEL/BN, ROWS/BM), 256, GEMM_SMEM_BYTES>>>(xn, wkr, k, nullptr, nullptr, ROWS, DMODEL, DMODEL);
    gemm_tc<EPI_KVHEAD><<<dim3(DMODEL/BN, ROWS/BM), 256, GEMM_SMEM_BYTES>>>(xn, wvr, v, nullptr, nullptr, ROWS, DMODEL, DMODEL);

    memproj_kernel<<<MEMT, 1024>>>(mem, wk, wv, k, v);

    attn_tc<<<dim3(SEQ/64, BATCH*NHEADS), 256, ATTN_SMEM_BYTES>>>(q, k, v, mb, ctx);

    gemm_tc<EPI_RESID><<<dim3(DMODEL/BN, ROWS/BM), 256, GEMM_SMEM_BYTES>>>(ctx, wor, x1, nullptr, x, ROWS, DMODEL, DMODEL);

    ln_kernel<<<ROWS, 256>>>(x1, ln2a, ln2b, xn2);

    gemm_tc<EPI_BIAS_RELU> <<<dim3(DFF/BN,   ROWS/BM), 256, GEMM_SMEM_BYTES>>>(xn2, fw1r, h1, fb1, nullptr, ROWS, DFF, DMODEL);
    gemm_tc<EPI_BIAS_RESID><<<dim3(DMODEL/BN, ROWS/BM), 256, GEMM_SMEM_BYTES>>>(h1, fw2r, out, fb2, x1, ROWS, DMODEL, DFF);

    mem_partial_kernel<<<dim3(BATCH, 16), 1024>>>(out, part);
    mem_final_kernel<<<BATCH, 1024>>>(part, out_mem);
}

// round 8
// speedup vs baseline: 5.8237x; 1.0511x over previous
#include <cuda_runtime.h>
#include <math.h>
#include <stdint.h>

// ---------------- problem constants ----------------
#define BATCH 4
#define SEQ   2048
#define DMODEL 1024
#define NHEADS 16
#define DK    64
#define MEMT  32
#define TTOT  (SEQ + MEMT)
#define T_PAD 2112
#define NKT   33
#define DFF   4096
#define ROWS  (BATCH * SEQ)
#define NWORDS 66

// ---------------- device scratch ----------------
__device__ float g_xn [ROWS * DMODEL];
__device__ float g_q  [BATCH * NHEADS * SEQ   * DK];
__device__ float g_k  [BATCH * NHEADS * T_PAD * DK];
__device__ float g_v  [BATCH * NHEADS * T_PAD * DK];
__device__ float g_ctx[ROWS * DMODEL];
__device__ float g_x1 [ROWS * DMODEL];
__device__ float g_xn2[ROWS * DMODEL];
__device__ float g_h1 [ROWS * DFF];
__device__ float g_part[BATCH * 16 * DMODEL];
__device__ uint32_t g_mb[SEQ * NWORDS];
// transposed + tf32-rounded weights
__device__ float g_wqkv[3 * DMODEL * DMODEL];   // [3072][1024]
__device__ float g_wo  [DMODEL * DMODEL];
__device__ float g_fw1 [DFF * DMODEL];
__device__ float g_fw2 [DMODEL * DFF];

// ---------------- helpers ----------------
__device__ __forceinline__ float tf32r(float f) {
    uint32_t u;
    asm("cvt.rna.tf32.f32 %0, %1;" : "=r"(u) : "f"(f));
    return __uint_as_float(u);
}
__device__ __forceinline__ uint32_t fbits(float f) { return __float_as_uint(f); }

__device__ __forceinline__ void cp_async16(uint32_t dst, const void* src) {
    asm volatile("cp.async.cg.shared.global [%0], [%1], 16;\n" :: "r"(dst), "l"(src));
}
__device__ __forceinline__ void mma_tf32(float* c, const uint32_t* a, const uint32_t* b) {
    asm volatile(
        "mma.sync.aligned.m16n8k8.row.col.f32.tf32.tf32.f32 "
        "{%0,%1,%2,%3},{%4,%5,%6,%7},{%8,%9},{%0,%1,%2,%3};"
        : "+f"(c[0]), "+f"(c[1]), "+f"(c[2]), "+f"(c[3])
        : "r"(a[0]), "r"(a[1]), "r"(a[2]), "r"(a[3]), "r"(b[0]), "r"(b[1]));
}
__device__ __forceinline__ uint32_t smem_u32(const void* p) {
    return (uint32_t)__cvta_generic_to_shared(p);
}

// ---------------- weight transpose + tf32 round: dst[N][K] = rnd(src[K][N]) ----------------
__global__ __launch_bounds__(256) void transpose_round(
    const float* __restrict__ src, float* __restrict__ dst, int K, int N)
{
    __shared__ float t[32][33];
    int tx = threadIdx.x, ty = threadIdx.y;   // 32 x 8
    int n0 = blockIdx.x * 32, k0 = blockIdx.y * 32;
    #pragma unroll
    for (int i = 0; i < 4; i++)
        t[ty + 8*i][tx] = src[(size_t)(k0 + ty + 8*i) * N + n0 + tx];
    __syncthreads();
    #pragma unroll
    for (int i = 0; i < 4; i++)
        dst[(size_t)(n0 + ty + 8*i) * K + k0 + tx] = tf32r(t[tx][ty + 8*i]);
}

// ---------------- layer norm (ddof=1); tf32-rounded output ----------------
__global__ __launch_bounds__(256) void ln_kernel(
    const float* __restrict__ x, const float* __restrict__ alpha,
    const float* __restrict__ bias, float* __restrict__ out)
{
    int row = blockIdx.x;
    int tid = threadIdx.x;
    const float4* xr = (const float4*)(x + (size_t)row * DMODEL);
    float4 v = xr[tid];
    float s  = v.x + v.y + v.z + v.w;
    float ss = v.x*v.x + v.y*v.y + v.z*v.z + v.w*v.w;
    #pragma unroll
    for (int off = 16; off > 0; off >>= 1) {
        s  += __shfl_xor_sync(0xffffffffu, s,  off);
        ss += __shfl_xor_sync(0xffffffffu, ss, off);
    }
    __shared__ float rs[8], rss[8];
    int wid = tid >> 5, lane = tid & 31;
    if (lane == 0) { rs[wid] = s; rss[wid] = ss; }
    __syncthreads();
    float S = 0.f, SS = 0.f;
    #pragma unroll
    for (int w = 0; w < 8; w++) { S += rs[w]; SS += rss[w]; }
    float mean = S * (1.f / DMODEL);
    float var  = (SS - (float)DMODEL * mean * mean) * (1.f / (DMODEL - 1));
    float inv  = 1.f / (sqrtf(fmaxf(var, 0.f)) + 1e-6f);
    float4 a  = ((const float4*)alpha)[tid];
    float4 bb = ((const float4*)bias)[tid];
    float4 o;
    o.x = tf32r(a.x * (v.x - mean) * inv + bb.x);
    o.y = tf32r(a.y * (v.y - mean) * inv + bb.y);
    o.z = tf32r(a.z * (v.z - mean) * inv + bb.z);
    o.w = tf32r(a.w * (v.w - mean) * inv + bb.w);
    ((float4*)(out + (size_t)row * DMODEL))[tid] = o;
}

// ---------------- TF32 mma.sync GEMM, 3-stage pipeline ----------------
// C = A[MxK] @ Wt[NxK]^T. A, Wt pre-rounded to tf32. Both staged K-contiguous.
#define EPI_QKV        0
#define EPI_RESID      3
#define EPI_BIAS_RELU  4
#define EPI_BIAS_RESID 5

#define BM 128
#define BN 128
#define BK 32
#define AST 36
#define BT_ST 36
#define ASZ (BM * AST)      // 4608
#define BSZ (BN * BT_ST)    // 4608  (FIX: was BK*BST=4352 -> smem overflow)
#define NSTG 3
#define GEMM_SMEM_BYTES (NSTG * (ASZ + BSZ) * 4)   // 110592

template<int EPI>
__global__ __launch_bounds__(256, 2) void gemm_tc(
    const float* __restrict__ A, const float* __restrict__ W,
    float* __restrict__ C, const float* __restrict__ bias,
    const float* __restrict__ R, float* __restrict__ C2, float* __restrict__ C3,
    int M, int N, int K)
{
    extern __shared__ float sm[];
    float* As = sm;                 // NSTG stages [BM][AST]
    float* Bs = sm + NSTG * ASZ;    // NSTG stages [BN][BT_ST]

    int tid  = threadIdx.x;
    int warp = tid >> 5, lane = tid & 31;
    int wm = warp & 1;
    int wn = warp >> 1;
    int lr = lane >> 2;
    int lc = lane & 3;

    const float* Abase = A + (size_t)blockIdx.y * BM * K;
    const float* Wbase = W + (size_t)blockIdx.x * BN * K;   // Wt is [N][K]

    uint32_t sA = smem_u32(As);
    uint32_t sB = smem_u32(Bs);

    float acc[4][4][4];
    #pragma unroll
    for (int mt = 0; mt < 4; mt++)
        #pragma unroll
        for (int nt = 0; nt < 4; nt++)
            #pragma unroll
            for (int i = 0; i < 4; i++) acc[mt][nt][i] = 0.f;

#define LOAD_STAGE(st, kt) do {                                                  \
        _Pragma("unroll")                                                        \
        for (int l = 0; l < 4; l++) {                                            \
            int fid = tid + l * 256;                                             \
            int r = fid >> 3, c4 = fid & 7;                                      \
            cp_async16(sA + (uint32_t)(((st) * ASZ) + r * AST + c4 * 4) * 4,     \
                       Abase + (size_t)r * K + (size_t)(kt) * BK + c4 * 4);      \
        }                                                                        \
        _Pragma("unroll")                                                        \
        for (int l = 0; l < 4; l++) {                                            \
            int fid = tid + l * 256;                                             \
            int r = fid >> 3, c4 = fid & 7;                                      \
            cp_async16(sB + (uint32_t)(((st) * BSZ) + r * BT_ST + c4 * 4) * 4,   \
                       Wbase + (size_t)r * K + (size_t)(kt) * BK + c4 * 4);      \
        }                                                                        \
        asm volatile("cp.async.commit_group;");                                  \
    } while (0)

    int NT = K / BK;
    LOAD_STAGE(0, 0);
    LOAD_STAGE(1, 1);

    for (int kt = 0; kt < NT; kt++) {
        int st = kt - (kt / NSTG) * NSTG;
        asm volatile("cp.async.wait_group 1;");
        __syncthreads();
        if (kt + 2 < NT) {
            int sl = st + 2; if (sl >= NSTG) sl -= NSTG;
            LOAD_STAGE(sl, kt + 2);
        } else {
            asm volatile("cp.async.commit_group;");
        }

        const float* as = As + st * ASZ;
        const float* bs = Bs + st * BSZ;

        #pragma unroll
        for (int ks = 0; ks < 4; ks++) {
            int k0 = ks * 8 + lc;
            uint32_t af[4][4], bf[4][2];
            #pragma unroll
            for (int mt = 0; mt < 4; mt++) {
                int r0 = wm * 64 + mt * 16 + lr;
                af[mt][0] = fbits(as[r0       * AST + k0    ]);
                af[mt][1] = fbits(as[(r0 + 8) * AST + k0    ]);
                af[mt][2] = fbits(as[r0       * AST + k0 + 4]);
                af[mt][3] = fbits(as[(r0 + 8) * AST + k0 + 4]);
            }
            #pragma unroll
            for (int nt = 0; nt < 4; nt++) {
                int c0 = wn * 32 + nt * 8 + lr;
                bf[nt][0] = fbits(bs[c0 * BT_ST + k0    ]);
                bf[nt][1] = fbits(bs[c0 * BT_ST + k0 + 4]);
            }
            #pragma unroll
            for (int mt = 0; mt < 4; mt++)
                #pragma unroll
                for (int nt = 0; nt < 4; nt++)
                    mma_tf32(acc[mt][nt], af[mt], bf[nt]);
        }
        __syncthreads();
    }

    #pragma unroll
    for (int mt = 0; mt < 4; mt++) {
        #pragma unroll
        for (int rg = 0; rg < 2; rg++) {
            int r = blockIdx.y * BM + wm * 64 + mt * 16 + lr + rg * 8;
            #pragma unroll
            for (int nt = 0; nt < 4; nt++) {
                int c = blockIdx.x * BN + wn * 32 + nt * 8 + lc * 2;
                float v0 = acc[mt][nt][rg * 2 + 0];
                float v1 = acc[mt][nt][rg * 2 + 1];
                if (EPI == EPI_QKV) {
                    int sel = c >> 10, cc = c & 1023;
                    int b = r >> 11, s2 = r & 2047, h = cc >> 6, d = cc & 63;
                    float2 o = make_float2(tf32r(v0), tf32r(v1));
                    if (sel == 0)
                        *(float2*)(C  + ((((size_t)(b * NHEADS + h)) * SEQ + s2) * DK + d)) = o;
                    else if (sel == 1)
                        *(float2*)(C2 + ((((size_t)(b * NHEADS + h)) * T_PAD + MEMT + s2) * DK + d)) = o;
                    else
                        *(float2*)(C3 + ((((size_t)(b * NHEADS + h)) * T_PAD + MEMT + s2) * DK + d)) = o;
                } else if (EPI == EPI_RESID) {
                    float2 rr = *(const float2*)(R + (size_t)r * N + c);
                    *(float2*)(C + (size_t)r * N + c) = make_float2(v0 + rr.x, v1 + rr.y);
                } else if (EPI == EPI_BIAS_RELU) {
                    float2 bb = *(const float2*)(bias + c);
                    *(float2*)(C + (size_t)r * N + c) =
                        make_float2(tf32r(fmaxf(v0 + bb.x, 0.f)), tf32r(fmaxf(v1 + bb.y, 0.f)));
                } else if (EPI == EPI_BIAS_RESID) {
                    float2 bb = *(const float2*)(bias + c);
                    float2 rr = *(const float2*)(R + (size_t)r * N + c);
                    *(float2*)(C + (size_t)r * N + c) = make_float2(v0 + bb.x + rr.x, v1 + bb.y + rr.y);
                }
            }
        }
    }
#undef LOAD_STAGE
}

// ---------------- memory-token K/V projection (rounded outputs) ----------------
__global__ __launch_bounds__(1024) void memproj_kernel(
    const float* __restrict__ mt, const float* __restrict__ wk,
    const float* __restrict__ wv, float* __restrict__ kh, float* __restrict__ vh)
{
    int m = blockIdx.x;
    int c = threadIdx.x;
    float ak = 0.f, av = 0.f;
    #pragma unroll 4
    for (int kk = 0; kk < DMODEL; kk++) {
        float xm = mt[(size_t)m * DMODEL + kk];
        ak = fmaf(xm, wk[(size_t)kk * DMODEL + c], ak);
        av = fmaf(xm, wv[(size_t)kk * DMODEL + c], av);
    }
    ak = tf32r(ak); av = tf32r(av);
    int h = c >> 6, d = c & 63;
    #pragma unroll
    for (int b = 0; b < BATCH; b++) {
        size_t idx = (((size_t)(b * NHEADS + h)) * T_PAD + m) * DK + d;
        kh[idx] = ak;
        vh[idx] = av;
    }
}

__global__ __launch_bounds__(256) void padclear_kernel(float* k, float* v)
{
    int bh = blockIdx.x;
    size_t base = ((size_t)bh * T_PAD + TTOT) * DK;
    for (int i = threadIdx.x; i < (T_PAD - TTOT) * DK; i += 256) {
        k[base + i] = 0.f;
        v[base + i] = 0.f;
    }
}

__global__ void maskbits_kernel(const int* __restrict__ mask, uint32_t* __restrict__ mb)
{
    int s = blockIdx.x;
    int w = threadIdx.x;
    uint32_t bits = 0;
    #pragma unroll 4
    for (int j = 0; j < 32; j++) {
        int t = w * 32 + j;
        if (t < TTOT && mask[(size_t)s * TTOT + t] != 0) bits |= (1u << j);
    }
    mb[(size_t)s * NWORDS + w] = bits;
}

// ---------------- TF32 flash attention: warp-owned rows ----------------
#define KST 68
#define VST 72
#define PST 68
#define ATTN_SMEM_BYTES ((2*64*KST + 2*64*VST + 8*16*PST) * 4)

__global__ __launch_bounds__(256, 2) void attn_tc(
    const float* __restrict__ q, const float* __restrict__ k,
    const float* __restrict__ v, const uint32_t* __restrict__ mb,
    float* __restrict__ ctx)
{
    extern __shared__ float smf[];
    float*    ks_ = smf;
    float*    vs_ = ks_ + 2 * 64 * KST;
    uint32_t* ps_ = (uint32_t*)(vs_ + 2 * 64 * VST);

    int tid  = threadIdx.x;
    int warp = tid >> 5, lane = tid & 31;
    int lr = lane >> 2, lc = lane & 3;
    int bh = blockIdx.y;
    int b  = bh >> 4, h = bh & 15;
    int q0 = blockIdx.x * 128;

    const float* qb = q + (((size_t)bh) * SEQ + q0) * DK;
    const float* kb = k + ((size_t)bh) * T_PAD * DK;
    const float* vb = v + ((size_t)bh) * T_PAD * DK;

    int row0 = warp * 16 + lr;
    int row1 = row0 + 8;
    int grow0 = q0 + row0, grow1 = q0 + row1;
    uint32_t* psw = ps_ + warp * 16 * PST;

    uint32_t qf[8][4];
    #pragma unroll
    for (int ks = 0; ks < 8; ks++) {
        qf[ks][0] = fbits(qb[(size_t)row0 * DK + ks * 8 + lc    ]);
        qf[ks][1] = fbits(qb[(size_t)row1 * DK + ks * 8 + lc    ]);
        qf[ks][2] = fbits(qb[(size_t)row0 * DK + ks * 8 + lc + 4]);
        qf[ks][3] = fbits(qb[(size_t)row1 * DK + ks * 8 + lc + 4]);
    }

    float o[8][4];
    #pragma unroll
    for (int nt = 0; nt < 8; nt++)
        #pragma unroll
        for (int i = 0; i < 4; i++) o[nt][i] = 0.f;

    float m0 = -INFINITY, m1 = -INFINITY, l0 = 0.f, l1 = 0.f;

    uint32_t sK = smem_u32(ks_);
    uint32_t sV = smem_u32(vs_);

#define LOADKV(st, tile) do {                                                         \
        _Pragma("unroll")                                                             \
        for (int l = 0; l < 4; l++) {                                                 \
            int fid = tid + l * 256;                                                  \
            int r = fid >> 4, c4 = fid & 15;                                          \
            cp_async16(sK + (uint32_t)((st) * 64 * KST + r * KST + c4 * 4) * 4,       \
                       kb + ((size_t)(tile) * 64 + r) * DK + c4 * 4);                 \
            cp_async16(sV + (uint32_t)((st) * 64 * VST + r * VST + c4 * 4) * 4,       \
                       vb + ((size_t)(tile) * 64 + r) * DK + c4 * 4);                 \
        }                                                                             \
        asm volatile("cp.async.commit_group;");                                       \
    } while (0)

    LOADKV(0, 0);

    for (int t = 0; t < NKT; t++) {
        int st = t & 1;
        __syncthreads();
        if (t + 1 < NKT) {
            LOADKV(st ^ 1, t + 1);
            asm volatile("cp.async.wait_group 1;");
        } else {
            asm volatile("cp.async.wait_group 0;");
        }
        __syncthreads();

        float c[8][4];
        #pragma unroll
        for (int nt = 0; nt < 8; nt++)
            #pragma unroll
            for (int i = 0; i < 4; i++) c[nt][i] = 0.f;

        const float* ksb = ks_ + st * 64 * KST;
        #pragma unroll
        for (int ks = 0; ks < 8; ks++) {
            int k0 = ks * 8 + lc;
            #pragma unroll
            for (int nt = 0; nt < 8; nt++) {
                int c0 = nt * 8 + lr;
                uint32_t bf[2];
                bf[0] = fbits(ksb[c0 * KST + k0    ]);
                bf[1] = fbits(ksb[c0 * KST + k0 + 4]);
                mma_tf32(c[nt], qf[ks], bf);
            }
        }

        uint32_t mwA0 = mb[(size_t)grow0 * NWORDS + t * 2    ];
        uint32_t mwA1 = mb[(size_t)grow0 * NWORDS + t * 2 + 1];
        uint32_t mwB0 = mb[(size_t)grow1 * NWORDS + t * 2    ];
        uint32_t mwB1 = mb[(size_t)grow1 * NWORDS + t * 2 + 1];
        float mx0 = -INFINITY, mx1 = -INFINITY;
        #pragma unroll
        for (int nt = 0; nt < 8; nt++) {
            uint32_t wA = (nt < 4) ? mwA0 : mwA1;
            uint32_t wB = (nt < 4) ? mwB0 : mwB1;
            int j = (nt * 8 + 2 * lc) & 31;
            c[nt][0] = ((wA >> j)       & 1u) ? c[nt][0] * 0.125f : -1e9f;
            c[nt][1] = ((wA >> (j + 1)) & 1u) ? c[nt][1] * 0.125f : -1e9f;
            c[nt][2] = ((wB >> j)       & 1u) ? c[nt][2] * 0.125f : -1e9f;
            c[nt][3] = ((wB >> (j + 1)) & 1u) ? c[nt][3] * 0.125f : -1e9f;
            mx0 = fmaxf(mx0, fmaxf(c[nt][0], c[nt][1]));
            mx1 = fmaxf(mx1, fmaxf(c[nt][2], c[nt][3]));
        }
        mx0 = fmaxf(mx0, __shfl_xor_sync(0xffffffffu, mx0, 1));
        mx0 = fmaxf(mx0, __shfl_xor_sync(0xffffffffu, mx0, 2));
        mx1 = fmaxf(mx1, __shfl_xor_sync(0xffffffffu, mx1, 1));
        mx1 = fmaxf(mx1, __shfl_xor_sync(0xffffffffu, mx1, 2));

        float mn0 = fmaxf(m0, mx0);
        float mn1 = fmaxf(m1, mx1);
        float a0 = __expf(m0 - mn0);
        float a1 = __expf(m1 - mn1);
        m0 = mn0; m1 = mn1;

        float s0 = 0.f, s1 = 0.f;
        #pragma unroll
        for (int nt = 0; nt < 8; nt++) {
            int col = nt * 8 + 2 * lc;
            float p00 = __expf(c[nt][0] - mn0);
            float p01 = __expf(c[nt][1] - mn0);
            float p10 = __expf(c[nt][2] - mn1);
            float p11 = __expf(c[nt][3] - mn1);
            s0 += p00 + p01;
            s1 += p10 + p11;
            psw[lr       * PST + col    ] = fbits(tf32r(p00));
            psw[lr       * PST + col + 1] = fbits(tf32r(p01));
            psw[(lr + 8) * PST + col    ] = fbits(tf32r(p10));
            psw[(lr + 8) * PST + col + 1] = fbits(tf32r(p11));
        }
        s0 += __shfl_xor_sync(0xffffffffu, s0, 1);
        s0 += __shfl_xor_sync(0xffffffffu, s0, 2);
        s1 += __shfl_xor_sync(0xffffffffu, s1, 1);
        s1 += __shfl_xor_sync(0xffffffffu, s1, 2);
        l0 = l0 * a0 + s0;
        l1 = l1 * a1 + s1;
        __syncwarp();

        #pragma unroll
        for (int nt = 0; nt < 8; nt++) {
            o[nt][0] *= a0; o[nt][1] *= a0;
            o[nt][2] *= a1; o[nt][3] *= a1;
        }
        const float* vsb = vs_ + st * 64 * VST;
        #pragma unroll
        for (int ks = 0; ks < 8; ks++) {
            int k0 = ks * 8 + lc;
            uint32_t af[4];
            af[0] = psw[lr       * PST + k0    ];
            af[1] = psw[(lr + 8) * PST + k0    ];
            af[2] = psw[lr       * PST + k0 + 4];
            af[3] = psw[(lr + 8) * PST + k0 + 4];
            #pragma unroll
            for (int nt = 0; nt < 8; nt++) {
                int n0 = nt * 8 + lr;
                uint32_t bf[2];
                bf[0] = fbits(vsb[(k0    ) * VST + n0]);
                bf[1] = fbits(vsb[(k0 + 4) * VST + n0]);
                mma_tf32(o[nt], af, bf);
            }
        }
    }

    float inv0 = 1.f / l0, inv1 = 1.f / l1;
    #pragma unroll
    for (int nt = 0; nt < 8; nt++) {
        int col = h * 64 + nt * 8 + 2 * lc;
        *(float2*)(ctx + ((size_t)b * SEQ + grow0) * DMODEL + col) =
            make_float2(tf32r(o[nt][0] * inv0), tf32r(o[nt][1] * inv0));
        *(float2*)(ctx + ((size_t)b * SEQ + grow1) * DMODEL + col) =
            make_float2(tf32r(o[nt][2] * inv1), tf32r(o[nt][3] * inv1));
    }
#undef LOADKV
}

// ---------------- new_memory ----------------
__global__ __launch_bounds__(1024) void mem_partial_kernel(
    const float* __restrict__ xo, float* __restrict__ part)
{
    int b = blockIdx.x, cz = blockIdx.y, d = threadIdx.x;
    const float* base = xo + ((size_t)b * SEQ + cz * 128) * DMODEL + d;
    float s = 0.f;
    #pragma unroll 4
    for (int i = 0; i < 128; i++) s += base[(size_t)i * DMODEL];
    part[((size_t)b * 16 + cz) * DMODEL + d] = s;
}

__global__ __launch_bounds__(1024) void mem_final_kernel(
    const float* __restrict__ part, float* __restrict__ memout)
{
    int b = blockIdx.x, d = threadIdx.x;
    float s = 0.f;
    #pragma unroll
    for (int i = 0; i < 16; i++) s += part[((size_t)b * 16 + i) * DMODEL + d];
    float vv = s * (1.f / SEQ);
    #pragma unroll
    for (int m = 0; m < MEMT; m++)
        memout[((size_t)b * MEMT + m) * DMODEL + d] = vv;
}

// ---------------- launch ----------------
extern "C" void kernel_launch(void* const* d_in, const int* in_sizes, int n_in,
                              void* d_out, int out_size)
{
    const float* x    = (const float*)d_in[0];
    const int*   mask = (const int*)  d_in[1];
    const float* mem  = (const float*)d_in[2];
    const float* wq   = (const float*)d_in[3];
    const float* wk   = (const float*)d_in[4];
    const float* wv   = (const float*)d_in[5];
    const float* wo   = (const float*)d_in[6];
    const float* ln1a = (const float*)d_in[7];
    const float* ln1b = (const float*)d_in[8];
    const float* ln2a = (const float*)d_in[9];
    const float* ln2b = (const float*)d_in[10];
    const float* fw1  = (const float*)d_in[11];
    const float* fb1  = (const float*)d_in[12];
    const float* fw2  = (const float*)d_in[13];
    const float* fb2  = (const float*)d_in[14];
    float* out = (float*)d_out;
    float* out_mem = out + (size_t)ROWS * DMODEL;

    void* p;
    float *xn, *q, *k, *v, *ctx, *x1, *xn2, *h1, *part;
    float *wqkvt, *wot, *fw1t, *fw2t;
    uint32_t* mb;
    cudaGetSymbolAddress(&p, g_xn);  xn  = (float*)p;
    cudaGetSymbolAddress(&p, g_q);   q   = (float*)p;
    cudaGetSymbolAddress(&p, g_k);   k   = (float*)p;
    cudaGetSymbolAddress(&p, g_v);   v   = (float*)p;
    cudaGetSymbolAddress(&p, g_ctx); ctx = (float*)p;
    cudaGetSymbolAddress(&p, g_x1);  x1  = (float*)p;
    cudaGetSymbolAddress(&p, g_xn2); xn2 = (float*)p;
    cudaGetSymbolAddress(&p, g_h1);  h1  = (float*)p;
    cudaGetSymbolAddress(&p, g_part);part= (float*)p;
    cudaGetSymbolAddress(&p, g_mb);  mb  = (uint32_t*)p;
    cudaGetSymbolAddress(&p, g_wqkv);wqkvt=(float*)p;
    cudaGetSymbolAddress(&p, g_wo);  wot = (float*)p;
    cudaGetSymbolAddress(&p, g_fw1); fw1t= (float*)p;
    cudaGetSymbolAddress(&p, g_fw2); fw2t= (float*)p;

    cudaFuncSetAttribute(gemm_tc<EPI_QKV>,       cudaFuncAttributeMaxDynamicSharedMemorySize, GEMM_SMEM_BYTES);
    cudaFuncSetAttribute(gemm_tc<EPI_RESID>,     cudaFuncAttributeMaxDynamicSharedMemorySize, GEMM_SMEM_BYTES);
    cudaFuncSetAttribute(gemm_tc<EPI_BIAS_RELU>, cudaFuncAttributeMaxDynamicSharedMemorySize, GEMM_SMEM_BYTES);
    cudaFuncSetAttribute(gemm_tc<EPI_BIAS_RESID>,cudaFuncAttributeMaxDynamicSharedMemorySize, GEMM_SMEM_BYTES);
    cudaFuncSetAttribute(attn_tc, cudaFuncAttributeMaxDynamicSharedMemorySize, ATTN_SMEM_BYTES);

    // transpose + tf32-round weights to [N][K]
    dim3 tb(32, 8);
    transpose_round<<<dim3(DMODEL/32, DMODEL/32), tb>>>(wq,  wqkvt,                    DMODEL, DMODEL);
    transpose_round<<<dim3(DMODEL/32, DMODEL/32), tb>>>(wk,  wqkvt + DMODEL*DMODEL,    DMODEL, DMODEL);
    transpose_round<<<dim3(DMODEL/32, DMODEL/32), tb>>>(wv,  wqkvt + 2*DMODEL*DMODEL,  DMODEL, DMODEL);
    transpose_round<<<dim3(DMODEL/32, DMODEL/32), tb>>>(wo,  wot,  DMODEL, DMODEL);
    transpose_round<<<dim3(DFF/32,    DMODEL/32), tb>>>(fw1, fw1t, DMODEL, DFF);
    transpose_round<<<dim3(DMODEL/32, DFF/32),    tb>>>(fw2, fw2t, DFF, DMODEL);

    ln_kernel<<<ROWS, 256>>>(x, ln1a, ln1b, xn);
    maskbits_kernel<<<SEQ, NWORDS>>>(mask, mb);
    padclear_kernel<<<BATCH * NHEADS, 256>>>(k, v);

    // fused QKV projection (N = 3072)
    gemm_tc<EPI_QKV><<<dim3(3*DMODEL/BN, ROWS/BM), 256, GEMM_SMEM_BYTES>>>(
        xn, wqkvt, q, nullptr, nullptr, k, v, ROWS, 3*DMODEL, DMODEL);

    memproj_kernel<<<MEMT, 1024>>>(mem, wk, wv, k, v);

    attn_tc<<<dim3(SEQ/128, BATCH*NHEADS), 256, ATTN_SMEM_BYTES>>>(q, k, v, mb, ctx);

    gemm_tc<EPI_RESID><<<dim3(DMODEL/BN, ROWS/BM), 256, GEMM_SMEM_BYTES>>>(
        ctx, wot, x1, nullptr, x, nullptr, nullptr, ROWS, DMODEL, DMODEL);

    ln_kernel<<<ROWS, 256>>>(x1, ln2a, ln2b, xn2);

    gemm_tc<EPI_BIAS_RELU><<<dim3(DFF/BN, ROWS/BM), 256, GEMM_SMEM_BYTES>>>(
        xn2, fw1t, h1, fb1, nullptr, nullptr, nullptr, ROWS, DFF, DMODEL);
    gemm_tc<EPI_BIAS_RESID><<<dim3(DMODEL/BN, ROWS/BM), 256, GEMM_SMEM_BYTES>>>(
        h1, fw2t, out, fb2, x1, nullptr, nullptr, ROWS, DMODEL, DFF);

    mem_partial_kernel<<<dim3(BATCH, 16), 1024>>>(out, part);
    mem_final_kernel<<<BATCH, 1024>>>(part, out_mem);
}

// round 10
// speedup vs baseline: 10.1679x; 1.7460x over previous
#include <cuda_runtime.h>
#include <cuda_fp16.h>
#include <math.h>
#include <stdint.h>

// ---------------- problem constants ----------------
#define BATCH 4
#define SEQ   2048
#define DMODEL 1024
#define NHEADS 16
#define DK    64
#define MEMT  32
#define TTOT  (SEQ + MEMT)
#define T_PAD 2112
#define NKT   33
#define DFF   4096
#define ROWS  (BATCH * SEQ)
#define NWORDS 66

// ---------------- device scratch ----------------
__device__ __half g_xn [ROWS * DMODEL];
__device__ __half g_q  [BATCH * NHEADS * SEQ   * DK];
__device__ __half g_k  [BATCH * NHEADS * T_PAD * DK];
__device__ __half g_v  [BATCH * NHEADS * T_PAD * DK];
__device__ __half g_ctx[ROWS * DMODEL];
__device__ float  g_x1 [ROWS * DMODEL];
__device__ __half g_xn2[ROWS * DMODEL];
__device__ __half g_h1 [ROWS * DFF];
__device__ float  g_part[BATCH * 16 * DMODEL];
__device__ uint32_t g_mb[SEQ * NWORDS];
// transposed fp16 weights [N][K]
__device__ __half g_wqkv[3 * DMODEL * DMODEL];
__device__ __half g_wo  [DMODEL * DMODEL];
__device__ __half g_fw1 [DFF * DMODEL];
__device__ __half g_fw2 [DMODEL * DFF];

// ---------------- helpers ----------------
__device__ __forceinline__ void cp_async16(uint32_t dst, const void* src) {
    asm volatile("cp.async.cg.shared.global [%0], [%1], 16;\n" :: "r"(dst), "l"(src));
}
__device__ __forceinline__ void mma_f16(float* c, const uint32_t* a, const uint32_t* b) {
    asm volatile(
        "mma.sync.aligned.m16n8k16.row.col.f32.f16.f16.f32 "
        "{%0,%1,%2,%3},{%4,%5,%6,%7},{%8,%9},{%0,%1,%2,%3};"
        : "+f"(c[0]), "+f"(c[1]), "+f"(c[2]), "+f"(c[3])
        : "r"(a[0]), "r"(a[1]), "r"(a[2]), "r"(a[3]), "r"(b[0]), "r"(b[1]));
}
__device__ __forceinline__ void ldsm_x4_t(uint32_t& r0, uint32_t& r1, uint32_t& r2, uint32_t& r3, uint32_t addr) {
    asm volatile("ldmatrix.sync.aligned.m8n8.x4.trans.shared.b16 {%0,%1,%2,%3}, [%4];"
                 : "=r"(r0), "=r"(r1), "=r"(r2), "=r"(r3) : "r"(addr));
}
__device__ __forceinline__ uint32_t smem_u32(const void* p) {
    return (uint32_t)__cvta_generic_to_shared(p);
}

// ---------------- weight transpose + fp16: dst[N][K] = h(src[K][N]) ----------------
__global__ __launch_bounds__(256) void transpose_half(
    const float* __restrict__ src, __half* __restrict__ dst, int K, int N)
{
    __shared__ float t[32][33];
    int tx = threadIdx.x, ty = threadIdx.y;
    int n0 = blockIdx.x * 32, k0 = blockIdx.y * 32;
    #pragma unroll
    for (int i = 0; i < 4; i++)
        t[ty + 8*i][tx] = src[(size_t)(k0 + ty + 8*i) * N + n0 + tx];
    __syncthreads();
    #pragma unroll
    for (int i = 0; i < 4; i++)
        dst[(size_t)(n0 + ty + 8*i) * K + k0 + tx] = __float2half_rn(t[tx][ty + 8*i]);
}

// ---------------- layer norm (ddof=1); fp16 output ----------------
__global__ __launch_bounds__(256) void ln_kernel(
    const float* __restrict__ x, const float* __restrict__ alpha,
    const float* __restrict__ bias, __half* __restrict__ out)
{
    int row = blockIdx.x;
    int tid = threadIdx.x;
    const float4* xr = (const float4*)(x + (size_t)row * DMODEL);
    float4 v = xr[tid];
    float s  = v.x + v.y + v.z + v.w;
    float ss = v.x*v.x + v.y*v.y + v.z*v.z + v.w*v.w;
    #pragma unroll
    for (int off = 16; off > 0; off >>= 1) {
        s  += __shfl_xor_sync(0xffffffffu, s,  off);
        ss += __shfl_xor_sync(0xffffffffu, ss, off);
    }
    __shared__ float rs[8], rss[8];
    int wid = tid >> 5, lane = tid & 31;
    if (lane == 0) { rs[wid] = s; rss[wid] = ss; }
    __syncthreads();
    float S = 0.f, SS = 0.f;
    #pragma unroll
    for (int w = 0; w < 8; w++) { S += rs[w]; SS += rss[w]; }
    float mean = S * (1.f / DMODEL);
    float var  = (SS - (float)DMODEL * mean * mean) * (1.f / (DMODEL - 1));
    float inv  = 1.f / (sqrtf(fmaxf(var, 0.f)) + 1e-6f);
    float4 a  = ((const float4*)alpha)[tid];
    float4 bb = ((const float4*)bias)[tid];
    __half2* o2 = (__half2*)(out + (size_t)row * DMODEL) + tid * 2;
    o2[0] = __floats2half2_rn(a.x * (v.x - mean) * inv + bb.x,
                              a.y * (v.y - mean) * inv + bb.y);
    o2[1] = __floats2half2_rn(a.z * (v.z - mean) * inv + bb.z,
                              a.w * (v.w - mean) * inv + bb.w);
}

// ---------------- fp16 mma GEMM, 3-stage pipeline ----------------
#define EPI_QKV        0
#define EPI_RESID      3
#define EPI_BIAS_RELU  4
#define EPI_BIAS_RESID 5

#define BM 128
#define BN 128
#define BK 64
#define STH 72                    // stride in halves
#define TSZ (128 * STH)           // halves per tensor per stage (9216)
#define NSTG 3
#define GEMM_SMEM_BYTES (NSTG * 2 * TSZ * 2)   // 110592

template<int EPI>
__global__ __launch_bounds__(256, 2) void gemm_tc(
    const __half* __restrict__ A, const __half* __restrict__ W,
    void* __restrict__ Cp, const float* __restrict__ bias,
    const float* __restrict__ R, __half* __restrict__ C2, __half* __restrict__ C3,
    int M, int N, int K)
{
    extern __shared__ __half sm[];
    __half* As = sm;
    __half* Bs = sm + NSTG * TSZ;

    int tid  = threadIdx.x;
    int warp = tid >> 5, lane = tid & 31;
    int wm = warp & 1;
    int wn = warp >> 1;
    int lr = lane >> 2;
    int lc = lane & 3;

    const __half* Abase = A + (size_t)blockIdx.y * BM * K;
    const __half* Wbase = W + (size_t)blockIdx.x * BN * K;

    uint32_t sA = smem_u32(As);
    uint32_t sB = smem_u32(Bs);

    float acc[4][4][4];
    #pragma unroll
    for (int mt = 0; mt < 4; mt++)
        #pragma unroll
        for (int nt = 0; nt < 4; nt++)
            #pragma unroll
            for (int i = 0; i < 4; i++) acc[mt][nt][i] = 0.f;

#define LOAD_STAGE(st, kt) do {                                                   \
        _Pragma("unroll")                                                         \
        for (int l = 0; l < 4; l++) {                                             \
            int fid = tid + l * 256;                                              \
            int r = fid >> 3, c8 = fid & 7;                                       \
            cp_async16(sA + (uint32_t)((st) * TSZ + r * STH + c8 * 8) * 2,        \
                       Abase + (size_t)r * K + (size_t)(kt) * BK + c8 * 8);       \
        }                                                                         \
        _Pragma("unroll")                                                         \
        for (int l = 0; l < 4; l++) {                                             \
            int fid = tid + l * 256;                                              \
            int r = fid >> 3, c8 = fid & 7;                                       \
            cp_async16(sB + (uint32_t)((st) * TSZ + r * STH + c8 * 8) * 2,        \
                       Wbase + (size_t)r * K + (size_t)(kt) * BK + c8 * 8);       \
        }                                                                         \
        asm volatile("cp.async.commit_group;");                                   \
    } while (0)

    int NT = K / BK;
    LOAD_STAGE(0, 0);
    LOAD_STAGE(1, 1);

    for (int kt = 0; kt < NT; kt++) {
        int st = kt - (kt / NSTG) * NSTG;
        asm volatile("cp.async.wait_group 1;");
        __syncthreads();
        if (kt + 2 < NT) {
            int sl = st + 2; if (sl >= NSTG) sl -= NSTG;
            LOAD_STAGE(sl, kt + 2);
        } else {
            asm volatile("cp.async.commit_group;");
        }

        const uint32_t* as32 = (const uint32_t*)(As + st * TSZ);
        const uint32_t* bs32 = (const uint32_t*)(Bs + st * TSZ);

        #pragma unroll
        for (int ks = 0; ks < 4; ks++) {
            uint32_t af[4][4], bf[4][2];
            #pragma unroll
            for (int mt = 0; mt < 4; mt++) {
                int r0 = wm * 64 + mt * 16 + lr;
                af[mt][0] = as32[r0       * 36 + ks * 8 + lc    ];
                af[mt][1] = as32[(r0 + 8) * 36 + ks * 8 + lc    ];
                af[mt][2] = as32[r0       * 36 + ks * 8 + lc + 4];
                af[mt][3] = as32[(r0 + 8) * 36 + ks * 8 + lc + 4];
            }
            #pragma unroll
            for (int nt = 0; nt < 4; nt++) {
                int c0 = wn * 32 + nt * 8 + lr;
                bf[nt][0] = bs32[c0 * 36 + ks * 8 + lc    ];
                bf[nt][1] = bs32[c0 * 36 + ks * 8 + lc + 4];
            }
            #pragma unroll
            for (int mt = 0; mt < 4; mt++)
                #pragma unroll
                for (int nt = 0; nt < 4; nt++)
                    mma_f16(acc[mt][nt], af[mt], bf[nt]);
        }
        __syncthreads();
    }

    #pragma unroll
    for (int mt = 0; mt < 4; mt++) {
        #pragma unroll
        for (int rg = 0; rg < 2; rg++) {
            int r = blockIdx.y * BM + wm * 64 + mt * 16 + lr + rg * 8;
            #pragma unroll
            for (int nt = 0; nt < 4; nt++) {
                int c = blockIdx.x * BN + wn * 32 + nt * 8 + lc * 2;
                float v0 = acc[mt][nt][rg * 2 + 0];
                float v1 = acc[mt][nt][rg * 2 + 1];
                if (EPI == EPI_QKV) {
                    int sel = c >> 10, cc = c & 1023;
                    int b = r >> 11, s2 = r & 2047, h = cc >> 6, d = cc & 63;
                    __half2 o = __floats2half2_rn(v0, v1);
                    if (sel == 0)
                        *(__half2*)((__half*)Cp + ((((size_t)(b * NHEADS + h)) * SEQ + s2) * DK + d)) = o;
                    else if (sel == 1)
                        *(__half2*)(C2 + ((((size_t)(b * NHEADS + h)) * T_PAD + MEMT + s2) * DK + d)) = o;
                    else
                        *(__half2*)(C3 + ((((size_t)(b * NHEADS + h)) * T_PAD + MEMT + s2) * DK + d)) = o;
                } else if (EPI == EPI_RESID) {
                    float2 rr = *(const float2*)(R + (size_t)r * N + c);
                    *(float2*)((float*)Cp + (size_t)r * N + c) = make_float2(v0 + rr.x, v1 + rr.y);
                } else if (EPI == EPI_BIAS_RELU) {
                    float2 bb = *(const float2*)(bias + c);
                    *(__half2*)((__half*)Cp + (size_t)r * N + c) =
                        __floats2half2_rn(fmaxf(v0 + bb.x, 0.f), fmaxf(v1 + bb.y, 0.f));
                } else if (EPI == EPI_BIAS_RESID) {
                    float2 bb = *(const float2*)(bias + c);
                    float2 rr = *(const float2*)(R + (size_t)r * N + c);
                    *(float2*)((float*)Cp + (size_t)r * N + c) = make_float2(v0 + bb.x + rr.x, v1 + bb.y + rr.y);
                }
            }
        }
    }
#undef LOAD_STAGE
}

// ---------------- memory-token K/V projection (fp16 outputs) ----------------
__global__ __launch_bounds__(1024) void memproj_kernel(
    const float* __restrict__ mt, const float* __restrict__ wk,
    const float* __restrict__ wv, __half* __restrict__ kh, __half* __restrict__ vh)
{
    int m = blockIdx.x;
    int c = threadIdx.x;
    float ak = 0.f, av = 0.f;
    #pragma unroll 4
    for (int kk = 0; kk < DMODEL; kk++) {
        float xm = mt[(size_t)m * DMODEL + kk];
        ak = fmaf(xm, wk[(size_t)kk * DMODEL + c], ak);
        av = fmaf(xm, wv[(size_t)kk * DMODEL + c], av);
    }
    __half ah = __float2half_rn(ak), vh_ = __float2half_rn(av);
    int h = c >> 6, d = c & 63;
    #pragma unroll
    for (int b = 0; b < BATCH; b++) {
        size_t idx = (((size_t)(b * NHEADS + h)) * T_PAD + m) * DK + d;
        kh[idx] = ah;
        vh[idx] = vh_;
    }
}

__global__ __launch_bounds__(256) void padclear_kernel(__half* k, __half* v)
{
    int bh = blockIdx.x;
    size_t base = ((size_t)bh * T_PAD + TTOT) * DK / 2;
    uint32_t* k32 = (uint32_t*)k;
    uint32_t* v32 = (uint32_t*)v;
    for (int i = threadIdx.x; i < (T_PAD - TTOT) * DK / 2; i += 256) {
        k32[base + i] = 0u;
        v32[base + i] = 0u;
    }
}

__global__ void maskbits_kernel(const int* __restrict__ mask, uint32_t* __restrict__ mb)
{
    int s = blockIdx.x;
    int w = threadIdx.x;
    uint32_t bits = 0;
    #pragma unroll 4
    for (int j = 0; j < 32; j++) {
        int t = w * 32 + j;
        if (t < TTOT && mask[(size_t)s * TTOT + t] != 0) bits |= (1u << j);
    }
    mb[(size_t)s * NWORDS + w] = bits;
}

// ---------------- fp16 flash attention: warp-owned rows ----------------
#define KSTH 72
#define KTSZ (64 * KSTH)
#define PSTH 72
#define ATTN_SMEM_BYTES ((2*KTSZ + 2*KTSZ + 8*16*PSTH) * 2)   // 55296

__global__ __launch_bounds__(256, 2) void attn_tc(
    const __half* __restrict__ q, const __half* __restrict__ k,
    const __half* __restrict__ v, const uint32_t* __restrict__ mb,
    __half* __restrict__ ctx)
{
    extern __shared__ __half smh[];
    __half* ks_ = smh;
    __half* vs_ = ks_ + 2 * KTSZ;
    __half* ps_ = vs_ + 2 * KTSZ;

    int tid  = threadIdx.x;
    int warp = tid >> 5, lane = tid & 31;
    int lr = lane >> 2, lc = lane & 3;
    int bh = blockIdx.y;
    int b  = bh >> 4, h = bh & 15;
    int q0 = blockIdx.x * 128;

    const __half* qb = q + (((size_t)bh) * SEQ + q0) * DK;
    const __half* kb = k + ((size_t)bh) * T_PAD * DK;
    const __half* vb = v + ((size_t)bh) * T_PAD * DK;

    int row0 = warp * 16 + lr;
    int row1 = row0 + 8;
    int grow0 = q0 + row0, grow1 = q0 + row1;
    __half* psw = ps_ + warp * 16 * PSTH;
    const uint32_t* psw32 = (const uint32_t*)psw;

    uint32_t qf[4][4];
    #pragma unroll
    for (int ks = 0; ks < 4; ks++) {
        qf[ks][0] = *(const uint32_t*)(qb + (size_t)row0 * DK + ks * 16 + 2 * lc    );
        qf[ks][1] = *(const uint32_t*)(qb + (size_t)row1 * DK + ks * 16 + 2 * lc    );
        qf[ks][2] = *(const uint32_t*)(qb + (size_t)row0 * DK + ks * 16 + 2 * lc + 8);
        qf[ks][3] = *(const uint32_t*)(qb + (size_t)row1 * DK + ks * 16 + 2 * lc + 8);
    }

    float o[8][4];
    #pragma unroll
    for (int nt = 0; nt < 8; nt++)
        #pragma unroll
        for (int i = 0; i < 4; i++) o[nt][i] = 0.f;

    float m0 = -INFINITY, m1 = -INFINITY, l0 = 0.f, l1 = 0.f;

    uint32_t sK = smem_u32(ks_);
    uint32_t sV = smem_u32(vs_);

    // FIX (R9 NaN): 64 rows x 64 halves = 8192 B = 512 16B-chunks per tensor
    // -> two iterations of 256 threads, r = fid>>3 (0..63), c8 = fid&7 (0..7).
#define LOADKV(st, tile) do {                                                       \
        _Pragma("unroll")                                                           \
        for (int l = 0; l < 2; l++) {                                               \
            int fid = tid + l * 256;                                                \
            int r = fid >> 3, c8 = fid & 7;                                         \
            cp_async16(sK + (uint32_t)((st) * KTSZ + r * KSTH + c8 * 8) * 2,        \
                       kb + ((size_t)(tile) * 64 + r) * DK + c8 * 8);               \
            cp_async16(sV + (uint32_t)((st) * KTSZ + r * KSTH + c8 * 8) * 2,        \
                       vb + ((size_t)(tile) * 64 + r) * DK + c8 * 8);               \
        }                                                                           \
        asm volatile("cp.async.commit_group;");                                     \
    } while (0)

    LOADKV(0, 0);

    for (int t = 0; t < NKT; t++) {
        int st = t & 1;
        __syncthreads();
        if (t + 1 < NKT) {
            LOADKV(st ^ 1, t + 1);
            asm volatile("cp.async.wait_group 1;");
        } else {
            asm volatile("cp.async.wait_group 0;");
        }
        __syncthreads();

        float c[8][4];
        #pragma unroll
        for (int nt = 0; nt < 8; nt++)
            #pragma unroll
            for (int i = 0; i < 4; i++) c[nt][i] = 0.f;

        const uint32_t* ks32 = (const uint32_t*)(ks_ + st * KTSZ);
        #pragma unroll
        for (int ks = 0; ks < 4; ks++) {
            #pragma unroll
            for (int nt = 0; nt < 8; nt++) {
                int c0 = nt * 8 + lr;
                uint32_t bf[2];
                bf[0] = ks32[c0 * 36 + ks * 8 + lc    ];
                bf[1] = ks32[c0 * 36 + ks * 8 + lc + 4];
                mma_f16(c[nt], qf[ks], bf);
            }
        }

        uint32_t mwA0 = mb[(size_t)grow0 * NWORDS + t * 2    ];
        uint32_t mwA1 = mb[(size_t)grow0 * NWORDS + t * 2 + 1];
        uint32_t mwB0 = mb[(size_t)grow1 * NWORDS + t * 2    ];
        uint32_t mwB1 = mb[(size_t)grow1 * NWORDS + t * 2 + 1];
        float mx0 = -INFINITY, mx1 = -INFINITY;
        #pragma unroll
        for (int nt = 0; nt < 8; nt++) {
            uint32_t wA = (nt < 4) ? mwA0 : mwA1;
            uint32_t wB = (nt < 4) ? mwB0 : mwB1;
            int j = (nt * 8 + 2 * lc) & 31;
            c[nt][0] = ((wA >> j)       & 1u) ? c[nt][0] * 0.125f : -1e9f;
            c[nt][1] = ((wA >> (j + 1)) & 1u) ? c[nt][1] * 0.125f : -1e9f;
            c[nt][2] = ((wB >> j)       & 1u) ? c[nt][2] * 0.125f : -1e9f;
            c[nt][3] = ((wB >> (j + 1)) & 1u) ? c[nt][3] * 0.125f : -1e9f;
            mx0 = fmaxf(mx0, fmaxf(c[nt][0], c[nt][1]));
            mx1 = fmaxf(mx1, fmaxf(c[nt][2], c[nt][3]));
        }
        mx0 = fmaxf(mx0, __shfl_xor_sync(0xffffffffu, mx0, 1));
        mx0 = fmaxf(mx0, __shfl_xor_sync(0xffffffffu, mx0, 2));
        mx1 = fmaxf(mx1, __shfl_xor_sync(0xffffffffu, mx1, 1));
        mx1 = fmaxf(mx1, __shfl_xor_sync(0xffffffffu, mx1, 2));

        float mn0 = fmaxf(m0, mx0);
        float mn1 = fmaxf(m1, mx1);
        float a0 = __expf(m0 - mn0);
        float a1 = __expf(m1 - mn1);
        m0 = mn0; m1 = mn1;

        float s0 = 0.f, s1 = 0.f;
        #pragma unroll
        for (int nt = 0; nt < 8; nt++) {
            int col = nt * 8 + 2 * lc;
            float p00 = __expf(c[nt][0] - mn0);
            float p01 = __expf(c[nt][1] - mn0);
            float p10 = __expf(c[nt][2] - mn1);
            float p11 = __expf(c[nt][3] - mn1);
            s0 += p00 + p01;
            s1 += p10 + p11;
            *(__half2*)(psw + lr       * PSTH + col) = __floats2half2_rn(p00, p01);
            *(__half2*)(psw + (lr + 8) * PSTH + col) = __floats2half2_rn(p10, p11);
        }
        s0 += __shfl_xor_sync(0xffffffffu, s0, 1);
        s0 += __shfl_xor_sync(0xffffffffu, s0, 2);
        s1 += __shfl_xor_sync(0xffffffffu, s1, 1);
        s1 += __shfl_xor_sync(0xffffffffu, s1, 2);
        l0 = l0 * a0 + s0;
        l1 = l1 * a1 + s1;
        __syncwarp();

        #pragma unroll
        for (int nt = 0; nt < 8; nt++) {
            o[nt][0] *= a0; o[nt][1] *= a0;
            o[nt][2] *= a1; o[nt][3] *= a1;
        }
        uint32_t vbase = sV + (uint32_t)(st * KTSZ) * 2;
        #pragma unroll
        for (int ks = 0; ks < 4; ks++) {
            uint32_t af[4];
            af[0] = psw32[lr       * 36 + ks * 8 + lc    ];
            af[1] = psw32[(lr + 8) * 36 + ks * 8 + lc    ];
            af[2] = psw32[lr       * 36 + ks * 8 + lc + 4];
            af[3] = psw32[(lr + 8) * 36 + ks * 8 + lc + 4];
            #pragma unroll
            for (int np = 0; np < 4; np++) {
                uint32_t addr = vbase
                    + (uint32_t)((ks * 16 + (lane & 15)) * KSTH) * 2
                    + (uint32_t)(np * 16 + ((lane >> 4) << 3)) * 2;
                uint32_t b0, b1, b2, b3;
                ldsm_x4_t(b0, b1, b2, b3, addr);
                uint32_t bf0[2] = {b0, b1};
                uint32_t bf1[2] = {b2, b3};
                mma_f16(o[np * 2    ], af, bf0);
                mma_f16(o[np * 2 + 1], af, bf1);
            }
        }
    }

    float inv0 = 1.f / l0, inv1 = 1.f / l1;
    #pragma unroll
    for (int nt = 0; nt < 8; nt++) {
        int col = h * 64 + nt * 8 + 2 * lc;
        *(__half2*)(ctx + ((size_t)b * SEQ + grow0) * DMODEL + col) =
            __floats2half2_rn(o[nt][0] * inv0, o[nt][1] * inv0);
        *(__half2*)(ctx + ((size_t)b * SEQ + grow1) * DMODEL + col) =
            __floats2half2_rn(o[nt][2] * inv1, o[nt][3] * inv1);
    }
#undef LOADKV
}

// ---------------- new_memory ----------------
__global__ __launch_bounds__(1024) void mem_partial_kernel(
    const float* __restrict__ xo, float* __restrict__ part)
{
    int b = blockIdx.x, cz = blockIdx.y, d = threadIdx.x;
    const float* base = xo + ((size_t)b * SEQ + cz * 128) * DMODEL + d;
    float s = 0.f;
    #pragma unroll 4
    for (int i = 0; i < 128; i++) s += base[(size_t)i * DMODEL];
    part[((size_t)b * 16 + cz) * DMODEL + d] = s;
}

__global__ __launch_bounds__(1024) void mem_final_kernel(
    const float* __restrict__ part, float* __restrict__ memout)
{
    int b = blockIdx.x, d = threadIdx.x;
    float s = 0.f;
    #pragma unroll
    for (int i = 0; i < 16; i++) s += part[((size_t)b * 16 + i) * DMODEL + d];
    float vv = s * (1.f / SEQ);
    #pragma unroll
    for (int m = 0; m < MEMT; m++)
        memout[((size_t)b * MEMT + m) * DMODEL + d] = vv;
}

// ---------------- launch ----------------
extern "C" void kernel_launch(void* const* d_in, const int* in_sizes, int n_in,
                              void* d_out, int out_size)
{
    const float* x    = (const float*)d_in[0];
    const int*   mask = (const int*)  d_in[1];
    const float* mem  = (const float*)d_in[2];
    const float* wq   = (const float*)d_in[3];
    const float* wk   = (const float*)d_in[4];
    const float* wv   = (const float*)d_in[5];
    const float* wo   = (const float*)d_in[6];
    const float* ln1a = (const float*)d_in[7];
    const float* ln1b = (const float*)d_in[8];
    const float* ln2a = (const float*)d_in[9];
    const float* ln2b = (const float*)d_in[10];
    const float* fw1  = (const float*)d_in[11];
    const float* fb1  = (const float*)d_in[12];
    const float* fw2  = (const float*)d_in[13];
    const float* fb2  = (const float*)d_in[14];
    float* out = (float*)d_out;
    float* out_mem = out + (size_t)ROWS * DMODEL;

    void* p;
    __half *xn, *q, *k, *v, *ctx, *xn2, *h1;
    float *x1, *part;
    __half *wqkvt, *wot, *fw1t, *fw2t;
    uint32_t* mb;
    cudaGetSymbolAddress(&p, g_xn);  xn  = (__half*)p;
    cudaGetSymbolAddress(&p, g_q);   q   = (__half*)p;
    cudaGetSymbolAddress(&p, g_k);   k   = (__half*)p;
    cudaGetSymbolAddress(&p, g_v);   v   = (__half*)p;
    cudaGetSymbolAddress(&p, g_ctx); ctx = (__half*)p;
    cudaGetSymbolAddress(&p, g_x1);  x1  = (float*)p;
    cudaGetSymbolAddress(&p, g_xn2); xn2 = (__half*)p;
    cudaGetSymbolAddress(&p, g_h1);  h1  = (__half*)p;
    cudaGetSymbolAddress(&p, g_part);part= (float*)p;
    cudaGetSymbolAddress(&p, g_mb);  mb  = (uint32_t*)p;
    cudaGetSymbolAddress(&p, g_wqkv);wqkvt=(__half*)p;
    cudaGetSymbolAddress(&p, g_wo);  wot = (__half*)p;
    cudaGetSymbolAddress(&p, g_fw1); fw1t= (__half*)p;
    cudaGetSymbolAddress(&p, g_fw2); fw2t= (__half*)p;

    cudaFuncSetAttribute(gemm_tc<EPI_QKV>,       cudaFuncAttributeMaxDynamicSharedMemorySize, GEMM_SMEM_BYTES);
    cudaFuncSetAttribute(gemm_tc<EPI_RESID>,     cudaFuncAttributeMaxDynamicSharedMemorySize, GEMM_SMEM_BYTES);
    cudaFuncSetAttribute(gemm_tc<EPI_BIAS_RELU>, cudaFuncAttributeMaxDynamicSharedMemorySize, GEMM_SMEM_BYTES);
    cudaFuncSetAttribute(gemm_tc<EPI_BIAS_RESID>,cudaFuncAttributeMaxDynamicSharedMemorySize, GEMM_SMEM_BYTES);
    cudaFuncSetAttribute(attn_tc, cudaFuncAttributeMaxDynamicSharedMemorySize, ATTN_SMEM_BYTES);

    dim3 tb(32, 8);
    transpose_half<<<dim3(DMODEL/32, DMODEL/32), tb>>>(wq,  wqkvt,                   DMODEL, DMODEL);
    transpose_half<<<dim3(DMODEL/32, DMODEL/32), tb>>>(wk,  wqkvt + DMODEL*DMODEL,   DMODEL, DMODEL);
    transpose_half<<<dim3(DMODEL/32, DMODEL/32), tb>>>(wv,  wqkvt + 2*DMODEL*DMODEL, DMODEL, DMODEL);
    transpose_half<<<dim3(DMODEL/32, DMODEL/32), tb>>>(wo,  wot,  DMODEL, DMODEL);
    transpose_half<<<dim3(DFF/32,    DMODEL/32), tb>>>(fw1, fw1t, DMODEL, DFF);
    transpose_half<<<dim3(DMODEL/32, DFF/32),    tb>>>(fw2, fw2t, DFF, DMODEL);

    ln_kernel<<<ROWS, 256>>>(x, ln1a, ln1b, xn);
    maskbits_kernel<<<SEQ, NWORDS>>>(mask, mb);
    padclear_kernel<<<BATCH * NHEADS, 256>>>(k, v);

    gemm_tc<EPI_QKV><<<dim3(3*DMODEL/BN, ROWS/BM), 256, GEMM_SMEM_BYTES>>>(
        xn, wqkvt, q, nullptr, nullptr, k, v, ROWS, 3*DMODEL, DMODEL);

    memproj_kernel<<<MEMT, 1024>>>(mem, wk, wv, k, v);

    attn_tc<<<dim3(SEQ/128, BATCH*NHEADS), 256, ATTN_SMEM_BYTES>>>(q, k, v, mb, ctx);

    gemm_tc<EPI_RESID><<<dim3(DMODEL/BN, ROWS/BM), 256, GEMM_SMEM_BYTES>>>(
        ctx, wot, x1, nullptr, x, nullptr, nullptr, ROWS, DMODEL, DMODEL);

    ln_kernel<<<ROWS, 256>>>(x1, ln2a, ln2b, xn2);

    gemm_tc<EPI_BIAS_RELU><<<dim3(DFF/BN, ROWS/BM), 256, GEMM_SMEM_BYTES>>>(
        xn2, fw1t, h1, fb1, nullptr, nullptr, nullptr, ROWS, DFF, DMODEL);
    gemm_tc<EPI_BIAS_RESID><<<dim3(DMODEL/BN, ROWS/BM), 256, GEMM_SMEM_BYTES>>>(
        h1, fw2t, out, fb2, x1, nullptr, nullptr, ROWS, DMODEL, DFF);

    mem_partial_kernel<<<dim3(BATCH, 16), 1024>>>(out, part);
    mem_final_kernel<<<BATCH, 1024>>>(part, out_mem);
}

// round 11
// speedup vs baseline: 10.6629x; 1.0487x over previous
#include <cuda_runtime.h>
#include <cuda_fp16.h>
#include <math.h>
#include <stdint.h>

// ---------------- problem constants ----------------
#define BATCH 4
#define SEQ   2048
#define DMODEL 1024
#define NHEADS 16
#define DK    64
#define MEMT  32
#define TTOT  (SEQ + MEMT)
#define T_PAD 2112
#define NKT   33
#define DFF   4096
#define ROWS  (BATCH * SEQ)
#define NWORDS 66

// ---------------- device scratch ----------------
__device__ __half g_xn [ROWS * DMODEL];
__device__ __half g_q  [BATCH * NHEADS * SEQ   * DK];
__device__ __half g_k  [BATCH * NHEADS * T_PAD * DK];
__device__ __half g_v  [BATCH * NHEADS * T_PAD * DK];
__device__ __half g_ctx[ROWS * DMODEL];
__device__ float  g_x1 [ROWS * DMODEL];
__device__ __half g_xn2[ROWS * DMODEL];
__device__ __half g_h1 [ROWS * DFF];
__device__ float  g_part[BATCH * 16 * DMODEL];
__device__ uint32_t g_mb[SEQ * NWORDS];
__device__ __half g_wqkv[3 * DMODEL * DMODEL];
__device__ __half g_wo  [DMODEL * DMODEL];
__device__ __half g_fw1 [DFF * DMODEL];
__device__ __half g_fw2 [DMODEL * DFF];

// ---------------- helpers ----------------
__device__ __forceinline__ void cp_async16(uint32_t dst, const void* src) {
    asm volatile("cp.async.cg.shared.global [%0], [%1], 16;\n" :: "r"(dst), "l"(src));
}
__device__ __forceinline__ void mma_f16(float* c, const uint32_t* a, const uint32_t* b) {
    asm volatile(
        "mma.sync.aligned.m16n8k16.row.col.f32.f16.f16.f32 "
        "{%0,%1,%2,%3},{%4,%5,%6,%7},{%8,%9},{%0,%1,%2,%3};"
        : "+f"(c[0]), "+f"(c[1]), "+f"(c[2]), "+f"(c[3])
        : "r"(a[0]), "r"(a[1]), "r"(a[2]), "r"(a[3]), "r"(b[0]), "r"(b[1]));
}
__device__ __forceinline__ void ldsm_x4(uint32_t& r0, uint32_t& r1, uint32_t& r2, uint32_t& r3, uint32_t addr) {
    asm volatile("ldmatrix.sync.aligned.m8n8.x4.shared.b16 {%0,%1,%2,%3}, [%4];"
                 : "=r"(r0), "=r"(r1), "=r"(r2), "=r"(r3) : "r"(addr));
}
__device__ __forceinline__ void ldsm_x4_t(uint32_t& r0, uint32_t& r1, uint32_t& r2, uint32_t& r3, uint32_t addr) {
    asm volatile("ldmatrix.sync.aligned.m8n8.x4.trans.shared.b16 {%0,%1,%2,%3}, [%4];"
                 : "=r"(r0), "=r"(r1), "=r"(r2), "=r"(r3) : "r"(addr));
}
__device__ __forceinline__ uint32_t smem_u32(const void* p) {
    return (uint32_t)__cvta_generic_to_shared(p);
}

// ---------------- weight transpose + fp16: dst[N][K] = h(src[K][N]) ----------------
__global__ __launch_bounds__(256) void transpose_half(
    const float* __restrict__ src, __half* __restrict__ dst, int K, int N)
{
    __shared__ float t[32][33];
    int tx = threadIdx.x, ty = threadIdx.y;
    int n0 = blockIdx.x * 32, k0 = blockIdx.y * 32;
    #pragma unroll
    for (int i = 0; i < 4; i++)
        t[ty + 8*i][tx] = src[(size_t)(k0 + ty + 8*i) * N + n0 + tx];
    __syncthreads();
    #pragma unroll
    for (int i = 0; i < 4; i++)
        dst[(size_t)(n0 + ty + 8*i) * K + k0 + tx] = __float2half_rn(t[tx][ty + 8*i]);
}

// ---------------- layer norm (ddof=1); fp16 output ----------------
__global__ __launch_bounds__(256) void ln_kernel(
    const float* __restrict__ x, const float* __restrict__ alpha,
    const float* __restrict__ bias, __half* __restrict__ out)
{
    int row = blockIdx.x;
    int tid = threadIdx.x;
    const float4* xr = (const float4*)(x + (size_t)row * DMODEL);
    float4 v = xr[tid];
    float s  = v.x + v.y + v.z + v.w;
    float ss = v.x*v.x + v.y*v.y + v.z*v.z + v.w*v.w;
    #pragma unroll
    for (int off = 16; off > 0; off >>= 1) {
        s  += __shfl_xor_sync(0xffffffffu, s,  off);
        ss += __shfl_xor_sync(0xffffffffu, ss, off);
    }
    __shared__ float rs[8], rss[8];
    int wid = tid >> 5, lane = tid & 31;
    if (lane == 0) { rs[wid] = s; rss[wid] = ss; }
    __syncthreads();
    float S = 0.f, SS = 0.f;
    #pragma unroll
    for (int w = 0; w < 8; w++) { S += rs[w]; SS += rss[w]; }
    float mean = S * (1.f / DMODEL);
    float var  = (SS - (float)DMODEL * mean * mean) * (1.f / (DMODEL - 1));
    float inv  = 1.f / (sqrtf(fmaxf(var, 0.f)) + 1e-6f);
    float4 a  = ((const float4*)alpha)[tid];
    float4 bb = ((const float4*)bias)[tid];
    __half2* o2 = (__half2*)(out + (size_t)row * DMODEL) + tid * 2;
    o2[0] = __floats2half2_rn(a.x * (v.x - mean) * inv + bb.x,
                              a.y * (v.y - mean) * inv + bb.y);
    o2[1] = __floats2half2_rn(a.z * (v.z - mean) * inv + bb.z,
                              a.w * (v.w - mean) * inv + bb.w);
}

// ---------------- fp16 mma GEMM, 3-stage pipeline, ldmatrix fragments ----------------
#define EPI_QKV        0
#define EPI_RESID      3
#define EPI_BIAS_RELU  4
#define EPI_BIAS_RESID 5

#define BM 128
#define BN 128
#define BK 64
#define STH 72
#define TSZ (128 * STH)
#define NSTG 3
#define GEMM_SMEM_BYTES (NSTG * 2 * TSZ * 2)   // 110592

template<int EPI>
__global__ __launch_bounds__(256, 2) void gemm_tc(
    const __half* __restrict__ A, const __half* __restrict__ W,
    void* __restrict__ Cp, const float* __restrict__ bias,
    const float* __restrict__ R, __half* __restrict__ C2, __half* __restrict__ C3,
    int M, int N, int K)
{
    extern __shared__ __half sm[];
    __half* As = sm;
    __half* Bs = sm + NSTG * TSZ;

    int tid  = threadIdx.x;
    int warp = tid >> 5, lane = tid & 31;
    int wm = warp & 1;
    int wn = warp >> 1;
    int lr = lane >> 2;
    int lc = lane & 3;

    const __half* Abase = A + (size_t)blockIdx.y * BM * K;
    const __half* Wbase = W + (size_t)blockIdx.x * BN * K;

    uint32_t sA = smem_u32(As);
    uint32_t sB = smem_u32(Bs);

    // ldmatrix per-lane row/col offsets (constant across loop)
    int a_row = (lane & 7) + ((lane >> 3) & 1) * 8;   // + mt*16 + wm*64
    int a_kof = (lane >> 4) * 8;
    int b_row = (lane & 7) + ((lane >> 4) & 1) * 8;   // + nb*16 + wn*32
    int b_kof = ((lane >> 3) & 1) * 8;

    float acc[4][4][4];
    #pragma unroll
    for (int mt = 0; mt < 4; mt++)
        #pragma unroll
        for (int nt = 0; nt < 4; nt++)
            #pragma unroll
            for (int i = 0; i < 4; i++) acc[mt][nt][i] = 0.f;

#define LOAD_STAGE(st, kt) do {                                                   \
        _Pragma("unroll")                                                         \
        for (int l = 0; l < 4; l++) {                                             \
            int fid = tid + l * 256;                                              \
            int r = fid >> 3, c8 = fid & 7;                                       \
            cp_async16(sA + (uint32_t)((st) * TSZ + r * STH + c8 * 8) * 2,        \
                       Abase + (size_t)r * K + (size_t)(kt) * BK + c8 * 8);       \
        }                                                                         \
        _Pragma("unroll")                                                         \
        for (int l = 0; l < 4; l++) {                                             \
            int fid = tid + l * 256;                                              \
            int r = fid >> 3, c8 = fid & 7;                                       \
            cp_async16(sB + (uint32_t)((st) * TSZ + r * STH + c8 * 8) * 2,        \
                       Wbase + (size_t)r * K + (size_t)(kt) * BK + c8 * 8);       \
        }                                                                         \
        asm volatile("cp.async.commit_group;");                                   \
    } while (0)

    int NT = K / BK;
    LOAD_STAGE(0, 0);
    LOAD_STAGE(1, 1);

    for (int kt = 0; kt < NT; kt++) {
        int st = kt - (kt / NSTG) * NSTG;
        asm volatile("cp.async.wait_group 1;");
        __syncthreads();
        if (kt + 2 < NT) {
            int sl = st + 2; if (sl >= NSTG) sl -= NSTG;
            LOAD_STAGE(sl, kt + 2);
        } else {
            asm volatile("cp.async.commit_group;");
        }

        uint32_t aS = sA + (uint32_t)(st * TSZ) * 2;
        uint32_t bS = sB + (uint32_t)(st * TSZ) * 2;

        #pragma unroll
        for (int ks = 0; ks < 4; ks++) {
            uint32_t af[4][4], bf[4][2];
            #pragma unroll
            for (int mt = 0; mt < 4; mt++) {
                uint32_t addr = aS + (uint32_t)(((wm * 64 + mt * 16 + a_row) * STH)
                                                 + ks * 16 + a_kof) * 2;
                ldsm_x4(af[mt][0], af[mt][1], af[mt][2], af[mt][3], addr);
            }
            #pragma unroll
            for (int nb = 0; nb < 2; nb++) {
                uint32_t addr = bS + (uint32_t)(((wn * 32 + nb * 16 + b_row) * STH)
                                                 + ks * 16 + b_kof) * 2;
                uint32_t r0, r1, r2, r3;
                ldsm_x4(r0, r1, r2, r3, addr);
                bf[nb * 2    ][0] = r0; bf[nb * 2    ][1] = r1;
                bf[nb * 2 + 1][0] = r2; bf[nb * 2 + 1][1] = r3;
            }
            #pragma unroll
            for (int mt = 0; mt < 4; mt++)
                #pragma unroll
                for (int nt = 0; nt < 4; nt++)
                    mma_f16(acc[mt][nt], af[mt], bf[nt]);
        }
        __syncthreads();
    }

    #pragma unroll
    for (int mt = 0; mt < 4; mt++) {
        #pragma unroll
        for (int rg = 0; rg < 2; rg++) {
            int r = blockIdx.y * BM + wm * 64 + mt * 16 + lr + rg * 8;
            #pragma unroll
            for (int nt = 0; nt < 4; nt++) {
                int c = blockIdx.x * BN + wn * 32 + nt * 8 + lc * 2;
                float v0 = acc[mt][nt][rg * 2 + 0];
                float v1 = acc[mt][nt][rg * 2 + 1];
                if (EPI == EPI_QKV) {
                    int sel = c >> 10, cc = c & 1023;
                    int b = r >> 11, s2 = r & 2047, h = cc >> 6, d = cc & 63;
                    __half2 o = __floats2half2_rn(v0, v1);
                    if (sel == 0)
                        *(__half2*)((__half*)Cp + ((((size_t)(b * NHEADS + h)) * SEQ + s2) * DK + d)) = o;
                    else if (sel == 1)
                        *(__half2*)(C2 + ((((size_t)(b * NHEADS + h)) * T_PAD + MEMT + s2) * DK + d)) = o;
                    else
                        *(__half2*)(C3 + ((((size_t)(b * NHEADS + h)) * T_PAD + MEMT + s2) * DK + d)) = o;
                } else if (EPI == EPI_RESID) {
                    float2 rr = *(const float2*)(R + (size_t)r * N + c);
                    *(float2*)((float*)Cp + (size_t)r * N + c) = make_float2(v0 + rr.x, v1 + rr.y);
                } else if (EPI == EPI_BIAS_RELU) {
                    float2 bb = *(const float2*)(bias + c);
                    *(__half2*)((__half*)Cp + (size_t)r * N + c) =
                        __floats2half2_rn(fmaxf(v0 + bb.x, 0.f), fmaxf(v1 + bb.y, 0.f));
                } else if (EPI == EPI_BIAS_RESID) {
                    float2 bb = *(const float2*)(bias + c);
                    float2 rr = *(const float2*)(R + (size_t)r * N + c);
                    *(float2*)((float*)Cp + (size_t)r * N + c) = make_float2(v0 + bb.x + rr.x, v1 + bb.y + rr.y);
                }
            }
        }
    }
#undef LOAD_STAGE
}

// ---------------- memory-token K/V projection (fp16 outputs) ----------------
__global__ __launch_bounds__(1024) void memproj_kernel(
    const float* __restrict__ mt, const float* __restrict__ wk,
    const float* __restrict__ wv, __half* __restrict__ kh, __half* __restrict__ vh)
{
    int m = blockIdx.x;
    int c = threadIdx.x;
    float ak = 0.f, av = 0.f;
    #pragma unroll 4
    for (int kk = 0; kk < DMODEL; kk++) {
        float xm = mt[(size_t)m * DMODEL + kk];
        ak = fmaf(xm, wk[(size_t)kk * DMODEL + c], ak);
        av = fmaf(xm, wv[(size_t)kk * DMODEL + c], av);
    }
    __half ah = __float2half_rn(ak), vh_ = __float2half_rn(av);
    int h = c >> 6, d = c & 63;
    #pragma unroll
    for (int b = 0; b < BATCH; b++) {
        size_t idx = (((size_t)(b * NHEADS + h)) * T_PAD + m) * DK + d;
        kh[idx] = ah;
        vh[idx] = vh_;
    }
}

__global__ __launch_bounds__(256) void padclear_kernel(__half* k, __half* v)
{
    int bh = blockIdx.x;
    size_t base = ((size_t)bh * T_PAD + TTOT) * DK / 2;
    uint32_t* k32 = (uint32_t*)k;
    uint32_t* v32 = (uint32_t*)v;
    for (int i = threadIdx.x; i < (T_PAD - TTOT) * DK / 2; i += 256) {
        k32[base + i] = 0u;
        v32[base + i] = 0u;
    }
}

__global__ void maskbits_kernel(const int* __restrict__ mask, uint32_t* __restrict__ mb)
{
    int s = blockIdx.x;
    int w = threadIdx.x;
    uint32_t bits = 0;
    #pragma unroll 4
    for (int j = 0; j < 32; j++) {
        int t = w * 32 + j;
        if (t < TTOT && mask[(size_t)s * TTOT + t] != 0) bits |= (1u << j);
    }
    mb[(size_t)s * NWORDS + w] = bits;
}

// ---------------- fp16 flash attention: warp-owned rows, ldmatrix loads ----------------
#define KSTH 72
#define KTSZ (64 * KSTH)
#define PSTH 72
#define ATTN_SMEM_BYTES ((2*KTSZ + 2*KTSZ + 8*16*PSTH) * 2)   // 55296

__global__ __launch_bounds__(256, 2) void attn_tc(
    const __half* __restrict__ q, const __half* __restrict__ k,
    const __half* __restrict__ v, const uint32_t* __restrict__ mb,
    __half* __restrict__ ctx)
{
    extern __shared__ __half smh[];
    __half* ks_ = smh;
    __half* vs_ = ks_ + 2 * KTSZ;
    __half* ps_ = vs_ + 2 * KTSZ;

    int tid  = threadIdx.x;
    int warp = tid >> 5, lane = tid & 31;
    int lr = lane >> 2, lc = lane & 3;
    int bh = blockIdx.y;
    int b  = bh >> 4, h = bh & 15;
    int q0 = blockIdx.x * 128;

    const __half* qb = q + (((size_t)bh) * SEQ + q0) * DK;
    const __half* kb = k + ((size_t)bh) * T_PAD * DK;
    const __half* vb = v + ((size_t)bh) * T_PAD * DK;

    int row0 = warp * 16 + lr;
    int row1 = row0 + 8;
    int grow0 = q0 + row0, grow1 = q0 + row1;
    __half* psw = ps_ + warp * 16 * PSTH;
    uint32_t sP = smem_u32(psw);

    // ldmatrix lane offsets
    int a_row = (lane & 7) + ((lane >> 3) & 1) * 8;
    int a_kof = (lane >> 4) * 8;
    int b_row = (lane & 7) + ((lane >> 4) & 1) * 8;
    int b_kof = ((lane >> 3) & 1) * 8;

    uint32_t qf[4][4];
    #pragma unroll
    for (int ks = 0; ks < 4; ks++) {
        qf[ks][0] = *(const uint32_t*)(qb + (size_t)row0 * DK + ks * 16 + 2 * lc    );
        qf[ks][1] = *(const uint32_t*)(qb + (size_t)row1 * DK + ks * 16 + 2 * lc    );
        qf[ks][2] = *(const uint32_t*)(qb + (size_t)row0 * DK + ks * 16 + 2 * lc + 8);
        qf[ks][3] = *(const uint32_t*)(qb + (size_t)row1 * DK + ks * 16 + 2 * lc + 8);
    }

    float o[8][4];
    #pragma unroll
    for (int nt = 0; nt < 8; nt++)
        #pragma unroll
        for (int i = 0; i < 4; i++) o[nt][i] = 0.f;

    float m0 = -INFINITY, m1 = -INFINITY, l0 = 0.f, l1 = 0.f;

    uint32_t sK = smem_u32(ks_);
    uint32_t sV = smem_u32(vs_);

#define LOADKV(st, tile) do {                                                       \
        _Pragma("unroll")                                                           \
        for (int l = 0; l < 2; l++) {                                               \
            int fid = tid + l * 256;                                                \
            int r = fid >> 3, c8 = fid & 7;                                         \
            cp_async16(sK + (uint32_t)((st) * KTSZ + r * KSTH + c8 * 8) * 2,        \
                       kb + ((size_t)(tile) * 64 + r) * DK + c8 * 8);               \
            cp_async16(sV + (uint32_t)((st) * KTSZ + r * KSTH + c8 * 8) * 2,        \
                       vb + ((size_t)(tile) * 64 + r) * DK + c8 * 8);               \
        }                                                                           \
        asm volatile("cp.async.commit_group;");                                     \
    } while (0)

    LOADKV(0, 0);

    for (int t = 0; t < NKT; t++) {
        int st = t & 1;
        __syncthreads();
        if (t + 1 < NKT) {
            LOADKV(st ^ 1, t + 1);
            asm volatile("cp.async.wait_group 1;");
        } else {
            asm volatile("cp.async.wait_group 0;");
        }
        __syncthreads();

        // ---- S = Q @ K^T ----
        float c[8][4];
        #pragma unroll
        for (int nt = 0; nt < 8; nt++)
            #pragma unroll
            for (int i = 0; i < 4; i++) c[nt][i] = 0.f;

        uint32_t kS = sK + (uint32_t)(st * KTSZ) * 2;
        #pragma unroll
        for (int ks = 0; ks < 4; ks++) {
            #pragma unroll
            for (int nb = 0; nb < 4; nb++) {
                uint32_t addr = kS + (uint32_t)(((nb * 16 + b_row) * KSTH)
                                                 + ks * 16 + b_kof) * 2;
                uint32_t r0, r1, r2, r3;
                ldsm_x4(r0, r1, r2, r3, addr);
                uint32_t bf0[2] = {r0, r1};
                uint32_t bf1[2] = {r2, r3};
                mma_f16(c[nb * 2    ], qf[ks], bf0);
                mma_f16(c[nb * 2 + 1], qf[ks], bf1);
            }
        }

        // ---- mask + scale + row max (shfl-only) ----
        uint32_t mwA0 = mb[(size_t)grow0 * NWORDS + t * 2    ];
        uint32_t mwA1 = mb[(size_t)grow0 * NWORDS + t * 2 + 1];
        uint32_t mwB0 = mb[(size_t)grow1 * NWORDS + t * 2    ];
        uint32_t mwB1 = mb[(size_t)grow1 * NWORDS + t * 2 + 1];
        float mx0 = -INFINITY, mx1 = -INFINITY;
        #pragma unroll
        for (int nt = 0; nt < 8; nt++) {
            uint32_t wA = (nt < 4) ? mwA0 : mwA1;
            uint32_t wB = (nt < 4) ? mwB0 : mwB1;
            int j = (nt * 8 + 2 * lc) & 31;
            c[nt][0] = ((wA >> j)       & 1u) ? c[nt][0] * 0.125f : -1e9f;
            c[nt][1] = ((wA >> (j + 1)) & 1u) ? c[nt][1] * 0.125f : -1e9f;
            c[nt][2] = ((wB >> j)       & 1u) ? c[nt][2] * 0.125f : -1e9f;
            c[nt][3] = ((wB >> (j + 1)) & 1u) ? c[nt][3] * 0.125f : -1e9f;
            mx0 = fmaxf(mx0, fmaxf(c[nt][0], c[nt][1]));
            mx1 = fmaxf(mx1, fmaxf(c[nt][2], c[nt][3]));
        }
        mx0 = fmaxf(mx0, __shfl_xor_sync(0xffffffffu, mx0, 1));
        mx0 = fmaxf(mx0, __shfl_xor_sync(0xffffffffu, mx0, 2));
        mx1 = fmaxf(mx1, __shfl_xor_sync(0xffffffffu, mx1, 1));
        mx1 = fmaxf(mx1, __shfl_xor_sync(0xffffffffu, mx1, 2));

        float mn0 = fmaxf(m0, mx0);
        float mn1 = fmaxf(m1, mx1);
        float a0 = __expf(m0 - mn0);
        float a1 = __expf(m1 - mn1);
        m0 = mn0; m1 = mn1;

        // ---- exp, fp16 P store, row sums ----
        float s0 = 0.f, s1 = 0.f;
        #pragma unroll
        for (int nt = 0; nt < 8; nt++) {
            int col = nt * 8 + 2 * lc;
            float p00 = __expf(c[nt][0] - mn0);
            float p01 = __expf(c[nt][1] - mn0);
            float p10 = __expf(c[nt][2] - mn1);
            float p11 = __expf(c[nt][3] - mn1);
            s0 += p00 + p01;
            s1 += p10 + p11;
            *(__half2*)(psw + lr       * PSTH + col) = __floats2half2_rn(p00, p01);
            *(__half2*)(psw + (lr + 8) * PSTH + col) = __floats2half2_rn(p10, p11);
        }
        s0 += __shfl_xor_sync(0xffffffffu, s0, 1);
        s0 += __shfl_xor_sync(0xffffffffu, s0, 2);
        s1 += __shfl_xor_sync(0xffffffffu, s1, 1);
        s1 += __shfl_xor_sync(0xffffffffu, s1, 2);
        l0 = l0 * a0 + s0;
        l1 = l1 * a1 + s1;
        __syncwarp();

        // ---- rescale O, O += P @ V ----
        #pragma unroll
        for (int nt = 0; nt < 8; nt++) {
            o[nt][0] *= a0; o[nt][1] *= a0;
            o[nt][2] *= a1; o[nt][3] *= a1;
        }
        uint32_t vbase = sV + (uint32_t)(st * KTSZ) * 2;
        #pragma unroll
        for (int ks = 0; ks < 4; ks++) {
            uint32_t af[4];
            uint32_t paddr = sP + (uint32_t)((a_row * PSTH) + ks * 16 + a_kof) * 2;
            ldsm_x4(af[0], af[1], af[2], af[3], paddr);
            #pragma unroll
            for (int np = 0; np < 4; np++) {
                uint32_t addr = vbase
                    + (uint32_t)((ks * 16 + (lane & 15)) * KSTH) * 2
                    + (uint32_t)(np * 16 + ((lane >> 4) << 3)) * 2;
                uint32_t b0, b1, b2, b3;
                ldsm_x4_t(b0, b1, b2, b3, addr);
                uint32_t bf0[2] = {b0, b1};
                uint32_t bf1[2] = {b2, b3};
                mma_f16(o[np * 2    ], af, bf0);
                mma_f16(o[np * 2 + 1], af, bf1);
            }
        }
    }

    float inv0 = 1.f / l0, inv1 = 1.f / l1;
    #pragma unroll
    for (int nt = 0; nt < 8; nt++) {
        int col = h * 64 + nt * 8 + 2 * lc;
        *(__half2*)(ctx + ((size_t)b * SEQ + grow0) * DMODEL + col) =
            __floats2half2_rn(o[nt][0] * inv0, o[nt][1] * inv0);
        *(__half2*)(ctx + ((size_t)b * SEQ + grow1) * DMODEL + col) =
            __floats2half2_rn(o[nt][2] * inv1, o[nt][3] * inv1);
    }
#undef LOADKV
}

// ---------------- new_memory ----------------
__global__ __launch_bounds__(1024) void mem_partial_kernel(
    const float* __restrict__ xo, float* __restrict__ part)
{
    int b = blockIdx.x, cz = blockIdx.y, d = threadIdx.x;
    const float* base = xo + ((size_t)b * SEQ + cz * 128) * DMODEL + d;
    float s = 0.f;
    #pragma unroll 4
    for (int i = 0; i < 128; i++) s += base[(size_t)i * DMODEL];
    part[((size_t)b * 16 + cz) * DMODEL + d] = s;
}

__global__ __launch_bounds__(1024) void mem_final_kernel(
    const float* __restrict__ part, float* __restrict__ memout)
{
    int b = blockIdx.x, d = threadIdx.x;
    float s = 0.f;
    #pragma unroll
    for (int i = 0; i < 16; i++) s += part[((size_t)b * 16 + i) * DMODEL + d];
    float vv = s * (1.f / SEQ);
    #pragma unroll
    for (int m = 0; m < MEMT; m++)
        memout[((size_t)b * MEMT + m) * DMODEL + d] = vv;
}

// ---------------- launch ----------------
extern "C" void kernel_launch(void* const* d_in, const int* in_sizes, int n_in,
                              void* d_out, int out_size)
{
    const float* x    = (const float*)d_in[0];
    const int*   mask = (const int*)  d_in[1];
    const float* mem  = (const float*)d_in[2];
    const float* wq   = (const float*)d_in[3];
    const float* wk   = (const float*)d_in[4];
    const float* wv   = (const float*)d_in[5];
    const float* wo   = (const float*)d_in[6];
    const float* ln1a = (const float*)d_in[7];
    const float* ln1b = (const float*)d_in[8];
    const float* ln2a = (const float*)d_in[9];
    const float* ln2b = (const float*)d_in[10];
    const float* fw1  = (const float*)d_in[11];
    const float* fb1  = (const float*)d_in[12];
    const float* fw2  = (const float*)d_in[13];
    const float* fb2  = (const float*)d_in[14];
    float* out = (float*)d_out;
    float* out_mem = out + (size_t)ROWS * DMODEL;

    void* p;
    __half *xn, *q, *k, *v, *ctx, *xn2, *h1;
    float *x1, *part;
    __half *wqkvt, *wot, *fw1t, *fw2t;
    uint32_t* mb;
    cudaGetSymbolAddress(&p, g_xn);  xn  = (__half*)p;
    cudaGetSymbolAddress(&p, g_q);   q   = (__half*)p;
    cudaGetSymbolAddress(&p, g_k);   k   = (__half*)p;
    cudaGetSymbolAddress(&p, g_v);   v   = (__half*)p;
    cudaGetSymbolAddress(&p, g_ctx); ctx = (__half*)p;
    cudaGetSymbolAddress(&p, g_x1);  x1  = (float*)p;
    cudaGetSymbolAddress(&p, g_xn2); xn2 = (__half*)p;
    cudaGetSymbolAddress(&p, g_h1);  h1  = (__half*)p;
    cudaGetSymbolAddress(&p, g_part);part= (float*)p;
    cudaGetSymbolAddress(&p, g_mb);  mb  = (uint32_t*)p;
    cudaGetSymbolAddress(&p, g_wqkv);wqkvt=(__half*)p;
    cudaGetSymbolAddress(&p, g_wo);  wot = (__half*)p;
    cudaGetSymbolAddress(&p, g_fw1); fw1t= (__half*)p;
    cudaGetSymbolAddress(&p, g_fw2); fw2t= (__half*)p;

    cudaFuncSetAttribute(gemm_tc<EPI_QKV>,       cudaFuncAttributeMaxDynamicSharedMemorySize, GEMM_SMEM_BYTES);
    cudaFuncSetAttribute(gemm_tc<EPI_RESID>,     cudaFuncAttributeMaxDynamicSharedMemorySize, GEMM_SMEM_BYTES);
    cudaFuncSetAttribute(gemm_tc<EPI_BIAS_RELU>, cudaFuncAttributeMaxDynamicSharedMemorySize, GEMM_SMEM_BYTES);
    cudaFuncSetAttribute(gemm_tc<EPI_BIAS_RESID>,cudaFuncAttributeMaxDynamicSharedMemorySize, GEMM_SMEM_BYTES);
    cudaFuncSetAttribute(attn_tc, cudaFuncAttributeMaxDynamicSharedMemorySize, ATTN_SMEM_BYTES);

    dim3 tb(32, 8);
    transpose_half<<<dim3(DMODEL/32, DMODEL/32), tb>>>(wq,  wqkvt,                   DMODEL, DMODEL);
    transpose_half<<<dim3(DMODEL/32, DMODEL/32), tb>>>(wk,  wqkvt + DMODEL*DMODEL,   DMODEL, DMODEL);
    transpose_half<<<dim3(DMODEL/32, DMODEL/32), tb>>>(wv,  wqkvt + 2*DMODEL*DMODEL, DMODEL, DMODEL);
    transpose_half<<<dim3(DMODEL/32, DMODEL/32), tb>>>(wo,  wot,  DMODEL, DMODEL);
    transpose_half<<<dim3(DFF/32,    DMODEL/32), tb>>>(fw1, fw1t, DMODEL, DFF);
    transpose_half<<<dim3(DMODEL/32, DFF/32),    tb>>>(fw2, fw2t, DFF, DMODEL);

    ln_kernel<<<ROWS, 256>>>(x, ln1a, ln1b, xn);
    maskbits_kernel<<<SEQ, NWORDS>>>(mask, mb);
    padclear_kernel<<<BATCH * NHEADS, 256>>>(k, v);

    gemm_tc<EPI_QKV><<<dim3(3*DMODEL/BN, ROWS/BM), 256, GEMM_SMEM_BYTES>>>(
        xn, wqkvt, q, nullptr, nullptr, k, v, ROWS, 3*DMODEL, DMODEL);

    memproj_kernel<<<MEMT, 1024>>>(mem, wk, wv, k, v);

    attn_tc<<<dim3(SEQ/128, BATCH*NHEADS), 256, ATTN_SMEM_BYTES>>>(q, k, v, mb, ctx);

    gemm_tc<EPI_RESID><<<dim3(DMODEL/BN, ROWS/BM), 256, GEMM_SMEM_BYTES>>>(
        ctx, wot, x1, nullptr, x, nullptr, nullptr, ROWS, DMODEL, DMODEL);

    ln_kernel<<<ROWS, 256>>>(x1, ln2a, ln2b, xn2);

    gemm_tc<EPI_BIAS_RELU><<<dim3(DFF/BN, ROWS/BM), 256, GEMM_SMEM_BYTES>>>(
        xn2, fw1t, h1, fb1, nullptr, nullptr, nullptr, ROWS, DFF, DMODEL);
    gemm_tc<EPI_BIAS_RESID><<<dim3(DMODEL/BN, ROWS/BM), 256, GEMM_SMEM_BYTES>>>(
        h1, fw2t, out, fb2, x1, nullptr, nullptr, ROWS, DMODEL, DFF);

    mem_partial_kernel<<<dim3(BATCH, 16), 1024>>>(out, part);
    mem_final_kernel<<<BATCH, 1024>>>(part, out_mem);
}

// round 12
// speedup vs baseline: 10.8456x; 1.0171x over previous
#include <cuda_runtime.h>
#include <cuda_fp16.h>
#include <math.h>
#include <stdint.h>

// ---------------- problem constants ----------------
#define BATCH 4
#define SEQ   2048
#define DMODEL 1024
#define NHEADS 16
#define DK    64
#define MEMT  32
#define TTOT  (SEQ + MEMT)
#define T_PAD 2112
#define NKT   33
#define DFF   4096
#define ROWS  (BATCH * SEQ)
#define NWORDS 66

// ---------------- device scratch ----------------
__device__ __half g_xn [ROWS * DMODEL];
__device__ __half g_q  [BATCH * NHEADS * SEQ   * DK];
__device__ __half g_k  [BATCH * NHEADS * T_PAD * DK];
__device__ __half g_v  [BATCH * NHEADS * T_PAD * DK];
__device__ __half g_ctx[ROWS * DMODEL];
__device__ float  g_x1 [ROWS * DMODEL];
__device__ __half g_xn2[ROWS * DMODEL];
__device__ __half g_h1 [ROWS * DFF];
__device__ float  g_part[BATCH * 16 * DMODEL];
__device__ uint32_t g_mb[SEQ * NWORDS];
__device__ __half g_wqkv[3 * DMODEL * DMODEL];
__device__ __half g_wo  [DMODEL * DMODEL];
__device__ __half g_fw1 [DFF * DMODEL];
__device__ __half g_fw2 [DMODEL * DFF];

// ---------------- helpers ----------------
__device__ __forceinline__ void cp_async16(uint32_t dst, const void* src) {
    asm volatile("cp.async.cg.shared.global [%0], [%1], 16;\n" :: "r"(dst), "l"(src));
}
__device__ __forceinline__ void mma_f16(float* c, const uint32_t* a, const uint32_t* b) {
    asm volatile(
        "mma.sync.aligned.m16n8k16.row.col.f32.f16.f16.f32 "
        "{%0,%1,%2,%3},{%4,%5,%6,%7},{%8,%9},{%0,%1,%2,%3};"
        : "+f"(c[0]), "+f"(c[1]), "+f"(c[2]), "+f"(c[3])
        : "r"(a[0]), "r"(a[1]), "r"(a[2]), "r"(a[3]), "r"(b[0]), "r"(b[1]));
}
__device__ __forceinline__ void ldsm_x4(uint32_t& r0, uint32_t& r1, uint32_t& r2, uint32_t& r3, uint32_t addr) {
    asm volatile("ldmatrix.sync.aligned.m8n8.x4.shared.b16 {%0,%1,%2,%3}, [%4];"
                 : "=r"(r0), "=r"(r1), "=r"(r2), "=r"(r3) : "r"(addr));
}
__device__ __forceinline__ void ldsm_x4_t(uint32_t& r0, uint32_t& r1, uint32_t& r2, uint32_t& r3, uint32_t addr) {
    asm volatile("ldmatrix.sync.aligned.m8n8.x4.trans.shared.b16 {%0,%1,%2,%3}, [%4];"
                 : "=r"(r0), "=r"(r1), "=r"(r2), "=r"(r3) : "r"(addr));
}
__device__ __forceinline__ uint32_t smem_u32(const void* p) {
    return (uint32_t)__cvta_generic_to_shared(p);
}

// ---------------- merged weight transpose + fp16 (single launch) ----------------
// tile ranges: [0,3072) wq/wk/wv -> g_wqkv, [3072,4096) wo,
//              [4096,8192) fw1 (K=1024,N=4096), [8192,12288) fw2 (K=4096,N=1024)
__global__ __launch_bounds__(256) void transpose_all(
    const float* __restrict__ wq, const float* __restrict__ wk,
    const float* __restrict__ wv, const float* __restrict__ wo,
    const float* __restrict__ fw1, const float* __restrict__ fw2,
    __half* __restrict__ dwqkv, __half* __restrict__ dwo,
    __half* __restrict__ dfw1, __half* __restrict__ dfw2)
{
    __shared__ float t[32][33];
    int tb = blockIdx.x;
    const float* src; __half* dst; int K, N, lt;
    if (tb < 3072) {
        int w = tb >> 10; lt = tb & 1023;
        src = (w == 0) ? wq : (w == 1) ? wk : wv;
        dst = dwqkv + (size_t)w * DMODEL * DMODEL;
        K = DMODEL; N = DMODEL;
    } else if (tb < 4096) {
        src = wo;  dst = dwo;  lt = tb - 3072; K = DMODEL; N = DMODEL;
    } else if (tb < 8192) {
        src = fw1; dst = dfw1; lt = tb - 4096; K = DMODEL; N = DFF;
    } else {
        src = fw2; dst = dfw2; lt = tb - 8192; K = DFF; N = DMODEL;
    }
    int ntn = N >> 5;
    int n0 = (lt % ntn) * 32, k0 = (lt / ntn) * 32;
    int tx = threadIdx.x, ty = threadIdx.y;
    #pragma unroll
    for (int i = 0; i < 4; i++)
        t[ty + 8*i][tx] = src[(size_t)(k0 + ty + 8*i) * N + n0 + tx];
    __syncthreads();
    #pragma unroll
    for (int i = 0; i < 4; i++)
        dst[(size_t)(n0 + ty + 8*i) * K + k0 + tx] = __float2half_rn(t[tx][ty + 8*i]);
}

// ---------------- layer norm (ddof=1); fp16 output ----------------
__global__ __launch_bounds__(256) void ln_kernel(
    const float* __restrict__ x, const float* __restrict__ alpha,
    const float* __restrict__ bias, __half* __restrict__ out)
{
    int row = blockIdx.x;
    int tid = threadIdx.x;
    const float4* xr = (const float4*)(x + (size_t)row * DMODEL);
    float4 v = xr[tid];
    float s  = v.x + v.y + v.z + v.w;
    float ss = v.x*v.x + v.y*v.y + v.z*v.z + v.w*v.w;
    #pragma unroll
    for (int off = 16; off > 0; off >>= 1) {
        s  += __shfl_xor_sync(0xffffffffu, s,  off);
        ss += __shfl_xor_sync(0xffffffffu, ss, off);
    }
    __shared__ float rs[8], rss[8];
    int wid = tid >> 5, lane = tid & 31;
    if (lane == 0) { rs[wid] = s; rss[wid] = ss; }
    __syncthreads();
    float S = 0.f, SS = 0.f;
    #pragma unroll
    for (int w = 0; w < 8; w++) { S += rs[w]; SS += rss[w]; }
    float mean = S * (1.f / DMODEL);
    float var  = (SS - (float)DMODEL * mean * mean) * (1.f / (DMODEL - 1));
    float inv  = 1.f / (sqrtf(fmaxf(var, 0.f)) + 1e-6f);
    float4 a  = ((const float4*)alpha)[tid];
    float4 bb = ((const float4*)bias)[tid];
    __half2* o2 = (__half2*)(out + (size_t)row * DMODEL) + tid * 2;
    o2[0] = __floats2half2_rn(a.x * (v.x - mean) * inv + bb.x,
                              a.y * (v.y - mean) * inv + bb.y);
    o2[1] = __floats2half2_rn(a.z * (v.z - mean) * inv + bb.z,
                              a.w * (v.w - mean) * inv + bb.w);
}

// ---------------- fp16 mma GEMM, 3-stage pipeline, 1 barrier/iter ----------------
#define EPI_QKV        0
#define EPI_RESID      3
#define EPI_BIAS_RELU  4
#define EPI_BIAS_RESID 5

#define BM 128
#define BN 128
#define BK 64
#define STH 72
#define TSZ (128 * STH)
#define NSTG 3
#define GEMM_SMEM_BYTES (NSTG * 2 * TSZ * 2)   // 110592

template<int EPI>
__global__ __launch_bounds__(256, 2) void gemm_tc(
    const __half* __restrict__ A, const __half* __restrict__ W,
    void* __restrict__ Cp, const float* __restrict__ bias,
    const float* __restrict__ R, __half* __restrict__ C2, __half* __restrict__ C3,
    int M, int N, int K)
{
    extern __shared__ __half sm[];
    __half* As = sm;
    __half* Bs = sm + NSTG * TSZ;

    int tid  = threadIdx.x;
    int warp = tid >> 5, lane = tid & 31;
    int wm = warp & 1;
    int wn = warp >> 1;
    int lr = lane >> 2;
    int lc = lane & 3;

    const __half* Abase = A + (size_t)blockIdx.y * BM * K;
    const __half* Wbase = W + (size_t)blockIdx.x * BN * K;

    uint32_t sA = smem_u32(As);
    uint32_t sB = smem_u32(Bs);

    int a_row = (lane & 7) + ((lane >> 3) & 1) * 8;
    int a_kof = (lane >> 4) * 8;
    int b_row = (lane & 7) + ((lane >> 4) & 1) * 8;
    int b_kof = ((lane >> 3) & 1) * 8;

    float acc[4][4][4];
    #pragma unroll
    for (int mt = 0; mt < 4; mt++)
        #pragma unroll
        for (int nt = 0; nt < 4; nt++)
            #pragma unroll
            for (int i = 0; i < 4; i++) acc[mt][nt][i] = 0.f;

#define LOAD_STAGE(st, kt) do {                                                   \
        _Pragma("unroll")                                                         \
        for (int l = 0; l < 4; l++) {                                             \
            int fid = tid + l * 256;                                              \
            int r = fid >> 3, c8 = fid & 7;                                       \
            cp_async16(sA + (uint32_t)((st) * TSZ + r * STH + c8 * 8) * 2,        \
                       Abase + (size_t)r * K + (size_t)(kt) * BK + c8 * 8);       \
        }                                                                         \
        _Pragma("unroll")                                                         \
        for (int l = 0; l < 4; l++) {                                             \
            int fid = tid + l * 256;                                              \
            int r = fid >> 3, c8 = fid & 7;                                       \
            cp_async16(sB + (uint32_t)((st) * TSZ + r * STH + c8 * 8) * 2,        \
                       Wbase + (size_t)r * K + (size_t)(kt) * BK + c8 * 8);       \
        }                                                                         \
        asm volatile("cp.async.commit_group;");                                   \
    } while (0)

    int NT = K / BK;
    LOAD_STAGE(0, 0);
    LOAD_STAGE(1, 1);

    for (int kt = 0; kt < NT; kt++) {
        int st = kt - (kt / NSTG) * NSTG;
        asm volatile("cp.async.wait_group 1;");
        __syncthreads();   // single barrier: all loads for kt visible; all warps done with kt-1
        if (kt + 2 < NT) {
            int sl = st + 2; if (sl >= NSTG) sl -= NSTG;
            LOAD_STAGE(sl, kt + 2);
        } else {
            asm volatile("cp.async.commit_group;");
        }

        uint32_t aS = sA + (uint32_t)(st * TSZ) * 2;
        uint32_t bS = sB + (uint32_t)(st * TSZ) * 2;

        #pragma unroll
        for (int ks = 0; ks < 4; ks++) {
            uint32_t af[4][4], bf[4][2];
            #pragma unroll
            for (int mt = 0; mt < 4; mt++) {
                uint32_t addr = aS + (uint32_t)(((wm * 64 + mt * 16 + a_row) * STH)
                                                 + ks * 16 + a_kof) * 2;
                ldsm_x4(af[mt][0], af[mt][1], af[mt][2], af[mt][3], addr);
            }
            #pragma unroll
            for (int nb = 0; nb < 2; nb++) {
                uint32_t addr = bS + (uint32_t)(((wn * 32 + nb * 16 + b_row) * STH)
                                                 + ks * 16 + b_kof) * 2;
                uint32_t r0, r1, r2, r3;
                ldsm_x4(r0, r1, r2, r3, addr);
                bf[nb * 2    ][0] = r0; bf[nb * 2    ][1] = r1;
                bf[nb * 2 + 1][0] = r2; bf[nb * 2 + 1][1] = r3;
            }
            #pragma unroll
            for (int mt = 0; mt < 4; mt++)
                #pragma unroll
                for (int nt = 0; nt < 4; nt++)
                    mma_f16(acc[mt][nt], af[mt], bf[nt]);
        }
        // no end-of-loop barrier: 3-stage ring + top barrier covers the WAR hazard
    }

    #pragma unroll
    for (int mt = 0; mt < 4; mt++) {
        #pragma unroll
        for (int rg = 0; rg < 2; rg++) {
            int r = blockIdx.y * BM + wm * 64 + mt * 16 + lr + rg * 8;
            #pragma unroll
            for (int nt = 0; nt < 4; nt++) {
                int c = blockIdx.x * BN + wn * 32 + nt * 8 + lc * 2;
                float v0 = acc[mt][nt][rg * 2 + 0];
                float v1 = acc[mt][nt][rg * 2 + 1];
                if (EPI == EPI_QKV) {
                    int sel = c >> 10, cc = c & 1023;
                    int b = r >> 11, s2 = r & 2047, h = cc >> 6, d = cc & 63;
                    __half2 o = __floats2half2_rn(v0, v1);
                    if (sel == 0)
                        *(__half2*)((__half*)Cp + ((((size_t)(b * NHEADS + h)) * SEQ + s2) * DK + d)) = o;
                    else if (sel == 1)
                        *(__half2*)(C2 + ((((size_t)(b * NHEADS + h)) * T_PAD + MEMT + s2) * DK + d)) = o;
                    else
                        *(__half2*)(C3 + ((((size_t)(b * NHEADS + h)) * T_PAD + MEMT + s2) * DK + d)) = o;
                } else if (EPI == EPI_RESID) {
                    float2 rr = *(const float2*)(R + (size_t)r * N + c);
                    *(float2*)((float*)Cp + (size_t)r * N + c) = make_float2(v0 + rr.x, v1 + rr.y);
                } else if (EPI == EPI_BIAS_RELU) {
                    float2 bb = *(const float2*)(bias + c);
                    *(__half2*)((__half*)Cp + (size_t)r * N + c) =
                        __floats2half2_rn(fmaxf(v0 + bb.x, 0.f), fmaxf(v1 + bb.y, 0.f));
                } else if (EPI == EPI_BIAS_RESID) {
                    float2 bb = *(const float2*)(bias + c);
                    float2 rr = *(const float2*)(R + (size_t)r * N + c);
                    *(float2*)((float*)Cp + (size_t)r * N + c) = make_float2(v0 + bb.x + rr.x, v1 + bb.y + rr.y);
                }
            }
        }
    }
#undef LOAD_STAGE
}

// ---------------- memory-token K/V projection (fp16 outputs) ----------------
__global__ __launch_bounds__(1024) void memproj_kernel(
    const float* __restrict__ mt, const float* __restrict__ wk,
    const float* __restrict__ wv, __half* __restrict__ kh, __half* __restrict__ vh)
{
    int m = blockIdx.x;
    int c = threadIdx.x;
    float ak = 0.f, av = 0.f;
    #pragma unroll 4
    for (int kk = 0; kk < DMODEL; kk++) {
        float xm = mt[(size_t)m * DMODEL + kk];
        ak = fmaf(xm, wk[(size_t)kk * DMODEL + c], ak);
        av = fmaf(xm, wv[(size_t)kk * DMODEL + c], av);
    }
    __half ah = __float2half_rn(ak), vh_ = __float2half_rn(av);
    int h = c >> 6, d = c & 63;
    #pragma unroll
    for (int b = 0; b < BATCH; b++) {
        size_t idx = (((size_t)(b * NHEADS + h)) * T_PAD + m) * DK + d;
        kh[idx] = ah;
        vh[idx] = vh_;
    }
}

__global__ __launch_bounds__(256) void padclear_kernel(__half* k, __half* v)
{
    int bh = blockIdx.x;
    size_t base = ((size_t)bh * T_PAD + TTOT) * DK / 2;
    uint32_t* k32 = (uint32_t*)k;
    uint32_t* v32 = (uint32_t*)v;
    for (int i = threadIdx.x; i < (T_PAD - TTOT) * DK / 2; i += 256) {
        k32[base + i] = 0u;
        v32[base + i] = 0u;
    }
}

__global__ void maskbits_kernel(const int* __restrict__ mask, uint32_t* __restrict__ mb)
{
    int s = blockIdx.x;
    int w = threadIdx.x;
    uint32_t bits = 0;
    #pragma unroll 4
    for (int j = 0; j < 32; j++) {
        int t = w * 32 + j;
        if (t < TTOT && mask[(size_t)s * TTOT + t] != 0) bits |= (1u << j);
    }
    mb[(size_t)s * NWORDS + w] = bits;
}

// ---------------- fp16 flash attention: warp-owned rows, 1 barrier/tile ----------------
#define KSTH 72
#define KTSZ (64 * KSTH)
#define PSTH 72
#define ATTN_SMEM_BYTES ((2*KTSZ + 2*KTSZ + 8*16*PSTH) * 2)   // 55296

__global__ __launch_bounds__(256, 2) void attn_tc(
    const __half* __restrict__ q, const __half* __restrict__ k,
    const __half* __restrict__ v, const uint32_t* __restrict__ mb,
    __half* __restrict__ ctx)
{
    extern __shared__ __half smh[];
    __half* ks_ = smh;
    __half* vs_ = ks_ + 2 * KTSZ;
    __half* ps_ = vs_ + 2 * KTSZ;

    int tid  = threadIdx.x;
    int warp = tid >> 5, lane = tid & 31;
    int lr = lane >> 2, lc = lane & 3;
    int bh = blockIdx.y;
    int b  = bh >> 4, h = bh & 15;
    int q0 = blockIdx.x * 128;

    const __half* qb = q + (((size_t)bh) * SEQ + q0) * DK;
    const __half* kb = k + ((size_t)bh) * T_PAD * DK;
    const __half* vb = v + ((size_t)bh) * T_PAD * DK;

    int row0 = warp * 16 + lr;
    int row1 = row0 + 8;
    int grow0 = q0 + row0, grow1 = q0 + row1;
    __half* psw = ps_ + warp * 16 * PSTH;
    uint32_t sP = smem_u32(psw);

    int a_row = (lane & 7) + ((lane >> 3) & 1) * 8;
    int a_kof = (lane >> 4) * 8;
    int b_row = (lane & 7) + ((lane >> 4) & 1) * 8;
    int b_kof = ((lane >> 3) & 1) * 8;

    uint32_t qf[4][4];
    #pragma unroll
    for (int ks = 0; ks < 4; ks++) {
        qf[ks][0] = *(const uint32_t*)(qb + (size_t)row0 * DK + ks * 16 + 2 * lc    );
        qf[ks][1] = *(const uint32_t*)(qb + (size_t)row1 * DK + ks * 16 + 2 * lc    );
        qf[ks][2] = *(const uint32_t*)(qb + (size_t)row0 * DK + ks * 16 + 2 * lc + 8);
        qf[ks][3] = *(const uint32_t*)(qb + (size_t)row1 * DK + ks * 16 + 2 * lc + 8);
    }

    float o[8][4];
    #pragma unroll
    for (int nt = 0; nt < 8; nt++)
        #pragma unroll
        for (int i = 0; i < 4; i++) o[nt][i] = 0.f;

    float m0 = -INFINITY, m1 = -INFINITY, l0 = 0.f, l1 = 0.f;

    uint32_t sK = smem_u32(ks_);
    uint32_t sV = smem_u32(vs_);

#define LOADKV(st, tile) do {                                                       \
        _Pragma("unroll")                                                           \
        for (int l = 0; l < 2; l++) {                                               \
            int fid = tid + l * 256;                                                \
            int r = fid >> 3, c8 = fid & 7;                                         \
            cp_async16(sK + (uint32_t)((st) * KTSZ + r * KSTH + c8 * 8) * 2,        \
                       kb + ((size_t)(tile) * 64 + r) * DK + c8 * 8);               \
            cp_async16(sV + (uint32_t)((st) * KTSZ + r * KSTH + c8 * 8) * 2,        \
                       vb + ((size_t)(tile) * 64 + r) * DK + c8 * 8);               \
        }                                                                           \
        asm volatile("cp.async.commit_group;");                                     \
    } while (0)

    LOADKV(0, 0);

    for (int t = 0; t < NKT; t++) {
        int st = t & 1;
        asm volatile("cp.async.wait_group 0;");   // own copies for tile t complete
        __syncthreads();                          // all threads' copies visible; all done with t-1
        if (t + 1 < NKT) LOADKV(st ^ 1, t + 1);   // overlaps compute below

        // ---- S = Q @ K^T ----
        float c[8][4];
        #pragma unroll
        for (int nt = 0; nt < 8; nt++)
            #pragma unroll
            for (int i = 0; i < 4; i++) c[nt][i] = 0.f;

        uint32_t kS = sK + (uint32_t)(st * KTSZ) * 2;
        #pragma unroll
        for (int ks = 0; ks < 4; ks++) {
            #pragma unroll
            for (int nb = 0; nb < 4; nb++) {
                uint32_t addr = kS + (uint32_t)(((nb * 16 + b_row) * KSTH)
                                                 + ks * 16 + b_kof) * 2;
                uint32_t r0, r1, r2, r3;
                ldsm_x4(r0, r1, r2, r3, addr);
                uint32_t bf0[2] = {r0, r1};
                uint32_t bf1[2] = {r2, r3};
                mma_f16(c[nb * 2    ], qf[ks], bf0);
                mma_f16(c[nb * 2 + 1], qf[ks], bf1);
            }
        }

        // ---- mask + scale + row max (shfl-only) ----
        uint32_t mwA0 = mb[(size_t)grow0 * NWORDS + t * 2    ];
        uint32_t mwA1 = mb[(size_t)grow0 * NWORDS + t * 2 + 1];
        uint32_t mwB0 = mb[(size_t)grow1 * NWORDS + t * 2    ];
        uint32_t mwB1 = mb[(size_t)grow1 * NWORDS + t * 2 + 1];
        float mx0 = -INFINITY, mx1 = -INFINITY;
        #pragma unroll
        for (int nt = 0; nt < 8; nt++) {
            uint32_t wA = (nt < 4) ? mwA0 : mwA1;
            uint32_t wB = (nt < 4) ? mwB0 : mwB1;
            int j = (nt * 8 + 2 * lc) & 31;
            c[nt][0] = ((wA >> j)       & 1u) ? c[nt][0] * 0.125f : -1e9f;
            c[nt][1] = ((wA >> (j + 1)) & 1u) ? c[nt][1] * 0.125f : -1e9f;
            c[nt][2] = ((wB >> j)       & 1u) ? c[nt][2] * 0.125f : -1e9f;
            c[nt][3] = ((wB >> (j + 1)) & 1u) ? c[nt][3] * 0.125f : -1e9f;
            mx0 = fmaxf(mx0, fmaxf(c[nt][0], c[nt][1]));
            mx1 = fmaxf(mx1, fmaxf(c[nt][2], c[nt][3]));
        }
        mx0 = fmaxf(mx0, __shfl_xor_sync(0xffffffffu, mx0, 1));
        mx0 = fmaxf(mx0, __shfl_xor_sync(0xffffffffu, mx0, 2));
        mx1 = fmaxf(mx1, __shfl_xor_sync(0xffffffffu, mx1, 1));
        mx1 = fmaxf(mx1, __shfl_xor_sync(0xffffffffu, mx1, 2));

        float mn0 = fmaxf(m0, mx0);
        float mn1 = fmaxf(m1, mx1);
        float a0 = __expf(m0 - mn0);
        float a1 = __expf(m1 - mn1);
        m0 = mn0; m1 = mn1;

        // ---- exp, fp16 P store, row sums ----
        float s0 = 0.f, s1 = 0.f;
        #pragma unroll
        for (int nt = 0; nt < 8; nt++) {
            int col = nt * 8 + 2 * lc;
            float p00 = __expf(c[nt][0] - mn0);
            float p01 = __expf(c[nt][1] - mn0);
            float p10 = __expf(c[nt][2] - mn1);
            float p11 = __expf(c[nt][3] - mn1);
            s0 += p00 + p01;
            s1 += p10 + p11;
            *(__half2*)(psw + lr       * PSTH + col) = __floats2half2_rn(p00, p01);
            *(__half2*)(psw + (lr + 8) * PSTH + col) = __floats2half2_rn(p10, p11);
        }
        s0 += __shfl_xor_sync(0xffffffffu, s0, 1);
        s0 += __shfl_xor_sync(0xffffffffu, s0, 2);
        s1 += __shfl_xor_sync(0xffffffffu, s1, 1);
        s1 += __shfl_xor_sync(0xffffffffu, s1, 2);
        l0 = l0 * a0 + s0;
        l1 = l1 * a1 + s1;
        __syncwarp();

        // ---- rescale O, O += P @ V ----
        #pragma unroll
        for (int nt = 0; nt < 8; nt++) {
            o[nt][0] *= a0; o[nt][1] *= a0;
            o[nt][2] *= a1; o[nt][3] *= a1;
        }
        uint32_t vbase = sV + (uint32_t)(st * KTSZ) * 2;
        #pragma unroll
        for (int ks = 0; ks < 4; ks++) {
            uint32_t af[4];
            uint32_t paddr = sP + (uint32_t)((a_row * PSTH) + ks * 16 + a_kof) * 2;
            ldsm_x4(af[0], af[1], af[2], af[3], paddr);
            #pragma unroll
            for (int np = 0; np < 4; np++) {
                uint32_t addr = vbase
                    + (uint32_t)((ks * 16 + (lane & 15)) * KSTH) * 2
                    + (uint32_t)(np * 16 + ((lane >> 4) << 3)) * 2;
                uint32_t b0, b1, b2, b3;
                ldsm_x4_t(b0, b1, b2, b3, addr);
                uint32_t bf0[2] = {b0, b1};
                uint32_t bf1[2] = {b2, b3};
                mma_f16(o[np * 2    ], af, bf0);
                mma_f16(o[np * 2 + 1], af, bf1);
            }
        }
    }

    float inv0 = 1.f / l0, inv1 = 1.f / l1;
    #pragma unroll
    for (int nt = 0; nt < 8; nt++) {
        int col = h * 64 + nt * 8 + 2 * lc;
        *(__half2*)(ctx + ((size_t)b * SEQ + grow0) * DMODEL + col) =
            __floats2half2_rn(o[nt][0] * inv0, o[nt][1] * inv0);
        *(__half2*)(ctx + ((size_t)b * SEQ + grow1) * DMODEL + col) =
            __floats2half2_rn(o[nt][2] * inv1, o[nt][3] * inv1);
    }
#undef LOADKV
}

// ---------------- new_memory ----------------
__global__ __launch_bounds__(1024) void mem_partial_kernel(
    const float* __restrict__ xo, float* __restrict__ part)
{
    int b = blockIdx.x, cz = blockIdx.y, d = threadIdx.x;
    const float* base = xo + ((size_t)b * SEQ + cz * 128) * DMODEL + d;
    float s = 0.f;
    #pragma unroll 4
    for (int i = 0; i < 128; i++) s += base[(size_t)i * DMODEL];
    part[((size_t)b * 16 + cz) * DMODEL + d] = s;
}

__global__ __launch_bounds__(1024) void mem_final_kernel(
    const float* __restrict__ part, float* __restrict__ memout)
{
    int b = blockIdx.x, d = threadIdx.x;
    float s = 0.f;
    #pragma unroll
    for (int i = 0; i < 16; i++) s += part[((size_t)b * 16 + i) * DMODEL + d];
    float vv = s * (1.f / SEQ);
    #pragma unroll
    for (int m = 0; m < MEMT; m++)
        memout[((size_t)b * MEMT + m) * DMODEL + d] = vv;
}

// ---------------- launch ----------------
extern "C" void kernel_launch(void* const* d_in, const int* in_sizes, int n_in,
                              void* d_out, int out_size)
{
    const float* x    = (const float*)d_in[0];
    const int*   mask = (const int*)  d_in[1];
    const float* mem  = (const float*)d_in[2];
    const float* wq   = (const float*)d_in[3];
    const float* wk   = (const float*)d_in[4];
    const float* wv   = (const float*)d_in[5];
    const float* wo   = (const float*)d_in[6];
    const float* ln1a = (const float*)d_in[7];
    const float* ln1b = (const float*)d_in[8];
    const float* ln2a = (const float*)d_in[9];
    const float* ln2b = (const float*)d_in[10];
    const float* fw1  = (const float*)d_in[11];
    const float* fb1  = (const float*)d_in[12];
    const float* fw2  = (const float*)d_in[13];
    const float* fb2  = (const float*)d_in[14];
    float* out = (float*)d_out;
    float* out_mem = out + (size_t)ROWS * DMODEL;

    void* p;
    __half *xn, *q, *k, *v, *ctx, *xn2, *h1;
    float *x1, *part;
    __half *wqkvt, *wot, *fw1t, *fw2t;
    uint32_t* mb;
    cudaGetSymbolAddress(&p, g_xn);  xn  = (__half*)p;
    cudaGetSymbolAddress(&p, g_q);   q   = (__half*)p;
    cudaGetSymbolAddress(&p, g_k);   k   = (__half*)p;
    cudaGetSymbolAddress(&p, g_v);   v   = (__half*)p;
    cudaGetSymbolAddress(&p, g_ctx); ctx = (__half*)p;
    cudaGetSymbolAddress(&p, g_x1);  x1  = (float*)p;
    cudaGetSymbolAddress(&p, g_xn2); xn2 = (__half*)p;
    cudaGetSymbolAddress(&p, g_h1);  h1  = (__half*)p;
    cudaGetSymbolAddress(&p, g_part);part= (float*)p;
    cudaGetSymbolAddress(&p, g_mb);  mb  = (uint32_t*)p;
    cudaGetSymbolAddress(&p, g_wqkv);wqkvt=(__half*)p;
    cudaGetSymbolAddress(&p, g_wo);  wot = (__half*)p;
    cudaGetSymbolAddress(&p, g_fw1); fw1t= (__half*)p;
    cudaGetSymbolAddress(&p, g_fw2); fw2t= (__half*)p;

    cudaFuncSetAttribute(gemm_tc<EPI_QKV>,       cudaFuncAttributeMaxDynamicSharedMemorySize, GEMM_SMEM_BYTES);
    cudaFuncSetAttribute(gemm_tc<EPI_RESID>,     cudaFuncAttributeMaxDynamicSharedMemorySize, GEMM_SMEM_BYTES);
    cudaFuncSetAttribute(gemm_tc<EPI_BIAS_RELU>, cudaFuncAttributeMaxDynamicSharedMemorySize, GEMM_SMEM_BYTES);
    cudaFuncSetAttribute(gemm_tc<EPI_BIAS_RESID>,cudaFuncAttributeMaxDynamicSharedMemorySize, GEMM_SMEM_BYTES);
    cudaFuncSetAttribute(attn_tc, cudaFuncAttributeMaxDynamicSharedMemorySize, ATTN_SMEM_BYTES);

    // launches 1-5 (small/independent), #6 = fused QKV GEMM so ncu (-s 5 -c 1) captures it
    ln_kernel<<<ROWS, 256>>>(x, ln1a, ln1b, xn);                       // 1
    maskbits_kernel<<<SEQ, NWORDS>>>(mask, mb);                        // 2
    padclear_kernel<<<BATCH * NHEADS, 256>>>(k, v);                    // 3
    memproj_kernel<<<MEMT, 1024>>>(mem, wk, wv, k, v);                 // 4 (uses raw fp32 weights)
    transpose_all<<<12288, dim3(32, 8)>>>(wq, wk, wv, wo, fw1, fw2,    // 5
                                          wqkvt, wot, fw1t, fw2t);

    gemm_tc<EPI_QKV><<<dim3(3*DMODEL/BN, ROWS/BM), 256, GEMM_SMEM_BYTES>>>(   // 6 <- profiled
        xn, wqkvt, q, nullptr, nullptr, k, v, ROWS, 3*DMODEL, DMODEL);

    attn_tc<<<dim3(SEQ/128, BATCH*NHEADS), 256, ATTN_SMEM_BYTES>>>(q, k, v, mb, ctx);

    gemm_tc<EPI_RESID><<<dim3(DMODEL/BN, ROWS/BM), 256, GEMM_SMEM_BYTES>>>(
        ctx, wot, x1, nullptr, x, nullptr, nullptr, ROWS, DMODEL, DMODEL);

    ln_kernel<<<ROWS, 256>>>(x1, ln2a, ln2b, xn2);

    gemm_tc<EPI_BIAS_RELU><<<dim3(DFF/BN, ROWS/BM), 256, GEMM_SMEM_BYTES>>>(
        xn2, fw1t, h1, fb1, nullptr, nullptr, nullptr, ROWS, DFF, DMODEL);
    gemm_tc<EPI_BIAS_RESID><<<dim3(DMODEL/BN, ROWS/BM), 256, GEMM_SMEM_BYTES>>>(
        h1, fw2t, out, fb2, x1, nullptr, nullptr, ROWS, DMODEL, DFF);

    mem_partial_kernel<<<dim3(BATCH, 16), 1024>>>(out, part);
    mem_final_kernel<<<BATCH, 1024>>>(part, out_mem);
}

// round 13
// speedup vs baseline: 11.8612x; 1.0936x over previous
#include <cuda_runtime.h>
#include <cuda_fp16.h>
#include <math.h>
#include <stdint.h>

// ---------------- problem constants ----------------
#define BATCH 4
#define SEQ   2048
#define DMODEL 1024
#define NHEADS 16
#define DK    64
#define MEMT  32
#define TTOT  (SEQ + MEMT)
#define T_PAD 2112
#define NKT   33
#define DFF   4096
#define ROWS  (BATCH * SEQ)
#define NWORDS 66

// ---------------- device scratch ----------------
__device__ __half g_xn [ROWS * DMODEL];
__device__ __half g_q  [BATCH * NHEADS * SEQ   * DK];
__device__ __half g_k  [BATCH * NHEADS * T_PAD * DK];
__device__ __half g_v  [BATCH * NHEADS * T_PAD * DK];
__device__ __half g_ctx[ROWS * DMODEL];
__device__ float  g_x1 [ROWS * DMODEL];
__device__ __half g_xn2[ROWS * DMODEL];
__device__ __half g_h1 [ROWS * DFF];
__device__ float  g_part[BATCH * 16 * DMODEL];
__device__ uint32_t g_mb[SEQ * NWORDS];
__device__ __half g_wqkv[3 * DMODEL * DMODEL];
__device__ __half g_wo  [DMODEL * DMODEL];
__device__ __half g_fw1 [DFF * DMODEL];
__device__ __half g_fw2 [DMODEL * DFF];
// memproj partials: [2 (k/v)][32 m][16 slice][1024 c]
__device__ float g_mpp[2 * MEMT * 16 * DMODEL];

// ---------------- helpers ----------------
__device__ __forceinline__ void cp_async16(uint32_t dst, const void* src) {
    asm volatile("cp.async.cg.shared.global [%0], [%1], 16;\n" :: "r"(dst), "l"(src));
}
__device__ __forceinline__ void mma_f16(float* c, const uint32_t* a, const uint32_t* b) {
    asm volatile(
        "mma.sync.aligned.m16n8k16.row.col.f32.f16.f16.f32 "
        "{%0,%1,%2,%3},{%4,%5,%6,%7},{%8,%9},{%0,%1,%2,%3};"
        : "+f"(c[0]), "+f"(c[1]), "+f"(c[2]), "+f"(c[3])
        : "r"(a[0]), "r"(a[1]), "r"(a[2]), "r"(a[3]), "r"(b[0]), "r"(b[1]));
}
__device__ __forceinline__ void ldsm_x4(uint32_t& r0, uint32_t& r1, uint32_t& r2, uint32_t& r3, uint32_t addr) {
    asm volatile("ldmatrix.sync.aligned.m8n8.x4.shared.b16 {%0,%1,%2,%3}, [%4];"
                 : "=r"(r0), "=r"(r1), "=r"(r2), "=r"(r3) : "r"(addr));
}
__device__ __forceinline__ void ldsm_x4_t(uint32_t& r0, uint32_t& r1, uint32_t& r2, uint32_t& r3, uint32_t addr) {
    asm volatile("ldmatrix.sync.aligned.m8n8.x4.trans.shared.b16 {%0,%1,%2,%3}, [%4];"
                 : "=r"(r0), "=r"(r1), "=r"(r2), "=r"(r3) : "r"(addr));
}
__device__ __forceinline__ uint32_t smem_u32(const void* p) {
    return (uint32_t)__cvta_generic_to_shared(p);
}

// ---------------- merged weight transpose + fp16 (single launch) ----------------
__global__ __launch_bounds__(256) void transpose_all(
    const float* __restrict__ wq, const float* __restrict__ wk,
    const float* __restrict__ wv, const float* __restrict__ wo,
    const float* __restrict__ fw1, const float* __restrict__ fw2,
    __half* __restrict__ dwqkv, __half* __restrict__ dwo,
    __half* __restrict__ dfw1, __half* __restrict__ dfw2)
{
    __shared__ float t[32][33];
    int tb = blockIdx.x;
    const float* src; __half* dst; int K, N, lt;
    if (tb < 3072) {
        int w = tb >> 10; lt = tb & 1023;
        src = (w == 0) ? wq : (w == 1) ? wk : wv;
        dst = dwqkv + (size_t)w * DMODEL * DMODEL;
        K = DMODEL; N = DMODEL;
    } else if (tb < 4096) {
        src = wo;  dst = dwo;  lt = tb - 3072; K = DMODEL; N = DMODEL;
    } else if (tb < 8192) {
        src = fw1; dst = dfw1; lt = tb - 4096; K = DMODEL; N = DFF;
    } else {
        src = fw2; dst = dfw2; lt = tb - 8192; K = DFF; N = DMODEL;
    }
    int ntn = N >> 5;
    int n0 = (lt % ntn) * 32, k0 = (lt / ntn) * 32;
    int tx = threadIdx.x, ty = threadIdx.y;
    #pragma unroll
    for (int i = 0; i < 4; i++)
        t[ty + 8*i][tx] = src[(size_t)(k0 + ty + 8*i) * N + n0 + tx];
    __syncthreads();
    #pragma unroll
    for (int i = 0; i < 4; i++)
        dst[(size_t)(n0 + ty + 8*i) * K + k0 + tx] = __float2half_rn(t[tx][ty + 8*i]);
}

// ---------------- layer norm (ddof=1); fp16 output ----------------
__global__ __launch_bounds__(256) void ln_kernel(
    const float* __restrict__ x, const float* __restrict__ alpha,
    const float* __restrict__ bias, __half* __restrict__ out)
{
    int row = blockIdx.x;
    int tid = threadIdx.x;
    const float4* xr = (const float4*)(x + (size_t)row * DMODEL);
    float4 v = xr[tid];
    float s  = v.x + v.y + v.z + v.w;
    float ss = v.x*v.x + v.y*v.y + v.z*v.z + v.w*v.w;
    #pragma unroll
    for (int off = 16; off > 0; off >>= 1) {
        s  += __shfl_xor_sync(0xffffffffu, s,  off);
        ss += __shfl_xor_sync(0xffffffffu, ss, off);
    }
    __shared__ float rs[8], rss[8];
    int wid = tid >> 5, lane = tid & 31;
    if (lane == 0) { rs[wid] = s; rss[wid] = ss; }
    __syncthreads();
    float S = 0.f, SS = 0.f;
    #pragma unroll
    for (int w = 0; w < 8; w++) { S += rs[w]; SS += rss[w]; }
    float mean = S * (1.f / DMODEL);
    float var  = (SS - (float)DMODEL * mean * mean) * (1.f / (DMODEL - 1));
    float inv  = 1.f / (sqrtf(fmaxf(var, 0.f)) + 1e-6f);
    float4 a  = ((const float4*)alpha)[tid];
    float4 bb = ((const float4*)bias)[tid];
    __half2* o2 = (__half2*)(out + (size_t)row * DMODEL) + tid * 2;
    o2[0] = __floats2half2_rn(a.x * (v.x - mean) * inv + bb.x,
                              a.y * (v.y - mean) * inv + bb.y);
    o2[1] = __floats2half2_rn(a.z * (v.z - mean) * inv + bb.z,
                              a.w * (v.w - mean) * inv + bb.w);
}

// ---------------- fp16 mma GEMM, 3-stage pipeline, 1 barrier/iter ----------------
#define EPI_QKV        0
#define EPI_RESID      3
#define EPI_BIAS_RELU  4
#define EPI_BIAS_RESID 5

#define BM 128
#define BN 128
#define BK 64
#define STH 72
#define TSZ (128 * STH)
#define NSTG 3
#define GEMM_SMEM_BYTES (NSTG * 2 * TSZ * 2)   // 110592

template<int EPI>
__global__ __launch_bounds__(256, 2) void gemm_tc(
    const __half* __restrict__ A, const __half* __restrict__ W,
    void* __restrict__ Cp, const float* __restrict__ bias,
    const float* __restrict__ R, __half* __restrict__ C2, __half* __restrict__ C3,
    int M, int N, int K)
{
    extern __shared__ __half sm[];
    __half* As = sm;
    __half* Bs = sm + NSTG * TSZ;

    int tid  = threadIdx.x;
    int warp = tid >> 5, lane = tid & 31;
    int wm = warp & 1;
    int wn = warp >> 1;
    int lr = lane >> 2;
    int lc = lane & 3;

    const __half* Abase = A + (size_t)blockIdx.y * BM * K;
    const __half* Wbase = W + (size_t)blockIdx.x * BN * K;

    uint32_t sA = smem_u32(As);
    uint32_t sB = smem_u32(Bs);

    int a_row = (lane & 7) + ((lane >> 3) & 1) * 8;
    int a_kof = (lane >> 4) * 8;
    int b_row = (lane & 7) + ((lane >> 4) & 1) * 8;
    int b_kof = ((lane >> 3) & 1) * 8;

    float acc[4][4][4];
    #pragma unroll
    for (int mt = 0; mt < 4; mt++)
        #pragma unroll
        for (int nt = 0; nt < 4; nt++)
            #pragma unroll
            for (int i = 0; i < 4; i++) acc[mt][nt][i] = 0.f;

#define LOAD_STAGE(st, kt) do {                                                   \
        _Pragma("unroll")                                                         \
        for (int l = 0; l < 4; l++) {                                             \
            int fid = tid + l * 256;                                              \
            int r = fid >> 3, c8 = fid & 7;                                       \
            cp_async16(sA + (uint32_t)((st) * TSZ + r * STH + c8 * 8) * 2,        \
                       Abase + (size_t)r * K + (size_t)(kt) * BK + c8 * 8);       \
        }                                                                         \
        _Pragma("unroll")                                                         \
        for (int l = 0; l < 4; l++) {                                             \
            int fid = tid + l * 256;                                              \
            int r = fid >> 3, c8 = fid & 7;                                       \
            cp_async16(sB + (uint32_t)((st) * TSZ + r * STH + c8 * 8) * 2,        \
                       Wbase + (size_t)r * K + (size_t)(kt) * BK + c8 * 8);       \
        }                                                                         \
        asm volatile("cp.async.commit_group;");                                   \
    } while (0)

    int NT = K / BK;
    LOAD_STAGE(0, 0);
    LOAD_STAGE(1, 1);

    for (int kt = 0; kt < NT; kt++) {
        int st = kt - (kt / NSTG) * NSTG;
        asm volatile("cp.async.wait_group 1;");
        __syncthreads();
        if (kt + 2 < NT) {
            int sl = st + 2; if (sl >= NSTG) sl -= NSTG;
            LOAD_STAGE(sl, kt + 2);
        } else {
            asm volatile("cp.async.commit_group;");
        }

        uint32_t aS = sA + (uint32_t)(st * TSZ) * 2;
        uint32_t bS = sB + (uint32_t)(st * TSZ) * 2;

        #pragma unroll
        for (int ks = 0; ks < 4; ks++) {
            uint32_t af[4][4], bf[4][2];
            #pragma unroll
            for (int mt = 0; mt < 4; mt++) {
                uint32_t addr = aS + (uint32_t)(((wm * 64 + mt * 16 + a_row) * STH)
                                                 + ks * 16 + a_kof) * 2;
                ldsm_x4(af[mt][0], af[mt][1], af[mt][2], af[mt][3], addr);
            }
            #pragma unroll
            for (int nb = 0; nb < 2; nb++) {
                uint32_t addr = bS + (uint32_t)(((wn * 32 + nb * 16 + b_row) * STH)
                                                 + ks * 16 + b_kof) * 2;
                uint32_t r0, r1, r2, r3;
                ldsm_x4(r0, r1, r2, r3, addr);
                bf[nb * 2    ][0] = r0; bf[nb * 2    ][1] = r1;
                bf[nb * 2 + 1][0] = r2; bf[nb * 2 + 1][1] = r3;
            }
            #pragma unroll
            for (int mt = 0; mt < 4; mt++)
                #pragma unroll
                for (int nt = 0; nt < 4; nt++)
                    mma_f16(acc[mt][nt], af[mt], bf[nt]);
        }
    }

    #pragma unroll
    for (int mt = 0; mt < 4; mt++) {
        #pragma unroll
        for (int rg = 0; rg < 2; rg++) {
            int r = blockIdx.y * BM + wm * 64 + mt * 16 + lr + rg * 8;
            #pragma unroll
            for (int nt = 0; nt < 4; nt++) {
                int c = blockIdx.x * BN + wn * 32 + nt * 8 + lc * 2;
                float v0 = acc[mt][nt][rg * 2 + 0];
                float v1 = acc[mt][nt][rg * 2 + 1];
                if (EPI == EPI_QKV) {
                    int sel = c >> 10, cc = c & 1023;
                    int b = r >> 11, s2 = r & 2047, h = cc >> 6, d = cc & 63;
                    __half2 o = __floats2half2_rn(v0, v1);
                    if (sel == 0)
                        *(__half2*)((__half*)Cp + ((((size_t)(b * NHEADS + h)) * SEQ + s2) * DK + d)) = o;
                    else if (sel == 1)
                        *(__half2*)(C2 + ((((size_t)(b * NHEADS + h)) * T_PAD + MEMT + s2) * DK + d)) = o;
                    else
                        *(__half2*)(C3 + ((((size_t)(b * NHEADS + h)) * T_PAD + MEMT + s2) * DK + d)) = o;
                } else if (EPI == EPI_RESID) {
                    float2 rr = *(const float2*)(R + (size_t)r * N + c);
                    *(float2*)((float*)Cp + (size_t)r * N + c) = make_float2(v0 + rr.x, v1 + rr.y);
                } else if (EPI == EPI_BIAS_RELU) {
                    float2 bb = *(const float2*)(bias + c);
                    *(__half2*)((__half*)Cp + (size_t)r * N + c) =
                        __floats2half2_rn(fmaxf(v0 + bb.x, 0.f), fmaxf(v1 + bb.y, 0.f));
                } else if (EPI == EPI_BIAS_RESID) {
                    float2 bb = *(const float2*)(bias + c);
                    float2 rr = *(const float2*)(R + (size_t)r * N + c);
                    *(float2*)((float*)Cp + (size_t)r * N + c) = make_float2(v0 + bb.x + rr.x, v1 + bb.y + rr.y);
                }
            }
        }
    }
#undef LOAD_STAGE
}

// ---------------- memory-token K/V projection: K-split two-stage ----------------
// stage 1: grid (MEMT, 16); block 1024; partial over 64-k slice
__global__ __launch_bounds__(1024) void memproj_part(
    const float* __restrict__ mt, const float* __restrict__ wk,
    const float* __restrict__ wv, float* __restrict__ pp)
{
    int m = blockIdx.x, sl = blockIdx.y;
    int c = threadIdx.x;
    int k0 = sl * 64;
    __shared__ float xs[64];
    if (c < 64) xs[c] = mt[(size_t)m * DMODEL + k0 + c];
    __syncthreads();
    float ak = 0.f, av = 0.f;
    #pragma unroll 8
    for (int kk = 0; kk < 64; kk++) {
        float xm = xs[kk];
        ak = fmaf(xm, wk[(size_t)(k0 + kk) * DMODEL + c], ak);
        av = fmaf(xm, wv[(size_t)(k0 + kk) * DMODEL + c], av);
    }
    pp[((size_t)m * 16 + sl) * DMODEL + c] = ak;
    pp[(size_t)MEMT * 16 * DMODEL + ((size_t)m * 16 + sl) * DMODEL + c] = av;
}

// stage 2: grid MEMT; block 1024; reduce 16 partials, broadcast to batches
__global__ __launch_bounds__(1024) void memproj_final(
    const float* __restrict__ pp, __half* __restrict__ kh, __half* __restrict__ vh)
{
    int m = blockIdx.x;
    int c = threadIdx.x;
    float ak = 0.f, av = 0.f;
    #pragma unroll
    for (int sl = 0; sl < 16; sl++) {
        ak += pp[((size_t)m * 16 + sl) * DMODEL + c];
        av += pp[(size_t)MEMT * 16 * DMODEL + ((size_t)m * 16 + sl) * DMODEL + c];
    }
    __half ah = __float2half_rn(ak), vh_ = __float2half_rn(av);
    int h = c >> 6, d = c & 63;
    #pragma unroll
    for (int b = 0; b < BATCH; b++) {
        size_t idx = (((size_t)(b * NHEADS + h)) * T_PAD + m) * DK + d;
        kh[idx] = ah;
        vh[idx] = vh_;
    }
}

__global__ __launch_bounds__(256) void padclear_kernel(__half* k, __half* v)
{
    int bh = blockIdx.x;
    size_t base = ((size_t)bh * T_PAD + TTOT) * DK / 2;
    uint32_t* k32 = (uint32_t*)k;
    uint32_t* v32 = (uint32_t*)v;
    for (int i = threadIdx.x; i < (T_PAD - TTOT) * DK / 2; i += 256) {
        k32[base + i] = 0u;
        v32[base + i] = 0u;
    }
}

__global__ void maskbits_kernel(const int* __restrict__ mask, uint32_t* __restrict__ mb)
{
    int s = blockIdx.x;
    int w = threadIdx.x;
    uint32_t bits = 0;
    #pragma unroll 4
    for (int j = 0; j < 32; j++) {
        int t = w * 32 + j;
        if (t < TTOT && mask[(size_t)s * TTOT + t] != 0) bits |= (1u << j);
    }
    mb[(size_t)s * NWORDS + w] = bits;
}

// ---------------- fp16 flash attention: warp-owned rows, 1 barrier/tile ----------------
#define KSTH 72
#define KTSZ (64 * KSTH)
#define PSTH 72
#define ATTN_SMEM_BYTES ((2*KTSZ + 2*KTSZ + 8*16*PSTH) * 2)   // 55296

__global__ __launch_bounds__(256, 2) void attn_tc(
    const __half* __restrict__ q, const __half* __restrict__ k,
    const __half* __restrict__ v, const uint32_t* __restrict__ mb,
    __half* __restrict__ ctx)
{
    extern __shared__ __half smh[];
    __half* ks_ = smh;
    __half* vs_ = ks_ + 2 * KTSZ;
    __half* ps_ = vs_ + 2 * KTSZ;

    int tid  = threadIdx.x;
    int warp = tid >> 5, lane = tid & 31;
    int lr = lane >> 2, lc = lane & 3;
    int bh = blockIdx.y;
    int b  = bh >> 4, h = bh & 15;
    int q0 = blockIdx.x * 128;

    const __half* qb = q + (((size_t)bh) * SEQ + q0) * DK;
    const __half* kb = k + ((size_t)bh) * T_PAD * DK;
    const __half* vb = v + ((size_t)bh) * T_PAD * DK;

    int row0 = warp * 16 + lr;
    int row1 = row0 + 8;
    int grow0 = q0 + row0, grow1 = q0 + row1;
    __half* psw = ps_ + warp * 16 * PSTH;
    uint32_t sP = smem_u32(psw);

    int a_row = (lane & 7) + ((lane >> 3) & 1) * 8;
    int a_kof = (lane >> 4) * 8;
    int b_row = (lane & 7) + ((lane >> 4) & 1) * 8;
    int b_kof = ((lane >> 3) & 1) * 8;

    uint32_t qf[4][4];
    #pragma unroll
    for (int ks = 0; ks < 4; ks++) {
        qf[ks][0] = *(const uint32_t*)(qb + (size_t)row0 * DK + ks * 16 + 2 * lc    );
        qf[ks][1] = *(const uint32_t*)(qb + (size_t)row1 * DK + ks * 16 + 2 * lc    );
        qf[ks][2] = *(const uint32_t*)(qb + (size_t)row0 * DK + ks * 16 + 2 * lc + 8);
        qf[ks][3] = *(const uint32_t*)(qb + (size_t)row1 * DK + ks * 16 + 2 * lc + 8);
    }

    float o[8][4];
    #pragma unroll
    for (int nt = 0; nt < 8; nt++)
        #pragma unroll
        for (int i = 0; i < 4; i++) o[nt][i] = 0.f;

    float m0 = -INFINITY, m1 = -INFINITY, l0 = 0.f, l1 = 0.f;

    uint32_t sK = smem_u32(ks_);
    uint32_t sV = smem_u32(vs_);

#define LOADKV(st, tile) do {                                                       \
        _Pragma("unroll")                                                           \
        for (int l = 0; l < 2; l++) {                                               \
            int fid = tid + l * 256;                                                \
            int r = fid >> 3, c8 = fid & 7;                                         \
            cp_async16(sK + (uint32_t)((st) * KTSZ + r * KSTH + c8 * 8) * 2,        \
                       kb + ((size_t)(tile) * 64 + r) * DK + c8 * 8);               \
            cp_async16(sV + (uint32_t)((st) * KTSZ + r * KSTH + c8 * 8) * 2,        \
                       vb + ((size_t)(tile) * 64 + r) * DK + c8 * 8);               \
        }                                                                           \
        asm volatile("cp.async.commit_group;");                                     \
    } while (0)

    LOADKV(0, 0);

    for (int t = 0; t < NKT; t++) {
        int st = t & 1;
        asm volatile("cp.async.wait_group 0;");
        __syncthreads();
        if (t + 1 < NKT) LOADKV(st ^ 1, t + 1);

        float c[8][4];
        #pragma unroll
        for (int nt = 0; nt < 8; nt++)
            #pragma unroll
            for (int i = 0; i < 4; i++) c[nt][i] = 0.f;

        uint32_t kS = sK + (uint32_t)(st * KTSZ) * 2;
        #pragma unroll
        for (int ks = 0; ks < 4; ks++) {
            #pragma unroll
            for (int nb = 0; nb < 4; nb++) {
                uint32_t addr = kS + (uint32_t)(((nb * 16 + b_row) * KSTH)
                                                 + ks * 16 + b_kof) * 2;
                uint32_t r0, r1, r2, r3;
                ldsm_x4(r0, r1, r2, r3, addr);
                uint32_t bf0[2] = {r0, r1};
                uint32_t bf1[2] = {r2, r3};
                mma_f16(c[nb * 2    ], qf[ks], bf0);
                mma_f16(c[nb * 2 + 1], qf[ks], bf1);
            }
        }

        uint32_t mwA0 = mb[(size_t)grow0 * NWORDS + t * 2    ];
        uint32_t mwA1 = mb[(size_t)grow0 * NWORDS + t * 2 + 1];
        uint32_t mwB0 = mb[(size_t)grow1 * NWORDS + t * 2    ];
        uint32_t mwB1 = mb[(size_t)grow1 * NWORDS + t * 2 + 1];
        float mx0 = -INFINITY, mx1 = -INFINITY;
        #pragma unroll
        for (int nt = 0; nt < 8; nt++) {
            uint32_t wA = (nt < 4) ? mwA0 : mwA1;
            uint32_t wB = (nt < 4) ? mwB0 : mwB1;
            int j = (nt * 8 + 2 * lc) & 31;
            c[nt][0] = ((wA >> j)       & 1u) ? c[nt][0] * 0.125f : -1e9f;
            c[nt][1] = ((wA >> (j + 1)) & 1u) ? c[nt][1] * 0.125f : -1e9f;
            c[nt][2] = ((wB >> j)       & 1u) ? c[nt][2] * 0.125f : -1e9f;
            c[nt][3] = ((wB >> (j + 1)) & 1u) ? c[nt][3] * 0.125f : -1e9f;
            mx0 = fmaxf(mx0, fmaxf(c[nt][0], c[nt][1]));
            mx1 = fmaxf(mx1, fmaxf(c[nt][2], c[nt][3]));
        }
        mx0 = fmaxf(mx0, __shfl_xor_sync(0xffffffffu, mx0, 1));
        mx0 = fmaxf(mx0, __shfl_xor_sync(0xffffffffu, mx0, 2));
        mx1 = fmaxf(mx1, __shfl_xor_sync(0xffffffffu, mx1, 1));
        mx1 = fmaxf(mx1, __shfl_xor_sync(0xffffffffu, mx1, 2));

        float mn0 = fmaxf(m0, mx0);
        float mn1 = fmaxf(m1, mx1);
        float a0 = __expf(m0 - mn0);
        float a1 = __expf(m1 - mn1);
        m0 = mn0; m1 = mn1;

        float s0 = 0.f, s1 = 0.f;
        #pragma unroll
        for (int nt = 0; nt < 8; nt++) {
            int col = nt * 8 + 2 * lc;
            float p00 = __expf(c[nt][0] - mn0);
            float p01 = __expf(c[nt][1] - mn0);
            float p10 = __expf(c[nt][2] - mn1);
            float p11 = __expf(c[nt][3] - mn1);
            s0 += p00 + p01;
            s1 += p10 + p11;
            *(__half2*)(psw + lr       * PSTH + col) = __floats2half2_rn(p00, p01);
            *(__half2*)(psw + (lr + 8) * PSTH + col) = __floats2half2_rn(p10, p11);
        }
        s0 += __shfl_xor_sync(0xffffffffu, s0, 1);
        s0 += __shfl_xor_sync(0xffffffffu, s0, 2);
        s1 += __shfl_xor_sync(0xffffffffu, s1, 1);
        s1 += __shfl_xor_sync(0xffffffffu, s1, 2);
        l0 = l0 * a0 + s0;
        l1 = l1 * a1 + s1;
        __syncwarp();

        #pragma unroll
        for (int nt = 0; nt < 8; nt++) {
            o[nt][0] *= a0; o[nt][1] *= a0;
            o[nt][2] *= a1; o[nt][3] *= a1;
        }
        uint32_t vbase = sV + (uint32_t)(st * KTSZ) * 2;
        #pragma unroll
        for (int ks = 0; ks < 4; ks++) {
            uint32_t af[4];
            uint32_t paddr = sP + (uint32_t)((a_row * PSTH) + ks * 16 + a_kof) * 2;
            ldsm_x4(af[0], af[1], af[2], af[3], paddr);
            #pragma unroll
            for (int np = 0; np < 4; np++) {
                uint32_t addr = vbase
                    + (uint32_t)((ks * 16 + (lane & 15)) * KSTH) * 2
                    + (uint32_t)(np * 16 + ((lane >> 4) << 3)) * 2;
                uint32_t b0, b1, b2, b3;
                ldsm_x4_t(b0, b1, b2, b3, addr);
                uint32_t bf0[2] = {b0, b1};
                uint32_t bf1[2] = {b2, b3};
                mma_f16(o[np * 2    ], af, bf0);
                mma_f16(o[np * 2 + 1], af, bf1);
            }
        }
    }

    float inv0 = 1.f / l0, inv1 = 1.f / l1;
    #pragma unroll
    for (int nt = 0; nt < 8; nt++) {
        int col = h * 64 + nt * 8 + 2 * lc;
        *(__half2*)(ctx + ((size_t)b * SEQ + grow0) * DMODEL + col) =
            __floats2half2_rn(o[nt][0] * inv0, o[nt][1] * inv0);
        *(__half2*)(ctx + ((size_t)b * SEQ + grow1) * DMODEL + col) =
            __floats2half2_rn(o[nt][2] * inv1, o[nt][3] * inv1);
    }
#undef LOADKV
}

// ---------------- new_memory ----------------
__global__ __launch_bounds__(1024) void mem_partial_kernel(
    const float* __restrict__ xo, float* __restrict__ part)
{
    int b = blockIdx.x, cz = blockIdx.y, d = threadIdx.x;
    const float* base = xo + ((size_t)b * SEQ + cz * 128) * DMODEL + d;
    float s = 0.f;
    #pragma unroll 4
    for (int i = 0; i < 128; i++) s += base[(size_t)i * DMODEL];
    part[((size_t)b * 16 + cz) * DMODEL + d] = s;
}

__global__ __launch_bounds__(1024) void mem_final_kernel(
    const float* __restrict__ part, float* __restrict__ memout)
{
    int b = blockIdx.x, d = threadIdx.x;
    float s = 0.f;
    #pragma unroll
    for (int i = 0; i < 16; i++) s += part[((size_t)b * 16 + i) * DMODEL + d];
    float vv = s * (1.f / SEQ);
    #pragma unroll
    for (int m = 0; m < MEMT; m++)
        memout[((size_t)b * MEMT + m) * DMODEL + d] = vv;
}

// ---------------- launch ----------------
extern "C" void kernel_launch(void* const* d_in, const int* in_sizes, int n_in,
                              void* d_out, int out_size)
{
    const float* x    = (const float*)d_in[0];
    const int*   mask = (const int*)  d_in[1];
    const float* mem  = (const float*)d_in[2];
    const float* wq   = (const float*)d_in[3];
    const float* wk   = (const float*)d_in[4];
    const float* wv   = (const float*)d_in[5];
    const float* wo   = (const float*)d_in[6];
    const float* ln1a = (const float*)d_in[7];
    const float* ln1b = (const float*)d_in[8];
    const float* ln2a = (const float*)d_in[9];
    const float* ln2b = (const float*)d_in[10];
    const float* fw1  = (const float*)d_in[11];
    const float* fb1  = (const float*)d_in[12];
    const float* fw2  = (const float*)d_in[13];
    const float* fb2  = (const float*)d_in[14];
    float* out = (float*)d_out;
    float* out_mem = out + (size_t)ROWS * DMODEL;

    void* p;
    __half *xn, *q, *k, *v, *ctx, *xn2, *h1;
    float *x1, *part, *mpp;
    __half *wqkvt, *wot, *fw1t, *fw2t;
    uint32_t* mb;
    cudaGetSymbolAddress(&p, g_xn);  xn  = (__half*)p;
    cudaGetSymbolAddress(&p, g_q);   q   = (__half*)p;
    cudaGetSymbolAddress(&p, g_k);   k   = (__half*)p;
    cudaGetSymbolAddress(&p, g_v);   v   = (__half*)p;
    cudaGetSymbolAddress(&p, g_ctx); ctx = (__half*)p;
    cudaGetSymbolAddress(&p, g_x1);  x1  = (float*)p;
    cudaGetSymbolAddress(&p, g_xn2); xn2 = (__half*)p;
    cudaGetSymbolAddress(&p, g_h1);  h1  = (__half*)p;
    cudaGetSymbolAddress(&p, g_part);part= (float*)p;
    cudaGetSymbolAddress(&p, g_mb);  mb  = (uint32_t*)p;
    cudaGetSymbolAddress(&p, g_wqkv);wqkvt=(__half*)p;
    cudaGetSymbolAddress(&p, g_wo);  wot = (__half*)p;
    cudaGetSymbolAddress(&p, g_fw1); fw1t= (__half*)p;
    cudaGetSymbolAddress(&p, g_fw2); fw2t= (__half*)p;
    cudaGetSymbolAddress(&p, g_mpp); mpp = (float*)p;

    cudaFuncSetAttribute(gemm_tc<EPI_QKV>,       cudaFuncAttributeMaxDynamicSharedMemorySize, GEMM_SMEM_BYTES);
    cudaFuncSetAttribute(gemm_tc<EPI_RESID>,     cudaFuncAttributeMaxDynamicSharedMemorySize, GEMM_SMEM_BYTES);
    cudaFuncSetAttribute(gemm_tc<EPI_BIAS_RELU>, cudaFuncAttributeMaxDynamicSharedMemorySize, GEMM_SMEM_BYTES);
    cudaFuncSetAttribute(gemm_tc<EPI_BIAS_RESID>,cudaFuncAttributeMaxDynamicSharedMemorySize, GEMM_SMEM_BYTES);
    cudaFuncSetAttribute(attn_tc, cudaFuncAttributeMaxDynamicSharedMemorySize, ATTN_SMEM_BYTES);

    ln_kernel<<<ROWS, 256>>>(x, ln1a, ln1b, xn);                       // 1
    maskbits_kernel<<<SEQ, NWORDS>>>(mask, mb);                        // 2
    padclear_kernel<<<BATCH * NHEADS, 256>>>(k, v);                    // 3
    memproj_part<<<dim3(MEMT, 16), 1024>>>(mem, wk, wv, mpp);          // 4
    transpose_all<<<12288, dim3(32, 8)>>>(wq, wk, wv, wo, fw1, fw2,    // 5
                                          wqkvt, wot, fw1t, fw2t);

    gemm_tc<EPI_QKV><<<dim3(3*DMODEL/BN, ROWS/BM), 256, GEMM_SMEM_BYTES>>>(   // 6 <- profiled
        xn, wqkvt, q, nullptr, nullptr, k, v, ROWS, 3*DMODEL, DMODEL);

    memproj_final<<<MEMT, 1024>>>(mpp, k, v);                          // 7

    attn_tc<<<dim3(SEQ/128, BATCH*NHEADS), 256, ATTN_SMEM_BYTES>>>(q, k, v, mb, ctx);

    gemm_tc<EPI_RESID><<<dim3(DMODEL/BN, ROWS/BM), 256, GEMM_SMEM_BYTES>>>(
        ctx, wot, x1, nullptr, x, nullptr, nullptr, ROWS, DMODEL, DMODEL);

    ln_kernel<<<ROWS, 256>>>(x1, ln2a, ln2b, xn2);

    gemm_tc<EPI_BIAS_RELU><<<dim3(DFF/BN, ROWS/BM), 256, GEMM_SMEM_BYTES>>>(
        xn2, fw1t, h1, fb1, nullptr, nullptr, nullptr, ROWS, DFF, DMODEL);
    gemm_tc<EPI_BIAS_RESID><<<dim3(DMODEL/BN, ROWS/BM), 256, GEMM_SMEM_BYTES>>>(
        h1, fw2t, out, fb2, x1, nullptr, nullptr, ROWS, DMODEL, DFF);

    mem_partial_kernel<<<dim3(BATCH, 16), 1024>>>(out, part);
    mem_final_kernel<<<BATCH, 1024>>>(part, out_mem);
}

// round 14
// speedup vs baseline: 12.5249x; 1.0560x over previous
#include <cuda_runtime.h>
#include <cuda_fp16.h>
#include <math.h>
#include <stdint.h>

// ---------------- problem constants ----------------
#define BATCH 4
#define SEQ   2048
#define DMODEL 1024
#define NHEADS 16
#define DK    64
#define MEMT  32
#define TTOT  (SEQ + MEMT)
#define T_PAD 2112
#define NKT   33
#define DFF   4096
#define ROWS  (BATCH * SEQ)
#define XROWS (ROWS + 128)        // +1 M-block for memory tokens
#define NWORDS 66

// ---------------- device scratch ----------------
__device__ __half g_xn [XROWS * DMODEL];
__device__ __half g_q  [BATCH * NHEADS * SEQ   * DK];
__device__ __half g_k  [BATCH * NHEADS * T_PAD * DK];
__device__ __half g_v  [BATCH * NHEADS * T_PAD * DK];
__device__ __half g_ctx[ROWS * DMODEL];
__device__ float  g_x1 [ROWS * DMODEL];
__device__ __half g_xn2[ROWS * DMODEL];
__device__ __half g_h1 [ROWS * DFF];
__device__ float  g_part[BATCH * 16 * DMODEL];
__device__ uint32_t g_mb[SEQ * NWORDS];
__device__ __half g_wqkv[3 * DMODEL * DMODEL];
__device__ __half g_wo  [DMODEL * DMODEL];
__device__ __half g_fw1 [DFF * DMODEL];
__device__ __half g_fw2 [DMODEL * DFF];

// ---------------- helpers ----------------
__device__ __forceinline__ void cp_async16(uint32_t dst, const void* src) {
    asm volatile("cp.async.cg.shared.global [%0], [%1], 16;\n" :: "r"(dst), "l"(src));
}
__device__ __forceinline__ void mma_f16(float* c, const uint32_t* a, const uint32_t* b) {
    asm volatile(
        "mma.sync.aligned.m16n8k16.row.col.f32.f16.f16.f32 "
        "{%0,%1,%2,%3},{%4,%5,%6,%7},{%8,%9},{%0,%1,%2,%3};"
        : "+f"(c[0]), "+f"(c[1]), "+f"(c[2]), "+f"(c[3])
        : "r"(a[0]), "r"(a[1]), "r"(a[2]), "r"(a[3]), "r"(b[0]), "r"(b[1]));
}
__device__ __forceinline__ void ldsm_x4(uint32_t& r0, uint32_t& r1, uint32_t& r2, uint32_t& r3, uint32_t addr) {
    asm volatile("ldmatrix.sync.aligned.m8n8.x4.shared.b16 {%0,%1,%2,%3}, [%4];"
                 : "=r"(r0), "=r"(r1), "=r"(r2), "=r"(r3) : "r"(addr));
}
__device__ __forceinline__ void ldsm_x4_t(uint32_t& r0, uint32_t& r1, uint32_t& r2, uint32_t& r3, uint32_t addr) {
    asm volatile("ldmatrix.sync.aligned.m8n8.x4.trans.shared.b16 {%0,%1,%2,%3}, [%4];"
                 : "=r"(r0), "=r"(r1), "=r"(r2), "=r"(r3) : "r"(addr));
}
__device__ __forceinline__ uint32_t smem_u32(const void* p) {
    return (uint32_t)__cvta_generic_to_shared(p);
}

// ---------------- merged weight transpose + fp16 (single launch) ----------------
__global__ __launch_bounds__(256) void transpose_all(
    const float* __restrict__ wq, const float* __restrict__ wk,
    const float* __restrict__ wv, const float* __restrict__ wo,
    const float* __restrict__ fw1, const float* __restrict__ fw2,
    __half* __restrict__ dwqkv, __half* __restrict__ dwo,
    __half* __restrict__ dfw1, __half* __restrict__ dfw2)
{
    __shared__ float t[32][33];
    int tb = blockIdx.x;
    const float* src; __half* dst; int K, N, lt;
    if (tb < 3072) {
        int w = tb >> 10; lt = tb & 1023;
        src = (w == 0) ? wq : (w == 1) ? wk : wv;
        dst = dwqkv + (size_t)w * DMODEL * DMODEL;
        K = DMODEL; N = DMODEL;
    } else if (tb < 4096) {
        src = wo;  dst = dwo;  lt = tb - 3072; K = DMODEL; N = DMODEL;
    } else if (tb < 8192) {
        src = fw1; dst = dfw1; lt = tb - 4096; K = DMODEL; N = DFF;
    } else {
        src = fw2; dst = dfw2; lt = tb - 8192; K = DFF; N = DMODEL;
    }
    int ntn = N >> 5;
    int n0 = (lt % ntn) * 32, k0 = (lt / ntn) * 32;
    int tx = threadIdx.x, ty = threadIdx.y;
    #pragma unroll
    for (int i = 0; i < 4; i++)
        t[ty + 8*i][tx] = src[(size_t)(k0 + ty + 8*i) * N + n0 + tx];
    __syncthreads();
    #pragma unroll
    for (int i = 0; i < 4; i++)
        dst[(size_t)(n0 + ty + 8*i) * K + k0 + tx] = __float2half_rn(t[tx][ty + 8*i]);
}

// ---------------- fill memory-token rows of xn (rows ROWS..XROWS) ----------------
__global__ __launch_bounds__(256) void memfill_kernel(
    const float* __restrict__ mt, __half* __restrict__ xn)
{
    int row = blockIdx.x;              // 0..127
    int c4 = threadIdx.x * 4;
    __half2 z = __floats2half2_rn(0.f, 0.f);
    __half2* dst = (__half2*)(xn + (size_t)(ROWS + row) * DMODEL + c4);
    if (row < MEMT) {
        float4 t = *(const float4*)(mt + (size_t)row * DMODEL + c4);
        dst[0] = __floats2half2_rn(t.x, t.y);
        dst[1] = __floats2half2_rn(t.z, t.w);
    } else {
        dst[0] = z;
        dst[1] = z;
    }
}

// ---------------- layer norm (ddof=1); fp16 output ----------------
__global__ __launch_bounds__(256) void ln_kernel(
    const float* __restrict__ x, const float* __restrict__ alpha,
    const float* __restrict__ bias, __half* __restrict__ out)
{
    int row = blockIdx.x;
    int tid = threadIdx.x;
    const float4* xr = (const float4*)(x + (size_t)row * DMODEL);
    float4 v = xr[tid];
    float s  = v.x + v.y + v.z + v.w;
    float ss = v.x*v.x + v.y*v.y + v.z*v.z + v.w*v.w;
    #pragma unroll
    for (int off = 16; off > 0; off >>= 1) {
        s  += __shfl_xor_sync(0xffffffffu, s,  off);
        ss += __shfl_xor_sync(0xffffffffu, ss, off);
    }
    __shared__ float rs[8], rss[8];
    int wid = tid >> 5, lane = tid & 31;
    if (lane == 0) { rs[wid] = s; rss[wid] = ss; }
    __syncthreads();
    float S = 0.f, SS = 0.f;
    #pragma unroll
    for (int w = 0; w < 8; w++) { S += rs[w]; SS += rss[w]; }
    float mean = S * (1.f / DMODEL);
    float var  = (SS - (float)DMODEL * mean * mean) * (1.f / (DMODEL - 1));
    float inv  = 1.f / (sqrtf(fmaxf(var, 0.f)) + 1e-6f);
    float4 a  = ((const float4*)alpha)[tid];
    float4 bb = ((const float4*)bias)[tid];
    __half2* o2 = (__half2*)(out + (size_t)row * DMODEL) + tid * 2;
    o2[0] = __floats2half2_rn(a.x * (v.x - mean) * inv + bb.x,
                              a.y * (v.y - mean) * inv + bb.y);
    o2[1] = __floats2half2_rn(a.z * (v.z - mean) * inv + bb.z,
                              a.w * (v.w - mean) * inv + bb.w);
}

// ---------------- fp16 mma GEMM, 3-stage pipeline, 1 barrier/iter ----------------
#define EPI_QKV        0
#define EPI_RESID      3
#define EPI_BIAS_RELU  4
#define EPI_BIAS_RESID 5

#define BM 128
#define BN 128
#define BK 64
#define STH 72
#define TSZ (128 * STH)
#define NSTG 3
#define GEMM_SMEM_BYTES (NSTG * 2 * TSZ * 2)   // 110592

template<int EPI>
__global__ __launch_bounds__(256, 2) void gemm_tc(
    const __half* __restrict__ A, const __half* __restrict__ W,
    void* __restrict__ Cp, const float* __restrict__ bias,
    const float* __restrict__ R, __half* __restrict__ C2, __half* __restrict__ C3,
    int M, int N, int K)
{
    extern __shared__ __half sm[];
    __half* As = sm;
    __half* Bs = sm + NSTG * TSZ;

    int tid  = threadIdx.x;
    int warp = tid >> 5, lane = tid & 31;
    int wm = warp & 1;
    int wn = warp >> 1;
    int lr = lane >> 2;
    int lc = lane & 3;

    const __half* Abase = A + (size_t)blockIdx.y * BM * K;
    const __half* Wbase = W + (size_t)blockIdx.x * BN * K;

    uint32_t sA = smem_u32(As);
    uint32_t sB = smem_u32(Bs);

    int a_row = (lane & 7) + ((lane >> 3) & 1) * 8;
    int a_kof = (lane >> 4) * 8;
    int b_row = (lane & 7) + ((lane >> 4) & 1) * 8;
    int b_kof = ((lane >> 3) & 1) * 8;

    float acc[4][4][4];
    #pragma unroll
    for (int mt = 0; mt < 4; mt++)
        #pragma unroll
        for (int nt = 0; nt < 4; nt++)
            #pragma unroll
            for (int i = 0; i < 4; i++) acc[mt][nt][i] = 0.f;

#define LOAD_STAGE(st, kt) do {                                                   \
        _Pragma("unroll")                                                         \
        for (int l = 0; l < 4; l++) {                                             \
            int fid = tid + l * 256;                                              \
            int r = fid >> 3, c8 = fid & 7;                                       \
            cp_async16(sA + (uint32_t)((st) * TSZ + r * STH + c8 * 8) * 2,        \
                       Abase + (size_t)r * K + (size_t)(kt) * BK + c8 * 8);       \
        }                                                                         \
        _Pragma("unroll")                                                         \
        for (int l = 0; l < 4; l++) {                                             \
            int fid = tid + l * 256;                                              \
            int r = fid >> 3, c8 = fid & 7;                                       \
            cp_async16(sB + (uint32_t)((st) * TSZ + r * STH + c8 * 8) * 2,        \
                       Wbase + (size_t)r * K + (size_t)(kt) * BK + c8 * 8);       \
        }                                                                         \
        asm volatile("cp.async.commit_group;");                                   \
    } while (0)

    int NT = K / BK;
    LOAD_STAGE(0, 0);
    LOAD_STAGE(1, 1);

    for (int kt = 0; kt < NT; kt++) {
        int st = kt - (kt / NSTG) * NSTG;
        asm volatile("cp.async.wait_group 1;");
        __syncthreads();
        if (kt + 2 < NT) {
            int sl = st + 2; if (sl >= NSTG) sl -= NSTG;
            LOAD_STAGE(sl, kt + 2);
        } else {
            asm volatile("cp.async.commit_group;");
        }

        uint32_t aS = sA + (uint32_t)(st * TSZ) * 2;
        uint32_t bS = sB + (uint32_t)(st * TSZ) * 2;

        #pragma unroll
        for (int ks = 0; ks < 4; ks++) {
            uint32_t af[4][4], bf[4][2];
            #pragma unroll
            for (int mt = 0; mt < 4; mt++) {
                uint32_t addr = aS + (uint32_t)(((wm * 64 + mt * 16 + a_row) * STH)
                                                 + ks * 16 + a_kof) * 2;
                ldsm_x4(af[mt][0], af[mt][1], af[mt][2], af[mt][3], addr);
            }
            #pragma unroll
            for (int nb = 0; nb < 2; nb++) {
                uint32_t addr = bS + (uint32_t)(((wn * 32 + nb * 16 + b_row) * STH)
                                                 + ks * 16 + b_kof) * 2;
                uint32_t r0, r1, r2, r3;
                ldsm_x4(r0, r1, r2, r3, addr);
                bf[nb * 2    ][0] = r0; bf[nb * 2    ][1] = r1;
                bf[nb * 2 + 1][0] = r2; bf[nb * 2 + 1][1] = r3;
            }
            #pragma unroll
            for (int mt = 0; mt < 4; mt++)
                #pragma unroll
                for (int nt = 0; nt < 4; nt++)
                    mma_f16(acc[mt][nt], af[mt], bf[nt]);
        }
    }

    #pragma unroll
    for (int mt = 0; mt < 4; mt++) {
        #pragma unroll
        for (int rg = 0; rg < 2; rg++) {
            int r = blockIdx.y * BM + wm * 64 + mt * 16 + lr + rg * 8;
            #pragma unroll
            for (int nt = 0; nt < 4; nt++) {
                int c = blockIdx.x * BN + wn * 32 + nt * 8 + lc * 2;
                float v0 = acc[mt][nt][rg * 2 + 0];
                float v1 = acc[mt][nt][rg * 2 + 1];
                if (EPI == EPI_QKV) {
                    int sel = c >> 10, cc = c & 1023;
                    int h = cc >> 6, d = cc & 63;
                    __half2 o = __floats2half2_rn(v0, v1);
                    if (r < ROWS) {
                        int b = r >> 11, s2 = r & 2047;
                        if (sel == 0)
                            *(__half2*)((__half*)Cp + ((((size_t)(b * NHEADS + h)) * SEQ + s2) * DK + d)) = o;
                        else if (sel == 1)
                            *(__half2*)(C2 + ((((size_t)(b * NHEADS + h)) * T_PAD + MEMT + s2) * DK + d)) = o;
                        else
                            *(__half2*)(C3 + ((((size_t)(b * NHEADS + h)) * T_PAD + MEMT + s2) * DK + d)) = o;
                    } else {
                        // memory-token rows: write K/V at t = rr for ALL batches
                        int rr = r - ROWS;
                        if (rr < MEMT && sel > 0) {
                            __half* dstb = (sel == 1) ? C2 : C3;
                            #pragma unroll
                            for (int b = 0; b < BATCH; b++)
                                *(__half2*)(dstb + ((((size_t)(b * NHEADS + h)) * T_PAD + rr) * DK + d)) = o;
                        }
                    }
                } else if (EPI == EPI_RESID) {
                    float2 rr = *(const float2*)(R + (size_t)r * N + c);
                    *(float2*)((float*)Cp + (size_t)r * N + c) = make_float2(v0 + rr.x, v1 + rr.y);
                } else if (EPI == EPI_BIAS_RELU) {
                    float2 bb = *(const float2*)(bias + c);
                    *(__half2*)((__half*)Cp + (size_t)r * N + c) =
                        __floats2half2_rn(fmaxf(v0 + bb.x, 0.f), fmaxf(v1 + bb.y, 0.f));
                } else if (EPI == EPI_BIAS_RESID) {
                    float2 bb = *(const float2*)(bias + c);
                    float2 rr = *(const float2*)(R + (size_t)r * N + c);
                    *(float2*)((float*)Cp + (size_t)r * N + c) = make_float2(v0 + bb.x + rr.x, v1 + bb.y + rr.y);
                }
            }
        }
    }
#undef LOAD_STAGE
}

__global__ __launch_bounds__(256) void padclear_kernel(__half* k, __half* v)
{
    int bh = blockIdx.x;
    size_t base = ((size_t)bh * T_PAD + TTOT) * DK / 2;
    uint32_t* k32 = (uint32_t*)k;
    uint32_t* v32 = (uint32_t*)v;
    for (int i = threadIdx.x; i < (T_PAD - TTOT) * DK / 2; i += 256) {
        k32[base + i] = 0u;
        v32[base + i] = 0u;
    }
}

__global__ void maskbits_kernel(const int* __restrict__ mask, uint32_t* __restrict__ mb)
{
    int s = blockIdx.x;
    int w = threadIdx.x;
    uint32_t bits = 0;
    #pragma unroll 4
    for (int j = 0; j < 32; j++) {
        int t = w * 32 + j;
        if (t < TTOT && mask[(size_t)s * TTOT + t] != 0) bits |= (1u << j);
    }
    mb[(size_t)s * NWORDS + w] = bits;
}

// ---------------- fp16 flash attention: warp-owned rows, 1 barrier/tile ----------------
#define KSTH 72
#define KTSZ (64 * KSTH)
#define PSTH 72
#define ATTN_SMEM_BYTES ((2*KTSZ + 2*KTSZ + 8*16*PSTH) * 2)   // 55296

__global__ __launch_bounds__(256, 2) void attn_tc(
    const __half* __restrict__ q, const __half* __restrict__ k,
    const __half* __restrict__ v, const uint32_t* __restrict__ mb,
    __half* __restrict__ ctx)
{
    extern __shared__ __half smh[];
    __half* ks_ = smh;
    __half* vs_ = ks_ + 2 * KTSZ;
    __half* ps_ = vs_ + 2 * KTSZ;

    int tid  = threadIdx.x;
    int warp = tid >> 5, lane = tid & 31;
    int lr = lane >> 2, lc = lane & 3;
    int bh = blockIdx.y;
    int b  = bh >> 4, h = bh & 15;
    int q0 = blockIdx.x * 128;

    const __half* qb = q + (((size_t)bh) * SEQ + q0) * DK;
    const __half* kb = k + ((size_t)bh) * T_PAD * DK;
    const __half* vb = v + ((size_t)bh) * T_PAD * DK;

    int row0 = warp * 16 + lr;
    int row1 = row0 + 8;
    int grow0 = q0 + row0, grow1 = q0 + row1;
    __half* psw = ps_ + warp * 16 * PSTH;
    uint32_t sP = smem_u32(psw);

    int a_row = (lane & 7) + ((lane >> 3) & 1) * 8;
    int a_kof = (lane >> 4) * 8;
    int b_row = (lane & 7) + ((lane >> 4) & 1) * 8;
    int b_kof = ((lane >> 3) & 1) * 8;

    uint32_t qf[4][4];
    #pragma unroll
    for (int ks = 0; ks < 4; ks++) {
        qf[ks][0] = *(const uint32_t*)(qb + (size_t)row0 * DK + ks * 16 + 2 * lc    );
        qf[ks][1] = *(const uint32_t*)(qb + (size_t)row1 * DK + ks * 16 + 2 * lc    );
        qf[ks][2] = *(const uint32_t*)(qb + (size_t)row0 * DK + ks * 16 + 2 * lc + 8);
        qf[ks][3] = *(const uint32_t*)(qb + (size_t)row1 * DK + ks * 16 + 2 * lc + 8);
    }

    float o[8][4];
    #pragma unroll
    for (int nt = 0; nt < 8; nt++)
        #pragma unroll
        for (int i = 0; i < 4; i++) o[nt][i] = 0.f;

    float m0 = -INFINITY, m1 = -INFINITY, l0 = 0.f, l1 = 0.f;

    uint32_t sK = smem_u32(ks_);
    uint32_t sV = smem_u32(vs_);

#define LOADKV(st, tile) do {                                                       \
        _Pragma("unroll")                                                           \
        for (int l = 0; l < 2; l++) {                                               \
            int fid = tid + l * 256;                                                \
            int r = fid >> 3, c8 = fid & 7;                                         \
            cp_async16(sK + (uint32_t)((st) * KTSZ + r * KSTH + c8 * 8) * 2,        \
                       kb + ((size_t)(tile) * 64 + r) * DK + c8 * 8);               \
            cp_async16(sV + (uint32_t)((st) * KTSZ + r * KSTH + c8 * 8) * 2,        \
                       vb + ((size_t)(tile) * 64 + r) * DK + c8 * 8);               \
        }                                                                           \
        asm volatile("cp.async.commit_group;");                                     \
    } while (0)

    LOADKV(0, 0);

    for (int t = 0; t < NKT; t++) {
        int st = t & 1;
        asm volatile("cp.async.wait_group 0;");
        __syncthreads();
        if (t + 1 < NKT) LOADKV(st ^ 1, t + 1);

        float c[8][4];
        #pragma unroll
        for (int nt = 0; nt < 8; nt++)
            #pragma unroll
            for (int i = 0; i < 4; i++) c[nt][i] = 0.f;

        uint32_t kS = sK + (uint32_t)(st * KTSZ) * 2;
        #pragma unroll
        for (int ks = 0; ks < 4; ks++) {
            #pragma unroll
            for (int nb = 0; nb < 4; nb++) {
                uint32_t addr = kS + (uint32_t)(((nb * 16 + b_row) * KSTH)
                                                 + ks * 16 + b_kof) * 2;
                uint32_t r0, r1, r2, r3;
                ldsm_x4(r0, r1, r2, r3, addr);
                uint32_t bf0[2] = {r0, r1};
                uint32_t bf1[2] = {r2, r3};
                mma_f16(c[nb * 2    ], qf[ks], bf0);
                mma_f16(c[nb * 2 + 1], qf[ks], bf1);
            }
        }

        uint32_t mwA0 = mb[(size_t)grow0 * NWORDS + t * 2    ];
        uint32_t mwA1 = mb[(size_t)grow0 * NWORDS + t * 2 + 1];
        uint32_t mwB0 = mb[(size_t)grow1 * NWORDS + t * 2    ];
        uint32_t mwB1 = mb[(size_t)grow1 * NWORDS + t * 2 + 1];
        bool nomask = __all_sync(0xffffffffu,
            (mwA0 & mwA1 & mwB0 & mwB1) == 0xffffffffu);

        float mx0 = -INFINITY, mx1 = -INFINITY;
        if (nomask) {
            #pragma unroll
            for (int nt = 0; nt < 8; nt++) {
                c[nt][0] *= 0.125f; c[nt][1] *= 0.125f;
                c[nt][2] *= 0.125f; c[nt][3] *= 0.125f;
                mx0 = fmaxf(mx0, fmaxf(c[nt][0], c[nt][1]));
                mx1 = fmaxf(mx1, fmaxf(c[nt][2], c[nt][3]));
            }
        } else {
            #pragma unroll
            for (int nt = 0; nt < 8; nt++) {
                uint32_t wA = (nt < 4) ? mwA0 : mwA1;
                uint32_t wB = (nt < 4) ? mwB0 : mwB1;
                int j = (nt * 8 + 2 * lc) & 31;
                c[nt][0] = ((wA >> j)       & 1u) ? c[nt][0] * 0.125f : -1e9f;
                c[nt][1] = ((wA >> (j + 1)) & 1u) ? c[nt][1] * 0.125f : -1e9f;
                c[nt][2] = ((wB >> j)       & 1u) ? c[nt][2] * 0.125f : -1e9f;
                c[nt][3] = ((wB >> (j + 1)) & 1u) ? c[nt][3] * 0.125f : -1e9f;
                mx0 = fmaxf(mx0, fmaxf(c[nt][0], c[nt][1]));
                mx1 = fmaxf(mx1, fmaxf(c[nt][2], c[nt][3]));
            }
        }
        mx0 = fmaxf(mx0, __shfl_xor_sync(0xffffffffu, mx0, 1));
        mx0 = fmaxf(mx0, __shfl_xor_sync(0xffffffffu, mx0, 2));
        mx1 = fmaxf(mx1, __shfl_xor_sync(0xffffffffu, mx1, 1));
        mx1 = fmaxf(mx1, __shfl_xor_sync(0xffffffffu, mx1, 2));

        float mn0 = fmaxf(m0, mx0);
        float mn1 = fmaxf(m1, mx1);
        float a0 = __expf(m0 - mn0);
        float a1 = __expf(m1 - mn1);
        m0 = mn0; m1 = mn1;

        float s0 = 0.f, s1 = 0.f;
        #pragma unroll
        for (int nt = 0; nt < 8; nt++) {
            int col = nt * 8 + 2 * lc;
            float p00 = __expf(c[nt][0] - mn0);
            float p01 = __expf(c[nt][1] - mn0);
            float p10 = __expf(c[nt][2] - mn1);
            float p11 = __expf(c[nt][3] - mn1);
            s0 += p00 + p01;
            s1 += p10 + p11;
            *(__half2*)(psw + lr       * PSTH + col) = __floats2half2_rn(p00, p01);
            *(__half2*)(psw + (lr + 8) * PSTH + col) = __floats2half2_rn(p10, p11);
        }
        s0 += __shfl_xor_sync(0xffffffffu, s0, 1);
        s0 += __shfl_xor_sync(0xffffffffu, s0, 2);
        s1 += __shfl_xor_sync(0xffffffffu, s1, 1);
        s1 += __shfl_xor_sync(0xffffffffu, s1, 2);
        l0 = l0 * a0 + s0;
        l1 = l1 * a1 + s1;
        __syncwarp();

        #pragma unroll
        for (int nt = 0; nt < 8; nt++) {
            o[nt][0] *= a0; o[nt][1] *= a0;
            o[nt][2] *= a1; o[nt][3] *= a1;
        }
        uint32_t vbase = sV + (uint32_t)(st * KTSZ) * 2;
        #pragma unroll
        for (int ks = 0; ks < 4; ks++) {
            uint32_t af[4];
            uint32_t paddr = sP + (uint32_t)((a_row * PSTH) + ks * 16 + a_kof) * 2;
            ldsm_x4(af[0], af[1], af[2], af[3], paddr);
            #pragma unroll
            for (int np = 0; np < 4; np++) {
                uint32_t addr = vbase
                    + (uint32_t)((ks * 16 + (lane & 15)) * KSTH) * 2
                    + (uint32_t)(np * 16 + ((lane >> 4) << 3)) * 2;
                uint32_t b0, b1, b2, b3;
                ldsm_x4_t(b0, b1, b2, b3, addr);
                uint32_t bf0[2] = {b0, b1};
                uint32_t bf1[2] = {b2, b3};
                mma_f16(o[np * 2    ], af, bf0);
                mma_f16(o[np * 2 + 1], af, bf1);
            }
        }
    }

    float inv0 = 1.f / l0, inv1 = 1.f / l1;
    #pragma unroll
    for (int nt = 0; nt < 8; nt++) {
        int col = h * 64 + nt * 8 + 2 * lc;
        *(__half2*)(ctx + ((size_t)b * SEQ + grow0) * DMODEL + col) =
            __floats2half2_rn(o[nt][0] * inv0, o[nt][1] * inv0);
        *(__half2*)(ctx + ((size_t)b * SEQ + grow1) * DMODEL + col) =
            __floats2half2_rn(o[nt][2] * inv1, o[nt][3] * inv1);
    }
#undef LOADKV
}

// ---------------- new_memory ----------------
__global__ __launch_bounds__(1024) void mem_partial_kernel(
    const float* __restrict__ xo, float* __restrict__ part)
{
    int b = blockIdx.x, cz = blockIdx.y, d = threadIdx.x;
    const float* base = xo + ((size_t)b * SEQ + cz * 128) * DMODEL + d;
    float s = 0.f;
    #pragma unroll 4
    for (int i = 0; i < 128; i++) s += base[(size_t)i * DMODEL];
    part[((size_t)b * 16 + cz) * DMODEL + d] = s;
}

__global__ __launch_bounds__(1024) void mem_final_kernel(
    const float* __restrict__ part, float* __restrict__ memout)
{
    int b = blockIdx.x, d = threadIdx.x;
    float s = 0.f;
    #pragma unroll
    for (int i = 0; i < 16; i++) s += part[((size_t)b * 16 + i) * DMODEL + d];
    float vv = s * (1.f / SEQ);
    #pragma unroll
    for (int m = 0; m < MEMT; m++)
        memout[((size_t)b * MEMT + m) * DMODEL + d] = vv;
}

// ---------------- launch ----------------
extern "C" void kernel_launch(void* const* d_in, const int* in_sizes, int n_in,
                              void* d_out, int out_size)
{
    const float* x    = (const float*)d_in[0];
    const int*   mask = (const int*)  d_in[1];
    const float* mem  = (const float*)d_in[2];
    const float* wq   = (const float*)d_in[3];
    const float* wk   = (const float*)d_in[4];
    const float* wv   = (const float*)d_in[5];
    const float* wo   = (const float*)d_in[6];
    const float* ln1a = (const float*)d_in[7];
    const float* ln1b = (const float*)d_in[8];
    const float* ln2a = (const float*)d_in[9];
    const float* ln2b = (const float*)d_in[10];
    const float* fw1  = (const float*)d_in[11];
    const float* fb1  = (const float*)d_in[12];
    const float* fw2  = (const float*)d_in[13];
    const float* fb2  = (const float*)d_in[14];
    float* out = (float*)d_out;
    float* out_mem = out + (size_t)ROWS * DMODEL;

    void* p;
    __half *xn, *q, *k, *v, *ctx, *xn2, *h1;
    float *x1, *part;
    __half *wqkvt, *wot, *fw1t, *fw2t;
    uint32_t* mb;
    cudaGetSymbolAddress(&p, g_xn);  xn  = (__half*)p;
    cudaGetSymbolAddress(&p, g_q);   q   = (__half*)p;
    cudaGetSymbolAddress(&p, g_k);   k   = (__half*)p;
    cudaGetSymbolAddress(&p, g_v);   v   = (__half*)p;
    cudaGetSymbolAddress(&p, g_ctx); ctx = (__half*)p;
    cudaGetSymbolAddress(&p, g_x1);  x1  = (float*)p;
    cudaGetSymbolAddress(&p, g_xn2); xn2 = (__half*)p;
    cudaGetSymbolAddress(&p, g_h1);  h1  = (__half*)p;
    cudaGetSymbolAddress(&p, g_part);part= (float*)p;
    cudaGetSymbolAddress(&p, g_mb);  mb  = (uint32_t*)p;
    cudaGetSymbolAddress(&p, g_wqkv);wqkvt=(__half*)p;
    cudaGetSymbolAddress(&p, g_wo);  wot = (__half*)p;
    cudaGetSymbolAddress(&p, g_fw1); fw1t= (__half*)p;
    cudaGetSymbolAddress(&p, g_fw2); fw2t= (__half*)p;

    cudaFuncSetAttribute(gemm_tc<EPI_QKV>,       cudaFuncAttributeMaxDynamicSharedMemorySize, GEMM_SMEM_BYTES);
    cudaFuncSetAttribute(gemm_tc<EPI_RESID>,     cudaFuncAttributeMaxDynamicSharedMemorySize, GEMM_SMEM_BYTES);
    cudaFuncSetAttribute(gemm_tc<EPI_BIAS_RELU>, cudaFuncAttributeMaxDynamicSharedMemorySize, GEMM_SMEM_BYTES);
    cudaFuncSetAttribute(gemm_tc<EPI_BIAS_RESID>,cudaFuncAttributeMaxDynamicSharedMemorySize, GEMM_SMEM_BYTES);
    cudaFuncSetAttribute(attn_tc, cudaFuncAttributeMaxDynamicSharedMemorySize, ATTN_SMEM_BYTES);

    ln_kernel<<<ROWS, 256>>>(x, ln1a, ln1b, xn);                       // 1
    maskbits_kernel<<<SEQ, NWORDS>>>(mask, mb);                        // 2
    padclear_kernel<<<BATCH * NHEADS, 256>>>(k, v);                    // 3
    memfill_kernel<<<128, 256>>>(mem, xn);                             // 4
    transpose_all<<<12288, dim3(32, 8)>>>(wq, wk, wv, wo, fw1, fw2,    // 5
                                          wqkvt, wot, fw1t, fw2t);

    // fused QKV + memory-token projection (extra M-block), N = 3072
    gemm_tc<EPI_QKV><<<dim3(3*DMODEL/BN, XROWS/BM), 256, GEMM_SMEM_BYTES>>>(  // 6 <- profiled
        xn, wqkvt, q, nullptr, nullptr, k, v, XROWS, 3*DMODEL, DMODEL);

    attn_tc<<<dim3(SEQ/128, BATCH*NHEADS), 256, ATTN_SMEM_BYTES>>>(q, k, v, mb, ctx);

    gemm_tc<EPI_RESID><<<dim3(DMODEL/BN, ROWS/BM), 256, GEMM_SMEM_BYTES>>>(
        ctx, wot, x1, nullptr, x, nullptr, nullptr, ROWS, DMODEL, DMODEL);

    ln_kernel<<<ROWS, 256>>>(x1, ln2a, ln2b, xn2);

    gemm_tc<EPI_BIAS_RELU><<<dim3(DFF/BN, ROWS/BM), 256, GEMM_SMEM_BYTES>>>(
        xn2, fw1t, h1, fb1, nullptr, nullptr, nullptr, ROWS, DFF, DMODEL);
    gemm_tc<EPI_BIAS_RESID><<<dim3(DMODEL/BN, ROWS/BM), 256, GEMM_SMEM_BYTES>>>(
        h1, fw2t, out, fb2, x1, nullptr, nullptr, ROWS, DMODEL, DFF);

    mem_partial_kernel<<<dim3(BATCH, 16), 1024>>>(out, part);
    mem_final_kernel<<<BATCH, 1024>>>(part, out_mem);
}